// round 2
// baseline (speedup 1.0000x reference)
#include <cuda_runtime.h>
#include <math.h>

#define D_MODEL 1024
#define N_HEADS 16
#define HEAD_DIM 64
#define B_SZ 2
#define SEQ 2048
#define M_TOT (B_SZ * SEQ)   // 4096

typedef unsigned long long u64;

// Packed fp32x2 ops (sm_103a). Exact fp32 semantics per lane.
#define FMA2(d,a,b,c) asm("fma.rn.f32x2 %0, %1, %2, %3;" : "=l"(d) : "l"(a), "l"(b), "l"(c))
#define MUL2(d,a,b)   asm("mul.rn.f32x2 %0, %1, %2;"     : "=l"(d) : "l"(a), "l"(b))
#define PK2(d,lo,hi)  asm("mov.b64 %0, {%1, %2};" : "=l"(d) : "f"(lo), "f"(hi))
#define UPK2(lo,hi,s) asm("mov.b64 {%0, %1}, %2;" : "=f"(lo), "=f"(hi) : "l"(s))

// Scratch (allocation-free rule: device globals)
__device__ float g_Q[(size_t)M_TOT * D_MODEL];
__device__ float g_K[(size_t)M_TOT * D_MODEL];
__device__ float g_V[(size_t)M_TOT * D_MODEL];
__device__ float g_A[(size_t)M_TOT * D_MODEL];

// ---------------------------------------------------------------------------
// SGEMM + bias: C[M,N] = A[M,K] @ B[K,N] + bias[N]
// 128x128x8 block, 8x8 per thread via FFMA2 (f32x2-packed along columns).
// ---------------------------------------------------------------------------
__global__ __launch_bounds__(256, 2)
void sgemm_bias(const float* __restrict__ A, const float* __restrict__ Bm,
                const float* __restrict__ bias, float* __restrict__ C,
                int M, int N, int K)
{
    __shared__ float As[8][128];
    __shared__ float Bs[8][128];

    const int bx = blockIdx.x, by = blockIdx.y;
    const int tid = threadIdx.x;
    const int tx = tid & 15, ty = tid >> 4;

    const float* Ab = A + (size_t)(by * 128) * K;
    const float* Bb = Bm + bx * 128;

    const int aRow = tid >> 1;          // 0..127
    const int aCol = (tid & 1) << 2;    // 0 or 4
    const int bRow = tid >> 5;          // 0..7
    const int bCol = (tid & 31) << 2;   // 0..124

    // acc[i][jp]: pair (col 2*jp, 2*jp+1) within this thread's 8 cols
    u64 acc[8][4];
    #pragma unroll
    for (int i = 0; i < 8; i++)
        #pragma unroll
        for (int j = 0; j < 4; j++) acc[i][j] = 0ull;

    for (int k0 = 0; k0 < K; k0 += 8) {
        float4 av = *(const float4*)(Ab + (size_t)aRow * K + k0 + aCol);
        As[aCol + 0][aRow] = av.x;
        As[aCol + 1][aRow] = av.y;
        As[aCol + 2][aRow] = av.z;
        As[aCol + 3][aRow] = av.w;
        float4 bv = *(const float4*)(Bb + (size_t)(k0 + bRow) * N + bCol);
        *(float4*)&Bs[bRow][bCol] = bv;
        __syncthreads();

        #pragma unroll
        for (int k = 0; k < 8; k++) {
            float a0[8];
            *(float4*)&a0[0] = *(float4*)&As[k][ty * 4];
            *(float4*)&a0[4] = *(float4*)&As[k][64 + ty * 4];
            float4 b0 = *(float4*)&Bs[k][tx * 4];
            float4 b1 = *(float4*)&Bs[k][64 + tx * 4];
            u64 bp[4];
            PK2(bp[0], b0.x, b0.y);
            PK2(bp[1], b0.z, b0.w);
            PK2(bp[2], b1.x, b1.y);
            PK2(bp[3], b1.z, b1.w);
            #pragma unroll
            for (int i = 0; i < 8; i++) {
                u64 ad;
                PK2(ad, a0[i], a0[i]);
                #pragma unroll
                for (int jp = 0; jp < 4; jp++)
                    FMA2(acc[i][jp], ad, bp[jp], acc[i][jp]);
            }
        }
        __syncthreads();
    }

    #pragma unroll
    for (int i = 0; i < 8; i++) {
        int row = by * 128 + ((i < 4) ? (ty * 4 + i) : (64 + ty * 4 + i - 4));
        int c0 = bx * 128 + tx * 4;
        int c1 = c0 + 64;
        float a00, a01, a02, a03, a10, a11, a12, a13;
        UPK2(a00, a01, acc[i][0]);
        UPK2(a02, a03, acc[i][1]);
        UPK2(a10, a11, acc[i][2]);
        UPK2(a12, a13, acc[i][3]);
        float4 v0, v1;
        v0.x = a00 + bias[c0 + 0];
        v0.y = a01 + bias[c0 + 1];
        v0.z = a02 + bias[c0 + 2];
        v0.w = a03 + bias[c0 + 3];
        v1.x = a10 + bias[c1 + 0];
        v1.y = a11 + bias[c1 + 1];
        v1.z = a12 + bias[c1 + 2];
        v1.w = a13 + bias[c1 + 3];
        *(float4*)&C[(size_t)row * N + c0] = v0;
        *(float4*)&C[(size_t)row * N + c1] = v1;
    }
}

// ---------------------------------------------------------------------------
// Flash-style attention, fp32, FFMA2.
// One block = one (b, h, 128-row q-tile). KV tiles of 128 keys.
// 256 threads as 16x16: thread owns 8 S-rows (ty*8+i) x 8 S-cols (tx+16j),
// output dims tx*4..tx*4+3. Online softmax over 16-lane groups.
// ---------------------------------------------------------------------------
#define ST  68    // K/V/Q smem row stride (64 + 4 pad)
#define PST 132   // P smem row stride (128 + 4 pad)

__global__ __launch_bounds__(256, 1)
void attn_kernel(const float* __restrict__ Qg, const float* __restrict__ Kg,
                 const float* __restrict__ Vg, float* __restrict__ Og)
{
    extern __shared__ float sm[];
    float* Qs = sm;                 // 128 x ST
    float* Ks = Qs + 128 * ST;      // 128 x ST
    float* Vs = Ks + 128 * ST;      // 128 x ST
    float* Ps = Vs + 128 * ST;      // 128 x PST

    const int qt = blockIdx.x;
    const int bh = blockIdx.y;
    const int b = bh >> 4, h = bh & 15;

    const int tid = threadIdx.x;
    const int tx = tid & 15, ty = tid >> 4;

    const float scale = 0.125f;  // 1/sqrt(64)

    const float* Qp = Qg + (size_t)(b * SEQ + qt * 128) * D_MODEL + h * HEAD_DIM;
    const float* Kp = Kg + (size_t)(b * SEQ) * D_MODEL + h * HEAD_DIM;
    const float* Vp = Vg + (size_t)(b * SEQ) * D_MODEL + h * HEAD_DIM;

    // Load Q tile (pre-scaled)
    for (int i = tid; i < 128 * 16; i += 256) {
        int r = i >> 4, c = (i & 15) << 2;
        float4 v = *(const float4*)(Qp + (size_t)r * D_MODEL + c);
        v.x *= scale; v.y *= scale; v.z *= scale; v.w *= scale;
        *(float4*)&Qs[r * ST + c] = v;
    }

    float m[8], l[8];
    u64 op[8][2];   // output accum pairs: dims (tx*4, +1) and (+2, +3)
    #pragma unroll
    for (int i = 0; i < 8; i++) {
        m[i] = -1e30f; l[i] = 0.f;
        op[i][0] = 0ull; op[i][1] = 0ull;
    }

    for (int kt = 0; kt < SEQ / 128; kt++) {
        const float* Kt = Kp + (size_t)kt * 128 * D_MODEL;
        const float* Vt = Vp + (size_t)kt * 128 * D_MODEL;
        for (int i = tid; i < 128 * 16; i += 256) {
            int r = i >> 4, c = (i & 15) << 2;
            *(float4*)&Ks[r * ST + c] = *(const float4*)(Kt + (size_t)r * D_MODEL + c);
            *(float4*)&Vs[r * ST + c] = *(const float4*)(Vt + (size_t)r * D_MODEL + c);
        }
        __syncthreads();

        // ---- S = (scaled Q) @ K^T, pairs packed along key-cols ----
        // sp[i][jp] = pair for keys (tx + 16*(2jp), tx + 16*(2jp+1))
        u64 sp[8][4];
        #pragma unroll
        for (int i = 0; i < 8; i++)
            #pragma unroll
            for (int jp = 0; jp < 4; jp++) sp[i][jp] = 0ull;

        #pragma unroll
        for (int d = 0; d < 64; d += 4) {
            float4 q4[8], k4[8];
            #pragma unroll
            for (int i = 0; i < 8; i++) q4[i] = *(float4*)&Qs[(ty * 8 + i) * ST + d];
            #pragma unroll
            for (int j = 0; j < 8; j++) k4[j] = *(float4*)&Ks[(tx + 16 * j) * ST + d];

            u64 kp[4][4];
            #pragma unroll
            for (int jp = 0; jp < 4; jp++) {
                PK2(kp[jp][0], k4[2 * jp].x, k4[2 * jp + 1].x);
                PK2(kp[jp][1], k4[2 * jp].y, k4[2 * jp + 1].y);
                PK2(kp[jp][2], k4[2 * jp].z, k4[2 * jp + 1].z);
                PK2(kp[jp][3], k4[2 * jp].w, k4[2 * jp + 1].w);
            }
            #pragma unroll
            for (int i = 0; i < 8; i++) {
                u64 ad0, ad1, ad2, ad3;
                PK2(ad0, q4[i].x, q4[i].x);
                PK2(ad1, q4[i].y, q4[i].y);
                PK2(ad2, q4[i].z, q4[i].z);
                PK2(ad3, q4[i].w, q4[i].w);
                #pragma unroll
                for (int jp = 0; jp < 4; jp++) {
                    FMA2(sp[i][jp], ad0, kp[jp][0], sp[i][jp]);
                    FMA2(sp[i][jp], ad1, kp[jp][1], sp[i][jp]);
                    FMA2(sp[i][jp], ad2, kp[jp][2], sp[i][jp]);
                    FMA2(sp[i][jp], ad3, kp[jp][3], sp[i][jp]);
                }
            }
        }

        // ---- Online softmax per row (16 lanes share a row-group) ----
        #pragma unroll
        for (int i = 0; i < 8; i++) {
            float s[8];
            #pragma unroll
            for (int jp = 0; jp < 4; jp++) UPK2(s[2 * jp], s[2 * jp + 1], sp[i][jp]);

            float rmax = s[0];
            #pragma unroll
            for (int j = 1; j < 8; j++) rmax = fmaxf(rmax, s[j]);
            #pragma unroll
            for (int off = 8; off > 0; off >>= 1)
                rmax = fmaxf(rmax, __shfl_xor_sync(0xffffffffu, rmax, off, 16));

            float mnew = fmaxf(m[i], rmax);
            float corr = __expf(m[i] - mnew);
            float rsum = 0.f;
            #pragma unroll
            for (int j = 0; j < 8; j++) {
                float p = __expf(s[j] - mnew);
                Ps[(ty * 8 + i) * PST + tx + 16 * j] = p;
                rsum += p;
            }
            #pragma unroll
            for (int off = 8; off > 0; off >>= 1)
                rsum += __shfl_xor_sync(0xffffffffu, rsum, off, 16);

            l[i] = l[i] * corr + rsum;
            m[i] = mnew;
            u64 cp;
            PK2(cp, corr, corr);
            MUL2(op[i][0], op[i][0], cp);
            MUL2(op[i][1], op[i][1], cp);
        }
        __syncwarp();   // Ps row-group producer == consumer (same 16 lanes)

        // ---- O += P @ V ----
        #pragma unroll
        for (int c0 = 0; c0 < 128; c0 += 4) {
            float4 p4[8];
            #pragma unroll
            for (int i = 0; i < 8; i++) p4[i] = *(float4*)&Ps[(ty * 8 + i) * PST + c0];
            #pragma unroll
            for (int cc = 0; cc < 4; cc++) {
                float4 vv = *(float4*)&Vs[(c0 + cc) * ST + tx * 4];
                u64 v01, v23;
                PK2(v01, vv.x, vv.y);
                PK2(v23, vv.z, vv.w);
                #pragma unroll
                for (int i = 0; i < 8; i++) {
                    float p = (cc == 0) ? p4[i].x : (cc == 1) ? p4[i].y
                             : (cc == 2) ? p4[i].z : p4[i].w;
                    u64 pd;
                    PK2(pd, p, p);
                    FMA2(op[i][0], pd, v01, op[i][0]);
                    FMA2(op[i][1], pd, v23, op[i][1]);
                }
            }
        }
        __syncthreads();  // protect Ks/Vs before next tile load
    }

    // ---- Normalize + store ----
    float* Op = Og + (size_t)(b * SEQ + qt * 128) * D_MODEL + h * HEAD_DIM;
    #pragma unroll
    for (int i = 0; i < 8; i++) {
        float inv = 1.0f / l[i];
        float o0, o1, o2, o3;
        UPK2(o0, o1, op[i][0]);
        UPK2(o2, o3, op[i][1]);
        float4 v;
        v.x = o0 * inv; v.y = o1 * inv; v.z = o2 * inv; v.w = o3 * inv;
        *(float4*)(Op + (size_t)(ty * 8 + i) * D_MODEL + tx * 4) = v;
    }
}

// ---------------------------------------------------------------------------
extern "C" void kernel_launch(void* const* d_in, const int* in_sizes, int n_in,
                              void* d_out, int out_size)
{
    const float* query = (const float*)d_in[0];
    const float* key   = (const float*)d_in[1];
    const float* value = (const float*)d_in[2];
    const float* Wq    = (const float*)d_in[3];
    const float* bq    = (const float*)d_in[4];
    const float* Wk    = (const float*)d_in[5];
    const float* bk    = (const float*)d_in[6];
    const float* Wv    = (const float*)d_in[7];
    const float* bv    = (const float*)d_in[8];
    const float* Wo    = (const float*)d_in[9];
    const float* bo    = (const float*)d_in[10];
    float* out = (float*)d_out;

    float *Qb, *Kb, *Vb, *Ab;
    cudaGetSymbolAddress((void**)&Qb, g_Q);
    cudaGetSymbolAddress((void**)&Kb, g_K);
    cudaGetSymbolAddress((void**)&Vb, g_V);
    cudaGetSymbolAddress((void**)&Ab, g_A);

    dim3 gg(D_MODEL / 128, M_TOT / 128);   // (8, 32)

    sgemm_bias<<<gg, 256>>>(query, Wq, bq, Qb, M_TOT, D_MODEL, D_MODEL);
    sgemm_bias<<<gg, 256>>>(key,   Wk, bk, Kb, M_TOT, D_MODEL, D_MODEL);
    sgemm_bias<<<gg, 256>>>(value, Wv, bv, Vb, M_TOT, D_MODEL, D_MODEL);

    size_t smem = (size_t)(3 * 128 * ST + 128 * PST) * sizeof(float);  // 172032 B
    cudaFuncSetAttribute(attn_kernel,
                         cudaFuncAttributeMaxDynamicSharedMemorySize, (int)smem);
    attn_kernel<<<dim3(SEQ / 128, B_SZ * N_HEADS), 256, smem>>>(Qb, Kb, Vb, Ab);

    sgemm_bias<<<gg, 256>>>(Ab, Wo, bo, out, M_TOT, D_MODEL, D_MODEL);
}

// round 4
// speedup vs baseline: 1.6327x; 1.6327x over previous
#include <cuda_runtime.h>
#include <cuda_bf16.h>
#include <stdint.h>
#include <math.h>

#define D_MODEL 1024
#define N_HEADS 16
#define HEAD_DIM 64
#define B_SZ 2
#define SEQ 2048
#define M_TOT (B_SZ * SEQ)   // 4096

// Scratch (allocation-free rule: device globals)
__device__ float g_Q[(size_t)M_TOT * D_MODEL];
__device__ float g_K[(size_t)M_TOT * D_MODEL];
__device__ float g_V[(size_t)M_TOT * D_MODEL];
__device__ float g_A[(size_t)M_TOT * D_MODEL];

// ===========================================================================
// helpers
// ===========================================================================
__device__ __forceinline__ uint32_t smem_u32(const void* p) {
    uint32_t a;
    asm("{ .reg .u64 t; cvta.to.shared.u64 t, %1; cvt.u32.u64 %0, t; }"
        : "=r"(a) : "l"(p));
    return a;
}

// swizzles: A rows are 64B (bits[5:4] ^= bits[8:7]); B rows are 256B
// (bits[6:4] ^= bits[10:8]).
#define SW64(o)  ((o) ^ (((o) >> 3) & 0x30))
#define SW256(o) ((o) ^ (((o) >> 4) & 0x70))

__device__ __forceinline__ void ldsm_x4(uint32_t* r, uint32_t a) {
    asm volatile("ldmatrix.sync.aligned.m8n8.x4.shared.b16 {%0,%1,%2,%3}, [%4];"
                 : "=r"(r[0]), "=r"(r[1]), "=r"(r[2]), "=r"(r[3]) : "r"(a));
}
__device__ __forceinline__ void ldsm_x4_t(uint32_t* r, uint32_t a) {
    asm volatile("ldmatrix.sync.aligned.m8n8.x4.trans.shared.b16 {%0,%1,%2,%3}, [%4];"
                 : "=r"(r[0]), "=r"(r[1]), "=r"(r[2]), "=r"(r[3]) : "r"(a));
}
__device__ __forceinline__ void mma_bf16(float* c, const uint32_t* a, const uint32_t* b) {
    asm volatile("mma.sync.aligned.m16n8k16.row.col.f32.bf16.bf16.f32 "
                 "{%0,%1,%2,%3}, {%4,%5,%6,%7}, {%8,%9}, {%0,%1,%2,%3};"
                 : "+f"(c[0]), "+f"(c[1]), "+f"(c[2]), "+f"(c[3])
                 : "r"(a[0]), "r"(a[1]), "r"(a[2]), "r"(a[3]),
                   "r"(b[0]), "r"(b[1]));
}

// float4 -> bf16 hi pair + residual lo pair (packed bf16x2 words)
__device__ __forceinline__ void cvt_hl(float4 v, uint2& hi, uint2& lo) {
    __nv_bfloat162 h01 = __floats2bfloat162_rn(v.x, v.y);
    __nv_bfloat162 h23 = __floats2bfloat162_rn(v.z, v.w);
    float f0 = __bfloat162float(__low2bfloat16(h01));
    float f1 = __bfloat162float(__high2bfloat16(h01));
    float f2 = __bfloat162float(__low2bfloat16(h23));
    float f3 = __bfloat162float(__high2bfloat16(h23));
    __nv_bfloat162 l01 = __floats2bfloat162_rn(v.x - f0, v.y - f1);
    __nv_bfloat162 l23 = __floats2bfloat162_rn(v.z - f2, v.w - f3);
    hi = make_uint2(*(uint32_t*)&h01, *(uint32_t*)&h23);
    lo = make_uint2(*(uint32_t*)&l01, *(uint32_t*)&l23);
}

// ===========================================================================
// Tensor-core GEMM + bias via mma.sync bf16, hi/lo split (3 terms).
// C[4096,1024] = X @ W + bias. Block 128x128, k-chunk 32 fp32.
// 8 warps: warp_m = wid&3 (32 rows), warp_n = wid>>2 (64 cols).
// ===========================================================================
__global__ __launch_bounds__(256, 2)
void gemm_mma(const float* __restrict__ X, const float* __restrict__ W,
              const float* __restrict__ bias, float* __restrict__ C)
{
    __shared__ __align__(16) uint8_t sAh[128 * 64], sAl[128 * 64];   // 128r x 32k bf16
    __shared__ __align__(16) uint8_t sBh[32 * 256], sBl[32 * 256];   // 32k x 128n bf16

    const int tid  = threadIdx.x;
    const int lane = tid & 31;
    const int wid  = tid >> 5;
    const int m_w  = (wid & 3) * 32;
    const int n_w  = (wid >> 2) * 64;
    const int m0   = blockIdx.y * 128;
    const int n0   = blockIdx.x * 128;

    const uint32_t bAh = smem_u32(sAh), bAl = smem_u32(sAl);
    const uint32_t bBh = smem_u32(sBh), bBl = smem_u32(sBl);

    float acc[2][8][4];
    #pragma unroll
    for (int mi = 0; mi < 2; mi++)
        #pragma unroll
        for (int nj = 0; nj < 8; nj++)
            #pragma unroll
            for (int e = 0; e < 4; e++) acc[mi][nj][e] = 0.f;

    // ldmatrix per-lane addressing
    const int a_row = lane & 15;          // + mi*16
    const int a_ch  = lane >> 4;          // 16B chunk (k-half)
    const int b_kr  = (lane & 7) + ((lane >> 3) & 1) * 8;   // + ks*16
    const int b_nc  = lane >> 4;          // 8-col chunk

    // load indices: 8 lanes cover 128B contiguous
    const int lr = tid >> 3;              // 0..31
    const int lc = (tid & 7) * 4;         // fp32 col

    for (int kc = 0; kc < 32; kc++) {
        // ---- X tile: rows (lr + j*32), cols kc*32 + lc..+3 ----
        #pragma unroll
        for (int j = 0; j < 4; j++) {
            int row = lr + j * 32;
            float4 v = *(const float4*)(X + (size_t)(m0 + row) * D_MODEL + kc * 32 + lc);
            uint2 hi, lo;
            cvt_hl(v, hi, lo);
            uint32_t so = SW64((uint32_t)(row * 64 + lc * 2));
            *(uint2*)(sAh + so) = hi;
            *(uint2*)(sAl + so) = lo;
        }
        // ---- W tile: k rows lr, cols n0 + lc + j*32 ----
        #pragma unroll
        for (int j = 0; j < 4; j++) {
            int col = lc + j * 32;
            float4 v = *(const float4*)(W + (size_t)(kc * 32 + lr) * D_MODEL + n0 + col);
            uint2 hi, lo;
            cvt_hl(v, hi, lo);
            uint32_t so = SW256((uint32_t)(lr * 256 + col * 2));
            *(uint2*)(sBh + so) = hi;
            *(uint2*)(sBl + so) = lo;
        }
        __syncthreads();

        #pragma unroll
        for (int ks = 0; ks < 2; ks++) {
            uint32_t ah[2][4], al[2][4];
            #pragma unroll
            for (int mi = 0; mi < 2; mi++) {
                uint32_t o = (uint32_t)((m_w + mi * 16 + a_row) * 64 + ks * 32 + a_ch * 16);
                ldsm_x4(ah[mi], bAh + SW64(o));
                ldsm_x4(al[mi], bAl + SW64(o));
            }
            #pragma unroll
            for (int njp = 0; njp < 4; njp++) {
                uint32_t o = (uint32_t)((ks * 16 + b_kr) * 256
                                        + (n_w + njp * 16) * 2 + b_nc * 16);
                uint32_t bh[4], bl[4];
                ldsm_x4_t(bh, bBh + SW256(o));
                ldsm_x4_t(bl, bBl + SW256(o));
                #pragma unroll
                for (int mi = 0; mi < 2; mi++) {
                    mma_bf16(acc[mi][njp * 2],     ah[mi], bh);       // hi*hi
                    mma_bf16(acc[mi][njp * 2 + 1], ah[mi], bh + 2);
                    mma_bf16(acc[mi][njp * 2],     ah[mi], bl);       // hi*lo
                    mma_bf16(acc[mi][njp * 2 + 1], ah[mi], bl + 2);
                    mma_bf16(acc[mi][njp * 2],     al[mi], bh);       // lo*hi
                    mma_bf16(acc[mi][njp * 2 + 1], al[mi], bh + 2);
                }
            }
        }
        __syncthreads();
    }

    // ---- epilogue: acc + bias -> C ----
    #pragma unroll
    for (int mi = 0; mi < 2; mi++) {
        #pragma unroll
        for (int nj = 0; nj < 8; nj++) {
            int col = n0 + n_w + nj * 8 + (lane & 3) * 2;
            int row = m0 + m_w + mi * 16 + (lane >> 2);
            float b0 = bias[col], b1 = bias[col + 1];
            float2 v0 = make_float2(acc[mi][nj][0] + b0, acc[mi][nj][1] + b1);
            float2 v1 = make_float2(acc[mi][nj][2] + b0, acc[mi][nj][3] + b1);
            *(float2*)(C + (size_t)row * D_MODEL + col) = v0;
            *(float2*)(C + (size_t)(row + 8) * D_MODEL + col) = v1;
        }
    }
}

// ===========================================================================
// Flash-style attention, fp32 scalar, 128x128 tiles, 8x8 per thread.
// 256 threads as 16x16: rows ty*8+i, S-cols tx+16j, output dims tx*4..+3.
// ===========================================================================
#define ST  68    // Q/K/V smem row stride (64 + 4 pad)
#define PST 132   // P smem row stride (128 + 4 pad)

__global__ __launch_bounds__(256)
void attn_kernel(const float* __restrict__ Qg, const float* __restrict__ Kg,
                 const float* __restrict__ Vg, float* __restrict__ Og)
{
    extern __shared__ float sm[];
    float* Qs = sm;                 // 128 x ST
    float* Ks = Qs + 128 * ST;
    float* Vs = Ks + 128 * ST;
    float* Ps = Vs + 128 * ST;      // 128 x PST

    const int qt = blockIdx.x;
    const int bh = blockIdx.y;
    const int b = bh >> 4, h = bh & 15;

    const int tid = threadIdx.x;
    const int tx = tid & 15, ty = tid >> 4;

    const float scale = 0.125f;  // 1/sqrt(64)

    const float* Qp = Qg + (size_t)(b * SEQ + qt * 128) * D_MODEL + h * HEAD_DIM;
    const float* Kp = Kg + (size_t)(b * SEQ) * D_MODEL + h * HEAD_DIM;
    const float* Vp = Vg + (size_t)(b * SEQ) * D_MODEL + h * HEAD_DIM;

    for (int i = tid; i < 128 * 16; i += 256) {
        int r = i >> 4, c = (i & 15) << 2;
        float4 v = *(const float4*)(Qp + (size_t)r * D_MODEL + c);
        v.x *= scale; v.y *= scale; v.z *= scale; v.w *= scale;
        *(float4*)&Qs[r * ST + c] = v;
    }

    float m[8], l[8], o[8][4];
    #pragma unroll
    for (int i = 0; i < 8; i++) {
        m[i] = -1e30f; l[i] = 0.f;
        #pragma unroll
        for (int j = 0; j < 4; j++) o[i][j] = 0.f;
    }

    for (int kt = 0; kt < SEQ / 128; kt++) {
        const float* Kt = Kp + (size_t)kt * 128 * D_MODEL;
        const float* Vt = Vp + (size_t)kt * 128 * D_MODEL;
        for (int i = tid; i < 128 * 16; i += 256) {
            int r = i >> 4, c = (i & 15) << 2;
            *(float4*)&Ks[r * ST + c] = *(const float4*)(Kt + (size_t)r * D_MODEL + c);
            *(float4*)&Vs[r * ST + c] = *(const float4*)(Vt + (size_t)r * D_MODEL + c);
        }
        __syncthreads();

        // ---- S = (scaled Q) @ K^T ----
        float s[8][8];
        #pragma unroll
        for (int i = 0; i < 8; i++)
            #pragma unroll
            for (int j = 0; j < 8; j++) s[i][j] = 0.f;

        #pragma unroll
        for (int d = 0; d < 64; d += 4) {
            float4 q4[8], k4[8];
            #pragma unroll
            for (int i = 0; i < 8; i++) q4[i] = *(float4*)&Qs[(ty * 8 + i) * ST + d];
            #pragma unroll
            for (int j = 0; j < 8; j++) k4[j] = *(float4*)&Ks[(tx + 16 * j) * ST + d];
            #pragma unroll
            for (int i = 0; i < 8; i++)
                #pragma unroll
                for (int j = 0; j < 8; j++)
                    s[i][j] += q4[i].x * k4[j].x + q4[i].y * k4[j].y
                             + q4[i].z * k4[j].z + q4[i].w * k4[j].w;
        }

        // ---- online softmax (16-lane row groups) ----
        #pragma unroll
        for (int i = 0; i < 8; i++) {
            float rmax = s[i][0];
            #pragma unroll
            for (int j = 1; j < 8; j++) rmax = fmaxf(rmax, s[i][j]);
            #pragma unroll
            for (int off = 8; off > 0; off >>= 1)
                rmax = fmaxf(rmax, __shfl_xor_sync(0xffffffffu, rmax, off, 16));

            float mnew = fmaxf(m[i], rmax);
            float corr = __expf(m[i] - mnew);
            float rsum = 0.f;
            #pragma unroll
            for (int j = 0; j < 8; j++) {
                float p = __expf(s[i][j] - mnew);
                Ps[(ty * 8 + i) * PST + tx + 16 * j] = p;
                rsum += p;
            }
            #pragma unroll
            for (int off = 8; off > 0; off >>= 1)
                rsum += __shfl_xor_sync(0xffffffffu, rsum, off, 16);

            l[i] = l[i] * corr + rsum;
            m[i] = mnew;
            #pragma unroll
            for (int j = 0; j < 4; j++) o[i][j] *= corr;
        }
        __syncwarp();   // Ps producer == consumer half-warp

        // ---- O += P @ V ----
        #pragma unroll
        for (int c0 = 0; c0 < 128; c0 += 4) {
            float4 p4[8];
            #pragma unroll
            for (int i = 0; i < 8; i++) p4[i] = *(float4*)&Ps[(ty * 8 + i) * PST + c0];
            #pragma unroll
            for (int cc = 0; cc < 4; cc++) {
                float4 vv = *(float4*)&Vs[(c0 + cc) * ST + tx * 4];
                #pragma unroll
                for (int i = 0; i < 8; i++) {
                    float p = (cc == 0) ? p4[i].x : (cc == 1) ? p4[i].y
                             : (cc == 2) ? p4[i].z : p4[i].w;
                    o[i][0] += p * vv.x;
                    o[i][1] += p * vv.y;
                    o[i][2] += p * vv.z;
                    o[i][3] += p * vv.w;
                }
            }
        }
        __syncthreads();
    }

    float* Op = Og + (size_t)(b * SEQ + qt * 128) * D_MODEL + h * HEAD_DIM;
    #pragma unroll
    for (int i = 0; i < 8; i++) {
        float inv = 1.0f / l[i];
        float4 v;
        v.x = o[i][0] * inv; v.y = o[i][1] * inv;
        v.z = o[i][2] * inv; v.w = o[i][3] * inv;
        *(float4*)(Op + (size_t)(ty * 8 + i) * D_MODEL + tx * 4) = v;
    }
}

// ---------------------------------------------------------------------------
extern "C" void kernel_launch(void* const* d_in, const int* in_sizes, int n_in,
                              void* d_out, int out_size)
{
    const float* query = (const float*)d_in[0];
    const float* key   = (const float*)d_in[1];
    const float* value = (const float*)d_in[2];
    const float* Wq    = (const float*)d_in[3];
    const float* bq    = (const float*)d_in[4];
    const float* Wk    = (const float*)d_in[5];
    const float* bk    = (const float*)d_in[6];
    const float* Wv    = (const float*)d_in[7];
    const float* bv    = (const float*)d_in[8];
    const float* Wo    = (const float*)d_in[9];
    const float* bo    = (const float*)d_in[10];
    float* out = (float*)d_out;

    float *Qb, *Kb, *Vb, *Ab;
    cudaGetSymbolAddress((void**)&Qb, g_Q);
    cudaGetSymbolAddress((void**)&Kb, g_K);
    cudaGetSymbolAddress((void**)&Vb, g_V);
    cudaGetSymbolAddress((void**)&Ab, g_A);

    size_t smem = (size_t)(3 * 128 * ST + 128 * PST) * sizeof(float);  // 172032 B
    cudaFuncSetAttribute(attn_kernel,
                         cudaFuncAttributeMaxDynamicSharedMemorySize, (int)smem);

    dim3 gg(D_MODEL / 128, M_TOT / 128);   // (8, 32)

    gemm_mma<<<gg, 256>>>(query, Wq, bq, Qb);
    gemm_mma<<<gg, 256>>>(key,   Wk, bk, Kb);
    gemm_mma<<<gg, 256>>>(value, Wv, bv, Vb);

    attn_kernel<<<dim3(SEQ / 128, B_SZ * N_HEADS), 256, smem>>>(Qb, Kb, Vb, Ab);

    gemm_mma<<<gg, 256>>>(Ab, Wo, bo, out);
}

// round 5
// speedup vs baseline: 4.3257x; 2.6494x over previous
#include <cuda_runtime.h>
#include <cuda_bf16.h>
#include <cuda_fp16.h>
#include <stdint.h>
#include <math.h>

#define D_MODEL 1024
#define N_HEADS 16
#define HEAD_DIM 64
#define B_SZ 2
#define SEQ 2048
#define M_TOT (B_SZ * SEQ)   // 4096

// Q pre-scale: 1/sqrt(64) * log2(e)  (softmax done in base-2)
#define QSCALE 0.1803368801111204f

// Scratch (allocation-free rule: device globals)
__device__ uint16_t g_Qh[(size_t)M_TOT * D_MODEL];   // bf16
__device__ uint16_t g_Ql[(size_t)M_TOT * D_MODEL];   // bf16
__device__ uint16_t g_Kh[(size_t)M_TOT * D_MODEL];   // bf16
__device__ uint16_t g_Kl[(size_t)M_TOT * D_MODEL];   // bf16
__device__ uint16_t g_Vh[(size_t)M_TOT * D_MODEL];   // f16
__device__ uint16_t g_Vl[(size_t)M_TOT * D_MODEL];   // f16
__device__ float    g_A [(size_t)M_TOT * D_MODEL];

// ===========================================================================
// helpers
// ===========================================================================
__device__ __forceinline__ uint32_t smem_u32(const void* p) {
    uint32_t a;
    asm("{ .reg .u64 t; cvta.to.shared.u64 t, %1; cvt.u32.u64 %0, t; }"
        : "=r"(a) : "l"(p));
    return a;
}

#define SW64(o)   ((o) ^ (((o) >> 3) & 0x30))
#define SW256(o)  ((o) ^ (((o) >> 4) & 0x70))
#define SW128B(o) ((o) ^ (((o) >> 3) & 0x70))   // 128B-row swizzle

__device__ __forceinline__ void ldsm_x4(uint32_t* r, uint32_t a) {
    asm volatile("ldmatrix.sync.aligned.m8n8.x4.shared.b16 {%0,%1,%2,%3}, [%4];"
                 : "=r"(r[0]), "=r"(r[1]), "=r"(r[2]), "=r"(r[3]) : "r"(a));
}
__device__ __forceinline__ void ldsm_x4_t(uint32_t* r, uint32_t a) {
    asm volatile("ldmatrix.sync.aligned.m8n8.x4.trans.shared.b16 {%0,%1,%2,%3}, [%4];"
                 : "=r"(r[0]), "=r"(r[1]), "=r"(r[2]), "=r"(r[3]) : "r"(a));
}
__device__ __forceinline__ void mma_bf16(float* c, const uint32_t* a, const uint32_t* b) {
    asm volatile("mma.sync.aligned.m16n8k16.row.col.f32.bf16.bf16.f32 "
                 "{%0,%1,%2,%3}, {%4,%5,%6,%7}, {%8,%9}, {%0,%1,%2,%3};"
                 : "+f"(c[0]), "+f"(c[1]), "+f"(c[2]), "+f"(c[3])
                 : "r"(a[0]), "r"(a[1]), "r"(a[2]), "r"(a[3]),
                   "r"(b[0]), "r"(b[1]));
}
__device__ __forceinline__ void mma_f16(float* c, const uint32_t* a, const uint32_t* b) {
    asm volatile("mma.sync.aligned.m16n8k16.row.col.f32.f16.f16.f32 "
                 "{%0,%1,%2,%3}, {%4,%5,%6,%7}, {%8,%9}, {%0,%1,%2,%3};"
                 : "+f"(c[0]), "+f"(c[1]), "+f"(c[2]), "+f"(c[3])
                 : "r"(a[0]), "r"(a[1]), "r"(a[2]), "r"(a[3]),
                   "r"(b[0]), "r"(b[1]));
}
// pack two f32 -> f16x2 {lo, hi}
__device__ __forceinline__ uint32_t cvt_f16x2(float hi, float lo) {
    uint32_t d;
    asm("cvt.rn.f16x2.f32 %0, %1, %2;" : "=r"(d) : "f"(hi), "f"(lo));
    return d;
}
__device__ __forceinline__ uint32_t ex2_f16x2(uint32_t x) {
    uint32_t d;
    asm("ex2.approx.f16x2 %0, %1;" : "=r"(d) : "r"(x));
    return d;
}
__device__ __forceinline__ uint32_t pk_bf(float a, float b) {
    __nv_bfloat162 t = __floats2bfloat162_rn(a, b);
    return *(uint32_t*)&t;
}
__device__ __forceinline__ uint32_t pk_h(float a, float b) {
    __half2 t = __floats2half2_rn(a, b);
    return *(uint32_t*)&t;
}
// fp32x4 -> bf16 hi + residual lo words (for GEMM smem tiles)
__device__ __forceinline__ void cvt_hl(float4 v, uint2& hi, uint2& lo) {
    __nv_bfloat162 h01 = __floats2bfloat162_rn(v.x, v.y);
    __nv_bfloat162 h23 = __floats2bfloat162_rn(v.z, v.w);
    float f0 = __bfloat162float(__low2bfloat16(h01));
    float f1 = __bfloat162float(__high2bfloat16(h01));
    float f2 = __bfloat162float(__low2bfloat16(h23));
    float f3 = __bfloat162float(__high2bfloat16(h23));
    __nv_bfloat162 l01 = __floats2bfloat162_rn(v.x - f0, v.y - f1);
    __nv_bfloat162 l23 = __floats2bfloat162_rn(v.z - f2, v.w - f3);
    hi = make_uint2(*(uint32_t*)&h01, *(uint32_t*)&h23);
    lo = make_uint2(*(uint32_t*)&l01, *(uint32_t*)&l23);
}

// ===========================================================================
// GEMM + bias via mma.sync bf16 hi/lo (3 terms). Block 128x128, kc=32.
// mode 0: fp32 -> C.  mode 1: (v)*scale -> bf16 hi/lo (Ch,Cl).
// mode 2: v -> f16 hi/lo (Ch,Cl).
// ===========================================================================
__global__ __launch_bounds__(256, 2)
void gemm_mma(const float* __restrict__ X, const float* __restrict__ W,
              const float* __restrict__ bias, float* __restrict__ C,
              uint16_t* __restrict__ Ch, uint16_t* __restrict__ Cl,
              float scale, int mode)
{
    __shared__ __align__(16) uint8_t sAh[128 * 64], sAl[128 * 64];
    __shared__ __align__(16) uint8_t sBh[32 * 256], sBl[32 * 256];

    const int tid  = threadIdx.x;
    const int lane = tid & 31;
    const int wid  = tid >> 5;
    const int m_w  = (wid & 3) * 32;
    const int n_w  = (wid >> 2) * 64;
    const int m0   = blockIdx.y * 128;
    const int n0   = blockIdx.x * 128;

    const uint32_t bAh = smem_u32(sAh), bAl = smem_u32(sAl);
    const uint32_t bBh = smem_u32(sBh), bBl = smem_u32(sBl);

    float acc[2][8][4];
    #pragma unroll
    for (int mi = 0; mi < 2; mi++)
        #pragma unroll
        for (int nj = 0; nj < 8; nj++)
            #pragma unroll
            for (int e = 0; e < 4; e++) acc[mi][nj][e] = 0.f;

    const int a_row = lane & 15;
    const int a_ch  = lane >> 4;
    const int b_kr  = (lane & 7) + ((lane >> 3) & 1) * 8;
    const int b_nc  = lane >> 4;
    const int lr = tid >> 3;
    const int lc = (tid & 7) * 4;

    for (int kc = 0; kc < 32; kc++) {
        #pragma unroll
        for (int j = 0; j < 4; j++) {
            int row = lr + j * 32;
            float4 v = *(const float4*)(X + (size_t)(m0 + row) * D_MODEL + kc * 32 + lc);
            uint2 hi, lo;
            cvt_hl(v, hi, lo);
            uint32_t so = SW64((uint32_t)(row * 64 + lc * 2));
            *(uint2*)(sAh + so) = hi;
            *(uint2*)(sAl + so) = lo;
        }
        #pragma unroll
        for (int j = 0; j < 4; j++) {
            int col = lc + j * 32;
            float4 v = *(const float4*)(W + (size_t)(kc * 32 + lr) * D_MODEL + n0 + col);
            uint2 hi, lo;
            cvt_hl(v, hi, lo);
            uint32_t so = SW256((uint32_t)(lr * 256 + col * 2));
            *(uint2*)(sBh + so) = hi;
            *(uint2*)(sBl + so) = lo;
        }
        __syncthreads();

        #pragma unroll
        for (int ks = 0; ks < 2; ks++) {
            uint32_t ah[2][4], al[2][4];
            #pragma unroll
            for (int mi = 0; mi < 2; mi++) {
                uint32_t o = (uint32_t)((m_w + mi * 16 + a_row) * 64 + ks * 32 + a_ch * 16);
                ldsm_x4(ah[mi], bAh + SW64(o));
                ldsm_x4(al[mi], bAl + SW64(o));
            }
            #pragma unroll
            for (int njp = 0; njp < 4; njp++) {
                uint32_t o = (uint32_t)((ks * 16 + b_kr) * 256
                                        + (n_w + njp * 16) * 2 + b_nc * 16);
                uint32_t bh[4], bl[4];
                ldsm_x4_t(bh, bBh + SW256(o));
                ldsm_x4_t(bl, bBl + SW256(o));
                #pragma unroll
                for (int mi = 0; mi < 2; mi++) {
                    mma_bf16(acc[mi][njp * 2],     ah[mi], bh);
                    mma_bf16(acc[mi][njp * 2 + 1], ah[mi], bh + 2);
                    mma_bf16(acc[mi][njp * 2],     ah[mi], bl);
                    mma_bf16(acc[mi][njp * 2 + 1], ah[mi], bl + 2);
                    mma_bf16(acc[mi][njp * 2],     al[mi], bh);
                    mma_bf16(acc[mi][njp * 2 + 1], al[mi], bh + 2);
                }
            }
        }
        __syncthreads();
    }

    #pragma unroll
    for (int mi = 0; mi < 2; mi++) {
        #pragma unroll
        for (int nj = 0; nj < 8; nj++) {
            int col = n0 + n_w + nj * 8 + (lane & 3) * 2;
            int r0  = m0 + m_w + mi * 16 + (lane >> 2);
            float b0 = bias[col], b1 = bias[col + 1];
            float vx0 = (acc[mi][nj][0] + b0) * scale;
            float vy0 = (acc[mi][nj][1] + b1) * scale;
            float vx1 = (acc[mi][nj][2] + b0) * scale;
            float vy1 = (acc[mi][nj][3] + b1) * scale;
            if (mode == 0) {
                *(float2*)(C + (size_t)r0 * D_MODEL + col) = make_float2(vx0, vy0);
                *(float2*)(C + (size_t)(r0 + 8) * D_MODEL + col) = make_float2(vx1, vy1);
            } else if (mode == 1) {
                float hx0 = __bfloat162float(__float2bfloat16_rn(vx0));
                float hy0 = __bfloat162float(__float2bfloat16_rn(vy0));
                float hx1 = __bfloat162float(__float2bfloat16_rn(vx1));
                float hy1 = __bfloat162float(__float2bfloat16_rn(vy1));
                *(uint32_t*)(Ch + (size_t)r0 * D_MODEL + col) = pk_bf(hx0, hy0);
                *(uint32_t*)(Cl + (size_t)r0 * D_MODEL + col) = pk_bf(vx0 - hx0, vy0 - hy0);
                *(uint32_t*)(Ch + (size_t)(r0 + 8) * D_MODEL + col) = pk_bf(hx1, hy1);
                *(uint32_t*)(Cl + (size_t)(r0 + 8) * D_MODEL + col) = pk_bf(vx1 - hx1, vy1 - hy1);
            } else {
                float hx0 = __half2float(__float2half_rn(vx0));
                float hy0 = __half2float(__float2half_rn(vy0));
                float hx1 = __half2float(__float2half_rn(vx1));
                float hy1 = __half2float(__float2half_rn(vy1));
                *(uint32_t*)(Ch + (size_t)r0 * D_MODEL + col) = pk_h(hx0, hy0);
                *(uint32_t*)(Cl + (size_t)r0 * D_MODEL + col) = pk_h(vx0 - hx0, vy0 - hy0);
                *(uint32_t*)(Ch + (size_t)(r0 + 8) * D_MODEL + col) = pk_h(hx1, hy1);
                *(uint32_t*)(Cl + (size_t)(r0 + 8) * D_MODEL + col) = pk_h(vx1 - hx1, vy1 - hy1);
            }
        }
    }
}

// ===========================================================================
// Tensor-core flash attention.
// Block = (q-tile 128, b*h). 8 warps; warp w owns q-rows w*16..+15.
// S = Q@K^T in bf16 hi/lo (3 terms); softmax in log2-domain with
// ex2.approx.f16x2; P kept in registers as f16 A-fragments; O += P@V with
// V f16 hi/lo (2 terms). Row sums via P x ones mma.
// ===========================================================================
#define TILE_B 16384   // one 128x64 2-byte tile

__global__ __launch_bounds__(256)
void attn_mma(const uint16_t* __restrict__ Qh, const uint16_t* __restrict__ Ql,
              const uint16_t* __restrict__ Kh, const uint16_t* __restrict__ Kl,
              const uint16_t* __restrict__ Vh, const uint16_t* __restrict__ Vl,
              float* __restrict__ Og)
{
    extern __shared__ __align__(16) uint8_t smx[];
    uint8_t* sK0 = smx;               // Kh tile (Q-hi staging first)
    uint8_t* sK1 = smx + TILE_B;      // Kl tile (Q-lo staging first)
    uint8_t* sV0 = smx + 2 * TILE_B;  // Vh tile
    uint8_t* sV1 = smx + 3 * TILE_B;  // Vl tile
    const uint32_t bK0 = smem_u32(sK0), bK1 = smem_u32(sK1);
    const uint32_t bV0 = smem_u32(sV0), bV1 = smem_u32(sV1);

    const int qt = blockIdx.x;
    const int bh = blockIdx.y;
    const int b = bh >> 4, h = bh & 15;
    const int tid = threadIdx.x;
    const int lane = tid & 31;
    const int w = tid >> 5;

    const size_t colb = (size_t)h * HEAD_DIM;
    const size_t qrow0 = (size_t)b * SEQ + qt * 128;
    const size_t krow0 = (size_t)b * SEQ;

    // ---- stage Q tile (hi/lo), extract A-fragments ----
    #pragma unroll
    for (int i = 0; i < 4; i++) {
        int lin = i * 256 + tid;            // 0..1023
        int r = lin >> 3, c16 = lin & 7;
        uint32_t so = SW128B((uint32_t)(r * 128 + c16 * 16));
        *(uint4*)(sK0 + so) = *(const uint4*)(Qh + (qrow0 + r) * D_MODEL + colb + c16 * 8);
        *(uint4*)(sK1 + so) = *(const uint4*)(Ql + (qrow0 + r) * D_MODEL + colb + c16 * 8);
    }
    __syncthreads();

    uint32_t qfh[4][4], qfl[4][4];
    {
        int row = w * 16 + (lane & 15);
        #pragma unroll
        for (int u = 0; u < 4; u++) {
            uint32_t off = SW128B((uint32_t)(row * 128 + u * 32 + (lane >> 4) * 16));
            ldsm_x4(qfh[u], bK0 + off);
            ldsm_x4(qfl[u], bK1 + off);
        }
    }
    __syncthreads();

    float O[8][4];
    float Lac[4];
    #pragma unroll
    for (int t = 0; t < 8; t++)
        #pragma unroll
        for (int e = 0; e < 4; e++) O[t][e] = 0.f;
    Lac[0] = Lac[1] = Lac[2] = Lac[3] = 0.f;
    float m0 = -1e30f, m1 = -1e30f;

    const uint32_t ones2[2] = {0x3C003C00u, 0x3C003C00u};

    for (int kt = 0; kt < SEQ / 128; kt++) {
        // ---- load K/V tiles (hi/lo) ----
        #pragma unroll
        for (int i = 0; i < 4; i++) {
            int lin = i * 256 + tid;
            int r = lin >> 3, c16 = lin & 7;
            size_t ga = (krow0 + kt * 128 + r) * D_MODEL + colb + c16 * 8;
            uint32_t so = SW128B((uint32_t)(r * 128 + c16 * 16));
            *(uint4*)(sK0 + so) = *(const uint4*)(Kh + ga);
            *(uint4*)(sK1 + so) = *(const uint4*)(Kl + ga);
            *(uint4*)(sV0 + so) = *(const uint4*)(Vh + ga);
            *(uint4*)(sV1 + so) = *(const uint4*)(Vl + ga);
        }
        __syncthreads();

        // ---- S = Q@K^T (16 n-tiles of 8 keys) ----
        float sacc[16][4];
        #pragma unroll
        for (int t = 0; t < 16; t++)
            #pragma unroll
            for (int e = 0; e < 4; e++) sacc[t][e] = 0.f;

        #pragma unroll
        for (int u = 0; u < 4; u++) {
            #pragma unroll
            for (int tp = 0; tp < 8; tp++) {
                int row = tp * 16 + ((lane >> 4) << 3) + (lane & 7);
                uint32_t off = SW128B((uint32_t)(row * 128 + u * 32 + ((lane >> 3) & 1) * 16));
                uint32_t kh[4], kl[4];
                ldsm_x4(kh, bK0 + off);
                ldsm_x4(kl, bK1 + off);
                mma_bf16(sacc[2 * tp],     qfh[u], kh);
                mma_bf16(sacc[2 * tp + 1], qfh[u], kh + 2);
                mma_bf16(sacc[2 * tp],     qfh[u], kl);
                mma_bf16(sacc[2 * tp + 1], qfh[u], kl + 2);
                mma_bf16(sacc[2 * tp],     qfl[u], kh);
                mma_bf16(sacc[2 * tp + 1], qfl[u], kh + 2);
            }
        }

        // ---- online softmax (rows r=lane>>2 and r+8; 4-lane groups) ----
        float mx0 = sacc[0][0], mx1 = sacc[0][2];
        #pragma unroll
        for (int t = 0; t < 16; t++) {
            mx0 = fmaxf(mx0, fmaxf(sacc[t][0], sacc[t][1]));
            mx1 = fmaxf(mx1, fmaxf(sacc[t][2], sacc[t][3]));
        }
        mx0 = fmaxf(mx0, __shfl_xor_sync(0xffffffffu, mx0, 1));
        mx0 = fmaxf(mx0, __shfl_xor_sync(0xffffffffu, mx0, 2));
        mx1 = fmaxf(mx1, __shfl_xor_sync(0xffffffffu, mx1, 1));
        mx1 = fmaxf(mx1, __shfl_xor_sync(0xffffffffu, mx1, 2));

        float mn0 = fmaxf(m0, mx0), mn1 = fmaxf(m1, mx1);
        float c0 = exp2f(m0 - mn0), c1 = exp2f(m1 - mn1);
        m0 = mn0; m1 = mn1;

        #pragma unroll
        for (int t = 0; t < 8; t++) {
            O[t][0] *= c0; O[t][1] *= c0;
            O[t][2] *= c1; O[t][3] *= c1;
        }
        Lac[0] *= c0; Lac[1] *= c0; Lac[2] *= c1; Lac[3] *= c1;

        // ---- P = exp2(S - m) as f16 A-fragments ----
        uint32_t P[8][4];
        #pragma unroll
        for (int t = 0; t < 16; t++) {
            uint32_t x01 = ex2_f16x2(cvt_f16x2(sacc[t][1] - mn0, sacc[t][0] - mn0));
            uint32_t x23 = ex2_f16x2(cvt_f16x2(sacc[t][3] - mn1, sacc[t][2] - mn1));
            if (t & 1) { P[t >> 1][2] = x01; P[t >> 1][3] = x23; }
            else       { P[t >> 1][0] = x01; P[t >> 1][1] = x23; }
        }

        // ---- row sums via P x ones ----
        #pragma unroll
        for (int u = 0; u < 8; u++) mma_f16(Lac, P[u], ones2);

        // ---- O += P @ V (V hi + lo) ----
        #pragma unroll
        for (int v = 0; v < 4; v++) {
            #pragma unroll
            for (int u = 0; u < 8; u++) {
                int row = u * 16 + ((lane >> 3) & 1) * 8 + (lane & 7);
                uint32_t off = SW128B((uint32_t)(row * 128 + (2 * v + (lane >> 4)) * 16));
                uint32_t vh[4], vl[4];
                ldsm_x4_t(vh, bV0 + off);
                ldsm_x4_t(vl, bV1 + off);
                mma_f16(O[2 * v],     P[u], vh);
                mma_f16(O[2 * v + 1], P[u], vh + 2);
                mma_f16(O[2 * v],     P[u], vl);
                mma_f16(O[2 * v + 1], P[u], vl + 2);
            }
        }
        __syncthreads();
    }

    // ---- normalize + store ----
    float inv0 = 1.0f / Lac[0];
    float inv1 = 1.0f / Lac[2];
    size_t r0 = qrow0 + w * 16 + (lane >> 2);
    size_t r1 = r0 + 8;
    #pragma unroll
    for (int t = 0; t < 8; t++) {
        size_t col = colb + t * 8 + (lane & 3) * 2;
        *(float2*)(Og + r0 * D_MODEL + col) = make_float2(O[t][0] * inv0, O[t][1] * inv0);
        *(float2*)(Og + r1 * D_MODEL + col) = make_float2(O[t][2] * inv1, O[t][3] * inv1);
    }
}

// ---------------------------------------------------------------------------
extern "C" void kernel_launch(void* const* d_in, const int* in_sizes, int n_in,
                              void* d_out, int out_size)
{
    const float* query = (const float*)d_in[0];
    const float* key   = (const float*)d_in[1];
    const float* value = (const float*)d_in[2];
    const float* Wq    = (const float*)d_in[3];
    const float* bq    = (const float*)d_in[4];
    const float* Wk    = (const float*)d_in[5];
    const float* bk    = (const float*)d_in[6];
    const float* Wv    = (const float*)d_in[7];
    const float* bv    = (const float*)d_in[8];
    const float* Wo    = (const float*)d_in[9];
    const float* bo    = (const float*)d_in[10];
    float* out = (float*)d_out;

    uint16_t *Qh, *Ql, *Kh, *Kl, *Vh, *Vl;
    float* Ab;
    cudaGetSymbolAddress((void**)&Qh, g_Qh);
    cudaGetSymbolAddress((void**)&Ql, g_Ql);
    cudaGetSymbolAddress((void**)&Kh, g_Kh);
    cudaGetSymbolAddress((void**)&Kl, g_Kl);
    cudaGetSymbolAddress((void**)&Vh, g_Vh);
    cudaGetSymbolAddress((void**)&Vl, g_Vl);
    cudaGetSymbolAddress((void**)&Ab, g_A);

    cudaFuncSetAttribute(attn_mma,
                         cudaFuncAttributeMaxDynamicSharedMemorySize, 4 * TILE_B);

    dim3 gg(D_MODEL / 128, M_TOT / 128);   // (8, 32)

    gemm_mma<<<gg, 256>>>(query, Wq, bq, nullptr, Qh, Ql, QSCALE, 1);
    gemm_mma<<<gg, 256>>>(key,   Wk, bk, nullptr, Kh, Kl, 1.0f, 1);
    gemm_mma<<<gg, 256>>>(value, Wv, bv, nullptr, Vh, Vl, 1.0f, 2);

    attn_mma<<<dim3(SEQ / 128, B_SZ * N_HEADS), 256, 4 * TILE_B>>>(
        Qh, Ql, Kh, Kl, Vh, Vl, Ab);

    gemm_mma<<<gg, 256>>>(Ab, Wo, bo, out, nullptr, nullptr, 1.0f, 0);
}

// round 6
// speedup vs baseline: 5.1427x; 1.1889x over previous
#include <cuda_runtime.h>
#include <cuda_bf16.h>
#include <cuda_fp16.h>
#include <stdint.h>
#include <math.h>

#define D_MODEL 1024
#define N_HEADS 16
#define HEAD_DIM 64
#define B_SZ 2
#define SEQ 2048
#define M_TOT (B_SZ * SEQ)   // 4096

// Q pre-scale: 1/sqrt(64) * log2(e)  (softmax done in base-2)
#define QSCALE 0.1803368801111204f

// Scratch (allocation-free rule: device globals)
__device__ uint16_t g_Qh[(size_t)M_TOT * D_MODEL];   // bf16
__device__ uint16_t g_Ql[(size_t)M_TOT * D_MODEL];   // bf16
__device__ uint16_t g_Kh[(size_t)M_TOT * D_MODEL];   // bf16
__device__ uint16_t g_Kl[(size_t)M_TOT * D_MODEL];   // bf16
__device__ uint16_t g_Vh[(size_t)M_TOT * D_MODEL];   // f16
__device__ uint16_t g_Vl[(size_t)M_TOT * D_MODEL];   // f16
__device__ uint16_t g_Ah[(size_t)M_TOT * D_MODEL];   // bf16 (attn out hi)
__device__ uint16_t g_Al[(size_t)M_TOT * D_MODEL];   // bf16 (attn out lo)
__device__ uint16_t g_Xh[(size_t)M_TOT * D_MODEL];   // bf16 (gemm A hi)
__device__ uint16_t g_Xl[(size_t)M_TOT * D_MODEL];   // bf16 (gemm A lo)
__device__ uint16_t g_Wh[(size_t)D_MODEL * D_MODEL]; // bf16 (gemm B hi)
__device__ uint16_t g_Wl[(size_t)D_MODEL * D_MODEL]; // bf16 (gemm B lo)

// ===========================================================================
// helpers
// ===========================================================================
__device__ __forceinline__ uint32_t smem_u32(const void* p) {
    uint32_t a;
    asm("{ .reg .u64 t; cvta.to.shared.u64 t, %1; cvt.u32.u64 %0, t; }"
        : "=r"(a) : "l"(p));
    return a;
}

#define SW64(o)   ((o) ^ (((o) >> 3) & 0x30))
#define SW256(o)  ((o) ^ (((o) >> 4) & 0x70))
#define SW128B(o) ((o) ^ (((o) >> 3) & 0x70))

#define CP16(s, g) \
    asm volatile("cp.async.cg.shared.global [%0], [%1], 16;" :: "r"(s), "l"(g))
#define CP_COMMIT() asm volatile("cp.async.commit_group;" ::: "memory")
#define CP_WAIT(n)  asm volatile("cp.async.wait_group %0;" :: "n"(n) : "memory")

__device__ __forceinline__ void ldsm_x4(uint32_t* r, uint32_t a) {
    asm volatile("ldmatrix.sync.aligned.m8n8.x4.shared.b16 {%0,%1,%2,%3}, [%4];"
                 : "=r"(r[0]), "=r"(r[1]), "=r"(r[2]), "=r"(r[3]) : "r"(a));
}
__device__ __forceinline__ void ldsm_x4_t(uint32_t* r, uint32_t a) {
    asm volatile("ldmatrix.sync.aligned.m8n8.x4.trans.shared.b16 {%0,%1,%2,%3}, [%4];"
                 : "=r"(r[0]), "=r"(r[1]), "=r"(r[2]), "=r"(r[3]) : "r"(a));
}
__device__ __forceinline__ void mma_bf16(float* c, const uint32_t* a, const uint32_t* b) {
    asm volatile("mma.sync.aligned.m16n8k16.row.col.f32.bf16.bf16.f32 "
                 "{%0,%1,%2,%3}, {%4,%5,%6,%7}, {%8,%9}, {%0,%1,%2,%3};"
                 : "+f"(c[0]), "+f"(c[1]), "+f"(c[2]), "+f"(c[3])
                 : "r"(a[0]), "r"(a[1]), "r"(a[2]), "r"(a[3]),
                   "r"(b[0]), "r"(b[1]));
}
__device__ __forceinline__ void mma_f16(float* c, const uint32_t* a, const uint32_t* b) {
    asm volatile("mma.sync.aligned.m16n8k16.row.col.f32.f16.f16.f32 "
                 "{%0,%1,%2,%3}, {%4,%5,%6,%7}, {%8,%9}, {%0,%1,%2,%3};"
                 : "+f"(c[0]), "+f"(c[1]), "+f"(c[2]), "+f"(c[3])
                 : "r"(a[0]), "r"(a[1]), "r"(a[2]), "r"(a[3]),
                   "r"(b[0]), "r"(b[1]));
}
__device__ __forceinline__ uint32_t cvt_f16x2(float hi, float lo) {
    uint32_t d;
    asm("cvt.rn.f16x2.f32 %0, %1, %2;" : "=r"(d) : "f"(hi), "f"(lo));
    return d;
}
__device__ __forceinline__ uint32_t ex2_f16x2(uint32_t x) {
    uint32_t d;
    asm("ex2.approx.f16x2 %0, %1;" : "=r"(d) : "r"(x));
    return d;
}
__device__ __forceinline__ uint32_t pk_bf(float a, float b) {
    __nv_bfloat162 t = __floats2bfloat162_rn(a, b);
    return *(uint32_t*)&t;
}
__device__ __forceinline__ uint32_t pk_h(float a, float b) {
    __half2 t = __floats2half2_rn(a, b);
    return *(uint32_t*)&t;
}
__device__ __forceinline__ void cvt_hl(float4 v, uint2& hi, uint2& lo) {
    __nv_bfloat162 h01 = __floats2bfloat162_rn(v.x, v.y);
    __nv_bfloat162 h23 = __floats2bfloat162_rn(v.z, v.w);
    float f0 = __bfloat162float(__low2bfloat16(h01));
    float f1 = __bfloat162float(__high2bfloat16(h01));
    float f2 = __bfloat162float(__low2bfloat16(h23));
    float f3 = __bfloat162float(__high2bfloat16(h23));
    __nv_bfloat162 l01 = __floats2bfloat162_rn(v.x - f0, v.y - f1);
    __nv_bfloat162 l23 = __floats2bfloat162_rn(v.z - f2, v.w - f3);
    hi = make_uint2(*(uint32_t*)&h01, *(uint32_t*)&h23);
    lo = make_uint2(*(uint32_t*)&l01, *(uint32_t*)&l23);
}

// ===========================================================================
// Elementwise fp32 -> bf16 hi/lo pre-conversion
// ===========================================================================
__global__ __launch_bounds__(256)
void cvt_kernel(const float4* __restrict__ X, uint2* __restrict__ H,
                uint2* __restrict__ L, int n4)
{
    int i = blockIdx.x * 256 + threadIdx.x;
    if (i < n4) {
        uint2 hi, lo;
        cvt_hl(X[i], hi, lo);
        H[i] = hi;
        L[i] = lo;
    }
}

// ===========================================================================
// GEMM + bias, bf16 hi/lo (3 terms), pre-converted operands, cp.async
// double-buffered. Block 128x128, kc=32 (16 bf16 k x2), 256 threads.
// mode 0: fp32 -> C. mode 1: *scale -> bf16 hi/lo. mode 2: f16 hi/lo.
// Dyn smem per buf (48KB): Ah@0 Al@8K Bh@16K Bl@32K; 2 bufs = 96KB.
// ===========================================================================
#define GB 49152

__device__ __forceinline__ void gemm_load(
    const uint16_t* Xh, const uint16_t* Xl,
    const uint16_t* Wh, const uint16_t* Wl,
    int m0, int n0, int kc, uint32_t sb, int tid)
{
    #pragma unroll
    for (int i = 0; i < 2; i++) {
        int slot = i * 256 + tid;
        int r = slot >> 2, c = slot & 3;
        size_t g = (size_t)(m0 + r) * D_MODEL + kc * 32 + c * 8;
        uint32_t so = SW64((uint32_t)(r * 64 + c * 16));
        CP16(sb + so, Xh + g);
        CP16(sb + 8192 + so, Xl + g);
    }
    #pragma unroll
    for (int i = 0; i < 2; i++) {
        int slot = i * 256 + tid;
        int kr = slot >> 4, c = slot & 15;
        size_t g = (size_t)(kc * 32 + kr) * D_MODEL + n0 + c * 8;
        uint32_t so = SW256((uint32_t)(kr * 256 + c * 16));
        CP16(sb + 16384 + so, Wh + g);
        CP16(sb + 32768 + so, Wl + g);
    }
}

__global__ __launch_bounds__(256, 2)
void gemm_mma(const uint16_t* __restrict__ Xh, const uint16_t* __restrict__ Xl,
              const uint16_t* __restrict__ Wh, const uint16_t* __restrict__ Wl,
              const float* __restrict__ bias, float* __restrict__ C,
              uint16_t* __restrict__ Ch, uint16_t* __restrict__ Cl,
              float scale, int mode)
{
    extern __shared__ __align__(16) uint8_t dsm[];
    const uint32_t sb0 = smem_u32(dsm);

    const int tid  = threadIdx.x;
    const int lane = tid & 31;
    const int wid  = tid >> 5;
    const int m_w  = (wid & 3) * 32;
    const int n_w  = (wid >> 2) * 64;
    const int m0   = blockIdx.y * 128;
    const int n0   = blockIdx.x * 128;

    float acc[2][8][4];
    #pragma unroll
    for (int mi = 0; mi < 2; mi++)
        #pragma unroll
        for (int nj = 0; nj < 8; nj++)
            #pragma unroll
            for (int e = 0; e < 4; e++) acc[mi][nj][e] = 0.f;

    const int a_row = lane & 15;
    const int a_ch  = lane >> 4;
    const int b_kr  = (lane & 7) + ((lane >> 3) & 1) * 8;
    const int b_nc  = lane >> 4;

    gemm_load(Xh, Xl, Wh, Wl, m0, n0, 0, sb0, tid);
    CP_COMMIT();

    for (int kc = 0; kc < 32; kc++) {
        if (kc + 1 < 32) {
            gemm_load(Xh, Xl, Wh, Wl, m0, n0, kc + 1, sb0 + ((kc + 1) & 1) * GB, tid);
            CP_COMMIT();
            CP_WAIT(1);
        } else {
            CP_WAIT(0);
        }
        __syncthreads();

        const uint32_t bAh = sb0 + (kc & 1) * GB;
        const uint32_t bAl = bAh + 8192;
        const uint32_t bBh = bAh + 16384;
        const uint32_t bBl = bAh + 32768;

        #pragma unroll
        for (int ks = 0; ks < 2; ks++) {
            uint32_t ah[2][4], al[2][4];
            #pragma unroll
            for (int mi = 0; mi < 2; mi++) {
                uint32_t o = (uint32_t)((m_w + mi * 16 + a_row) * 64 + ks * 32 + a_ch * 16);
                ldsm_x4(ah[mi], bAh + SW64(o));
                ldsm_x4(al[mi], bAl + SW64(o));
            }
            #pragma unroll
            for (int njp = 0; njp < 4; njp++) {
                uint32_t o = (uint32_t)((ks * 16 + b_kr) * 256
                                        + (n_w + njp * 16) * 2 + b_nc * 16);
                uint32_t bh[4], bl[4];
                ldsm_x4_t(bh, bBh + SW256(o));
                ldsm_x4_t(bl, bBl + SW256(o));
                #pragma unroll
                for (int mi = 0; mi < 2; mi++) {
                    mma_bf16(acc[mi][njp * 2],     ah[mi], bh);
                    mma_bf16(acc[mi][njp * 2 + 1], ah[mi], bh + 2);
                    mma_bf16(acc[mi][njp * 2],     ah[mi], bl);
                    mma_bf16(acc[mi][njp * 2 + 1], ah[mi], bl + 2);
                    mma_bf16(acc[mi][njp * 2],     al[mi], bh);
                    mma_bf16(acc[mi][njp * 2 + 1], al[mi], bh + 2);
                }
            }
        }
        __syncthreads();
    }

    #pragma unroll
    for (int mi = 0; mi < 2; mi++) {
        #pragma unroll
        for (int nj = 0; nj < 8; nj++) {
            int col = n0 + n_w + nj * 8 + (lane & 3) * 2;
            int r0  = m0 + m_w + mi * 16 + (lane >> 2);
            float b0 = bias[col], b1 = bias[col + 1];
            float vx0 = (acc[mi][nj][0] + b0) * scale;
            float vy0 = (acc[mi][nj][1] + b1) * scale;
            float vx1 = (acc[mi][nj][2] + b0) * scale;
            float vy1 = (acc[mi][nj][3] + b1) * scale;
            if (mode == 0) {
                *(float2*)(C + (size_t)r0 * D_MODEL + col) = make_float2(vx0, vy0);
                *(float2*)(C + (size_t)(r0 + 8) * D_MODEL + col) = make_float2(vx1, vy1);
            } else if (mode == 1) {
                float hx0 = __bfloat162float(__float2bfloat16_rn(vx0));
                float hy0 = __bfloat162float(__float2bfloat16_rn(vy0));
                float hx1 = __bfloat162float(__float2bfloat16_rn(vx1));
                float hy1 = __bfloat162float(__float2bfloat16_rn(vy1));
                *(uint32_t*)(Ch + (size_t)r0 * D_MODEL + col) = pk_bf(hx0, hy0);
                *(uint32_t*)(Cl + (size_t)r0 * D_MODEL + col) = pk_bf(vx0 - hx0, vy0 - hy0);
                *(uint32_t*)(Ch + (size_t)(r0 + 8) * D_MODEL + col) = pk_bf(hx1, hy1);
                *(uint32_t*)(Cl + (size_t)(r0 + 8) * D_MODEL + col) = pk_bf(vx1 - hx1, vy1 - hy1);
            } else {
                float hx0 = __half2float(__float2half_rn(vx0));
                float hy0 = __half2float(__float2half_rn(vy0));
                float hx1 = __half2float(__float2half_rn(vx1));
                float hy1 = __half2float(__float2half_rn(vy1));
                *(uint32_t*)(Ch + (size_t)r0 * D_MODEL + col) = pk_h(hx0, hy0);
                *(uint32_t*)(Cl + (size_t)r0 * D_MODEL + col) = pk_h(vx0 - hx0, vy0 - hy0);
                *(uint32_t*)(Ch + (size_t)(r0 + 8) * D_MODEL + col) = pk_h(hx1, hy1);
                *(uint32_t*)(Cl + (size_t)(r0 + 8) * D_MODEL + col) = pk_h(vx1 - hx1, vy1 - hy1);
            }
        }
    }
}

// ===========================================================================
// Tensor-core flash attention, cp.async double-buffered K/V.
// Buffers: 2 x {Kh,Kl,Vh,Vl} 16KB tiles = 128KB dynamic smem.
// Epilogue writes bf16 hi/lo (feeds O-projection GEMM directly).
// ===========================================================================
#define TILE_B 16384

__device__ __forceinline__ void attn_load_kv(
    const uint16_t* Kh, const uint16_t* Kl,
    const uint16_t* Vh, const uint16_t* Vl,
    size_t rowbase, size_t colb, uint32_t bb, int tid)
{
    #pragma unroll
    for (int i = 0; i < 4; i++) {
        int lin = i * 256 + tid;
        int r = lin >> 3, c = lin & 7;
        size_t ga = (rowbase + r) * D_MODEL + colb + c * 8;
        uint32_t so = SW128B((uint32_t)(r * 128 + c * 16));
        CP16(bb + so, Kh + ga);
        CP16(bb + TILE_B + so, Kl + ga);
        CP16(bb + 2 * TILE_B + so, Vh + ga);
        CP16(bb + 3 * TILE_B + so, Vl + ga);
    }
}

__global__ __launch_bounds__(256)
void attn_mma(const uint16_t* __restrict__ Qh, const uint16_t* __restrict__ Ql,
              const uint16_t* __restrict__ Kh, const uint16_t* __restrict__ Kl,
              const uint16_t* __restrict__ Vh, const uint16_t* __restrict__ Vl,
              uint16_t* __restrict__ Ah, uint16_t* __restrict__ Al)
{
    extern __shared__ __align__(16) uint8_t smx[];
    const uint32_t sb0 = smem_u32(smx);

    const int qt = blockIdx.x;
    const int bh = blockIdx.y;
    const int b = bh >> 4, h = bh & 15;
    const int tid = threadIdx.x;
    const int lane = tid & 31;
    const int w = tid >> 5;

    const size_t colb = (size_t)h * HEAD_DIM;
    const size_t qrow0 = (size_t)b * SEQ + qt * 128;
    const size_t krow0 = (size_t)b * SEQ;

    // prefetch K/V tile 0 into buffer 0
    attn_load_kv(Kh, Kl, Vh, Vl, krow0, colb, sb0, tid);
    CP_COMMIT();

    // stage Q (hi/lo) in buffer 1 area, extract A-fragments
    {
        uint8_t* q0 = smx + 4 * TILE_B;
        uint8_t* q1 = smx + 5 * TILE_B;
        #pragma unroll
        for (int i = 0; i < 4; i++) {
            int lin = i * 256 + tid;
            int r = lin >> 3, c16 = lin & 7;
            uint32_t so = SW128B((uint32_t)(r * 128 + c16 * 16));
            *(uint4*)(q0 + so) = *(const uint4*)(Qh + (qrow0 + r) * D_MODEL + colb + c16 * 8);
            *(uint4*)(q1 + so) = *(const uint4*)(Ql + (qrow0 + r) * D_MODEL + colb + c16 * 8);
        }
    }
    __syncthreads();

    uint32_t qfh[4][4], qfl[4][4];
    {
        const uint32_t bq0 = sb0 + 4 * TILE_B, bq1 = sb0 + 5 * TILE_B;
        int row = w * 16 + (lane & 15);
        #pragma unroll
        for (int u = 0; u < 4; u++) {
            uint32_t off = SW128B((uint32_t)(row * 128 + u * 32 + (lane >> 4) * 16));
            ldsm_x4(qfh[u], bq0 + off);
            ldsm_x4(qfl[u], bq1 + off);
        }
    }
    __syncthreads();   // all frags extracted before buffer 1 is overwritten

    float O[8][4];
    float Lac[4];
    #pragma unroll
    for (int t = 0; t < 8; t++)
        #pragma unroll
        for (int e = 0; e < 4; e++) O[t][e] = 0.f;
    Lac[0] = Lac[1] = Lac[2] = Lac[3] = 0.f;
    float m0 = -1e30f, m1 = -1e30f;

    const uint32_t ones2[2] = {0x3C003C00u, 0x3C003C00u};

    for (int kt = 0; kt < SEQ / 128; kt++) {
        if (kt + 1 < SEQ / 128) {
            attn_load_kv(Kh, Kl, Vh, Vl, krow0 + (kt + 1) * 128, colb,
                         sb0 + ((kt + 1) & 1) * 4 * TILE_B, tid);
            CP_COMMIT();
            CP_WAIT(1);
        } else {
            CP_WAIT(0);
        }
        __syncthreads();

        const uint32_t bK0 = sb0 + (kt & 1) * 4 * TILE_B;
        const uint32_t bK1 = bK0 + TILE_B;
        const uint32_t bV0 = bK0 + 2 * TILE_B;
        const uint32_t bV1 = bK0 + 3 * TILE_B;

        // ---- S = Q@K^T ----
        float sacc[16][4];
        #pragma unroll
        for (int t = 0; t < 16; t++)
            #pragma unroll
            for (int e = 0; e < 4; e++) sacc[t][e] = 0.f;

        #pragma unroll
        for (int u = 0; u < 4; u++) {
            #pragma unroll
            for (int tp = 0; tp < 8; tp++) {
                int row = tp * 16 + ((lane >> 4) << 3) + (lane & 7);
                uint32_t off = SW128B((uint32_t)(row * 128 + u * 32 + ((lane >> 3) & 1) * 16));
                uint32_t kh[4], kl[4];
                ldsm_x4(kh, bK0 + off);
                ldsm_x4(kl, bK1 + off);
                mma_bf16(sacc[2 * tp],     qfh[u], kh);
                mma_bf16(sacc[2 * tp + 1], qfh[u], kh + 2);
                mma_bf16(sacc[2 * tp],     qfh[u], kl);
                mma_bf16(sacc[2 * tp + 1], qfh[u], kl + 2);
                mma_bf16(sacc[2 * tp],     qfl[u], kh);
                mma_bf16(sacc[2 * tp + 1], qfl[u], kh + 2);
            }
        }

        // ---- online softmax ----
        float mx0 = sacc[0][0], mx1 = sacc[0][2];
        #pragma unroll
        for (int t = 0; t < 16; t++) {
            mx0 = fmaxf(mx0, fmaxf(sacc[t][0], sacc[t][1]));
            mx1 = fmaxf(mx1, fmaxf(sacc[t][2], sacc[t][3]));
        }
        mx0 = fmaxf(mx0, __shfl_xor_sync(0xffffffffu, mx0, 1));
        mx0 = fmaxf(mx0, __shfl_xor_sync(0xffffffffu, mx0, 2));
        mx1 = fmaxf(mx1, __shfl_xor_sync(0xffffffffu, mx1, 1));
        mx1 = fmaxf(mx1, __shfl_xor_sync(0xffffffffu, mx1, 2));

        float mn0 = fmaxf(m0, mx0), mn1 = fmaxf(m1, mx1);
        float c0 = exp2f(m0 - mn0), c1 = exp2f(m1 - mn1);
        m0 = mn0; m1 = mn1;

        #pragma unroll
        for (int t = 0; t < 8; t++) {
            O[t][0] *= c0; O[t][1] *= c0;
            O[t][2] *= c1; O[t][3] *= c1;
        }
        Lac[0] *= c0; Lac[1] *= c0; Lac[2] *= c1; Lac[3] *= c1;

        // ---- P = exp2(S - m), f16 A-fragments ----
        uint32_t P[8][4];
        #pragma unroll
        for (int t = 0; t < 16; t++) {
            uint32_t x01 = ex2_f16x2(cvt_f16x2(sacc[t][1] - mn0, sacc[t][0] - mn0));
            uint32_t x23 = ex2_f16x2(cvt_f16x2(sacc[t][3] - mn1, sacc[t][2] - mn1));
            if (t & 1) { P[t >> 1][2] = x01; P[t >> 1][3] = x23; }
            else       { P[t >> 1][0] = x01; P[t >> 1][1] = x23; }
        }

        // ---- row sums ----
        #pragma unroll
        for (int u = 0; u < 8; u++) mma_f16(Lac, P[u], ones2);

        // ---- O += P @ V ----
        #pragma unroll
        for (int v = 0; v < 4; v++) {
            #pragma unroll
            for (int u = 0; u < 8; u++) {
                int row = u * 16 + ((lane >> 3) & 1) * 8 + (lane & 7);
                uint32_t off = SW128B((uint32_t)(row * 128 + (2 * v + (lane >> 4)) * 16));
                uint32_t vh[4], vl[4];
                ldsm_x4_t(vh, bV0 + off);
                ldsm_x4_t(vl, bV1 + off);
                mma_f16(O[2 * v],     P[u], vh);
                mma_f16(O[2 * v + 1], P[u], vh + 2);
                mma_f16(O[2 * v],     P[u], vl);
                mma_f16(O[2 * v + 1], P[u], vl + 2);
            }
        }
        __syncthreads();
    }

    // ---- normalize + store as bf16 hi/lo ----
    float inv0 = 1.0f / Lac[0];
    float inv1 = 1.0f / Lac[2];
    size_t r0 = qrow0 + w * 16 + (lane >> 2);
    size_t r1 = r0 + 8;
    #pragma unroll
    for (int t = 0; t < 8; t++) {
        size_t col = colb + t * 8 + (lane & 3) * 2;
        float v00 = O[t][0] * inv0, v01 = O[t][1] * inv0;
        float v10 = O[t][2] * inv1, v11 = O[t][3] * inv1;
        float h00 = __bfloat162float(__float2bfloat16_rn(v00));
        float h01 = __bfloat162float(__float2bfloat16_rn(v01));
        float h10 = __bfloat162float(__float2bfloat16_rn(v10));
        float h11 = __bfloat162float(__float2bfloat16_rn(v11));
        *(uint32_t*)(Ah + r0 * D_MODEL + col) = pk_bf(h00, h01);
        *(uint32_t*)(Al + r0 * D_MODEL + col) = pk_bf(v00 - h00, v01 - h01);
        *(uint32_t*)(Ah + r1 * D_MODEL + col) = pk_bf(h10, h11);
        *(uint32_t*)(Al + r1 * D_MODEL + col) = pk_bf(v10 - h10, v11 - h11);
    }
}

// ---------------------------------------------------------------------------
extern "C" void kernel_launch(void* const* d_in, const int* in_sizes, int n_in,
                              void* d_out, int out_size)
{
    const float* query = (const float*)d_in[0];
    const float* key   = (const float*)d_in[1];
    const float* value = (const float*)d_in[2];
    const float* Wq    = (const float*)d_in[3];
    const float* bq    = (const float*)d_in[4];
    const float* Wk    = (const float*)d_in[5];
    const float* bk    = (const float*)d_in[6];
    const float* Wv    = (const float*)d_in[7];
    const float* bv    = (const float*)d_in[8];
    const float* Wo    = (const float*)d_in[9];
    const float* bo    = (const float*)d_in[10];
    float* out = (float*)d_out;

    uint16_t *Qh, *Ql, *Kh, *Kl, *Vh, *Vl, *Ah, *Al, *Xh, *Xl, *Wh, *Wl;
    cudaGetSymbolAddress((void**)&Qh, g_Qh);
    cudaGetSymbolAddress((void**)&Ql, g_Ql);
    cudaGetSymbolAddress((void**)&Kh, g_Kh);
    cudaGetSymbolAddress((void**)&Kl, g_Kl);
    cudaGetSymbolAddress((void**)&Vh, g_Vh);
    cudaGetSymbolAddress((void**)&Vl, g_Vl);
    cudaGetSymbolAddress((void**)&Ah, g_Ah);
    cudaGetSymbolAddress((void**)&Al, g_Al);
    cudaGetSymbolAddress((void**)&Xh, g_Xh);
    cudaGetSymbolAddress((void**)&Xl, g_Xl);
    cudaGetSymbolAddress((void**)&Wh, g_Wh);
    cudaGetSymbolAddress((void**)&Wl, g_Wl);

    cudaFuncSetAttribute(gemm_mma,
                         cudaFuncAttributeMaxDynamicSharedMemorySize, 2 * GB);
    cudaFuncSetAttribute(attn_mma,
                         cudaFuncAttributeMaxDynamicSharedMemorySize, 8 * TILE_B);

    const int nX4 = M_TOT * D_MODEL / 4;       // 1M float4
    const int nW4 = D_MODEL * D_MODEL / 4;     // 256K float4
    dim3 gg(D_MODEL / 128, M_TOT / 128);       // (8, 32)

    // Q projection
    cvt_kernel<<<nX4 / 256, 256>>>((const float4*)query, (uint2*)Xh, (uint2*)Xl, nX4);
    cvt_kernel<<<nW4 / 256, 256>>>((const float4*)Wq, (uint2*)Wh, (uint2*)Wl, nW4);
    gemm_mma<<<gg, 256, 2 * GB>>>(Xh, Xl, Wh, Wl, bq, nullptr, Qh, Ql, QSCALE, 1);
    // K projection
    cvt_kernel<<<nX4 / 256, 256>>>((const float4*)key, (uint2*)Xh, (uint2*)Xl, nX4);
    cvt_kernel<<<nW4 / 256, 256>>>((const float4*)Wk, (uint2*)Wh, (uint2*)Wl, nW4);
    gemm_mma<<<gg, 256, 2 * GB>>>(Xh, Xl, Wh, Wl, bk, nullptr, Kh, Kl, 1.0f, 1);
    // V projection
    cvt_kernel<<<nX4 / 256, 256>>>((const float4*)value, (uint2*)Xh, (uint2*)Xl, nX4);
    cvt_kernel<<<nW4 / 256, 256>>>((const float4*)Wv, (uint2*)Wh, (uint2*)Wl, nW4);
    gemm_mma<<<gg, 256, 2 * GB>>>(Xh, Xl, Wh, Wl, bv, nullptr, Vh, Vl, 1.0f, 2);

    attn_mma<<<dim3(SEQ / 128, B_SZ * N_HEADS), 256, 8 * TILE_B>>>(
        Qh, Ql, Kh, Kl, Vh, Vl, Ah, Al);

    // O projection
    cvt_kernel<<<nW4 / 256, 256>>>((const float4*)Wo, (uint2*)Wh, (uint2*)Wl, nW4);
    gemm_mma<<<gg, 256, 2 * GB>>>(Ah, Al, Wh, Wl, bo, out, nullptr, nullptr, 1.0f, 0);
}

// round 7
// speedup vs baseline: 6.0954x; 1.1852x over previous
#include <cuda_runtime.h>
#include <cuda_bf16.h>
#include <cuda_fp16.h>
#include <stdint.h>
#include <math.h>

#define D_MODEL 1024
#define N_HEADS 16
#define HEAD_DIM 64
#define B_SZ 2
#define SEQ 2048
#define M_TOT (B_SZ * SEQ)   // 4096

// Q pre-scale: 1/sqrt(64) * log2(e)  (softmax done in base-2)
#define QSCALE 0.1803368801111204f

// Scratch (allocation-free rule: device globals)
__device__ uint16_t g_Qh[(size_t)M_TOT * D_MODEL];   // bf16
__device__ uint16_t g_Ql[(size_t)M_TOT * D_MODEL];   // bf16
__device__ uint16_t g_Kh[(size_t)M_TOT * D_MODEL];   // bf16
__device__ uint16_t g_Kl[(size_t)M_TOT * D_MODEL];   // bf16
__device__ uint16_t g_Vh[(size_t)M_TOT * D_MODEL];   // f16
__device__ uint16_t g_Vl[(size_t)M_TOT * D_MODEL];   // f16
__device__ uint16_t g_Ao[(size_t)M_TOT * D_MODEL];   // f16 (attn out, hi only)
__device__ uint16_t g_Xq[(size_t)M_TOT * D_MODEL];   // f16 (query hi)
__device__ uint16_t g_Xk[(size_t)M_TOT * D_MODEL];   // f16 (key hi)
__device__ uint16_t g_Xv[(size_t)M_TOT * D_MODEL];   // f16 (value hi)
__device__ uint16_t g_Wqh[(size_t)D_MODEL * D_MODEL], g_Wql[(size_t)D_MODEL * D_MODEL];
__device__ uint16_t g_Wkh[(size_t)D_MODEL * D_MODEL], g_Wkl[(size_t)D_MODEL * D_MODEL];
__device__ uint16_t g_Wvh[(size_t)D_MODEL * D_MODEL], g_Wvl[(size_t)D_MODEL * D_MODEL];
__device__ uint16_t g_Woh[(size_t)D_MODEL * D_MODEL], g_Wol[(size_t)D_MODEL * D_MODEL];

// ===========================================================================
// helpers
// ===========================================================================
__device__ __forceinline__ uint32_t smem_u32(const void* p) {
    uint32_t a;
    asm("{ .reg .u64 t; cvta.to.shared.u64 t, %1; cvt.u32.u64 %0, t; }"
        : "=r"(a) : "l"(p));
    return a;
}

#define SW64(o)   ((o) ^ (((o) >> 3) & 0x30))
#define SW256(o)  ((o) ^ (((o) >> 4) & 0x70))
#define SW128B(o) ((o) ^ (((o) >> 3) & 0x70))

#define CP16(s, g) \
    asm volatile("cp.async.cg.shared.global [%0], [%1], 16;" :: "r"(s), "l"(g))
#define CP_COMMIT() asm volatile("cp.async.commit_group;" ::: "memory")
#define CP_WAIT(n)  asm volatile("cp.async.wait_group %0;" :: "n"(n) : "memory")

__device__ __forceinline__ void ldsm_x4(uint32_t* r, uint32_t a) {
    asm volatile("ldmatrix.sync.aligned.m8n8.x4.shared.b16 {%0,%1,%2,%3}, [%4];"
                 : "=r"(r[0]), "=r"(r[1]), "=r"(r[2]), "=r"(r[3]) : "r"(a));
}
__device__ __forceinline__ void ldsm_x4_t(uint32_t* r, uint32_t a) {
    asm volatile("ldmatrix.sync.aligned.m8n8.x4.trans.shared.b16 {%0,%1,%2,%3}, [%4];"
                 : "=r"(r[0]), "=r"(r[1]), "=r"(r[2]), "=r"(r[3]) : "r"(a));
}
__device__ __forceinline__ void mma_bf16(float* c, const uint32_t* a, const uint32_t* b) {
    asm volatile("mma.sync.aligned.m16n8k16.row.col.f32.bf16.bf16.f32 "
                 "{%0,%1,%2,%3}, {%4,%5,%6,%7}, {%8,%9}, {%0,%1,%2,%3};"
                 : "+f"(c[0]), "+f"(c[1]), "+f"(c[2]), "+f"(c[3])
                 : "r"(a[0]), "r"(a[1]), "r"(a[2]), "r"(a[3]),
                   "r"(b[0]), "r"(b[1]));
}
__device__ __forceinline__ void mma_f16(float* c, const uint32_t* a, const uint32_t* b) {
    asm volatile("mma.sync.aligned.m16n8k16.row.col.f32.f16.f16.f32 "
                 "{%0,%1,%2,%3}, {%4,%5,%6,%7}, {%8,%9}, {%0,%1,%2,%3};"
                 : "+f"(c[0]), "+f"(c[1]), "+f"(c[2]), "+f"(c[3])
                 : "r"(a[0]), "r"(a[1]), "r"(a[2]), "r"(a[3]),
                   "r"(b[0]), "r"(b[1]));
}
__device__ __forceinline__ uint32_t cvt_f16x2(float hi, float lo) {
    uint32_t d;
    asm("cvt.rn.f16x2.f32 %0, %1, %2;" : "=r"(d) : "f"(hi), "f"(lo));
    return d;
}
__device__ __forceinline__ uint32_t ex2_f16x2(uint32_t x) {
    uint32_t d;
    asm("ex2.approx.f16x2 %0, %1;" : "=r"(d) : "r"(x));
    return d;
}
__device__ __forceinline__ uint32_t pk_bf(float a, float b) {
    __nv_bfloat162 t = __floats2bfloat162_rn(a, b);
    return *(uint32_t*)&t;
}
__device__ __forceinline__ uint32_t pk_h(float a, float b) {
    __half2 t = __floats2half2_rn(a, b);
    return *(uint32_t*)&t;
}
// fp32x4 -> f16 hi pair + residual lo pair
__device__ __forceinline__ void cvt_hl_f16(float4 v, uint2& hi, uint2& lo) {
    __half2 h01 = __floats2half2_rn(v.x, v.y);
    __half2 h23 = __floats2half2_rn(v.z, v.w);
    float f0 = __half2float(__low2half(h01));
    float f1 = __half2float(__high2half(h01));
    float f2 = __half2float(__low2half(h23));
    float f3 = __half2float(__high2half(h23));
    __half2 l01 = __floats2half2_rn(v.x - f0, v.y - f1);
    __half2 l23 = __floats2half2_rn(v.z - f2, v.w - f3);
    hi = make_uint2(*(uint32_t*)&h01, *(uint32_t*)&h23);
    lo = make_uint2(*(uint32_t*)&l01, *(uint32_t*)&l23);
}

// ===========================================================================
// Batched conversions
// ===========================================================================
#define NX4 (M_TOT * D_MODEL / 4)   // 1M float4 per activation tensor
#define NW4 (D_MODEL * D_MODEL / 4) // 256K float4 per weight

// 3 activation tensors -> f16 hi only
__global__ __launch_bounds__(256)
void cvt_x3(const float4* __restrict__ q, const float4* __restrict__ k,
            const float4* __restrict__ v, uint2* __restrict__ oq,
            uint2* __restrict__ ok, uint2* __restrict__ ov)
{
    int g = blockIdx.x * 256 + threadIdx.x;
    int sel = g / NX4, i = g - sel * NX4;
    const float4* src = (sel == 0) ? q : (sel == 1) ? k : v;
    uint2* dst = (sel == 0) ? oq : (sel == 1) ? ok : ov;
    float4 x = src[i];
    __half2 h01 = __floats2half2_rn(x.x, x.y);
    __half2 h23 = __floats2half2_rn(x.z, x.w);
    dst[i] = make_uint2(*(uint32_t*)&h01, *(uint32_t*)&h23);
}

// 4 weight tensors -> f16 hi/lo
__global__ __launch_bounds__(256)
void cvt_w4(const float4* __restrict__ w0, const float4* __restrict__ w1,
            const float4* __restrict__ w2, const float4* __restrict__ w3,
            uint2* __restrict__ h0, uint2* __restrict__ l0,
            uint2* __restrict__ h1, uint2* __restrict__ l1,
            uint2* __restrict__ h2, uint2* __restrict__ l2,
            uint2* __restrict__ h3, uint2* __restrict__ l3)
{
    int g = blockIdx.x * 256 + threadIdx.x;
    int sel = g / NW4, i = g - sel * NW4;
    const float4* src = (sel == 0) ? w0 : (sel == 1) ? w1 : (sel == 2) ? w2 : w3;
    uint2* H = (sel == 0) ? h0 : (sel == 1) ? h1 : (sel == 2) ? h2 : h3;
    uint2* L = (sel == 0) ? l0 : (sel == 1) ? l1 : (sel == 2) ? l2 : l3;
    uint2 hi, lo;
    cvt_hl_f16(src[i], hi, lo);
    H[i] = hi;
    L[i] = lo;
}

// ===========================================================================
// GEMM + bias, f16 2-term (Xh*Wh + Xh*Wl). Block 128x128, kc=32, cp.async
// double-buffered. Stage (24KB): Ah@0, Bh@8K, Bl@16K; 2 stages = 48KB.
// mode 0: fp32 -> C. mode 1: *scale -> bf16 hi/lo. mode 2: f16 hi/lo.
// ===========================================================================
#define GB 24576

__device__ __forceinline__ void gemm_load(
    const uint16_t* Xh, const uint16_t* Wh, const uint16_t* Wl,
    int m0, int n0, int kc, uint32_t sb, int tid)
{
    #pragma unroll
    for (int i = 0; i < 2; i++) {
        int slot = i * 256 + tid;
        int r = slot >> 2, c = slot & 3;
        size_t g = (size_t)(m0 + r) * D_MODEL + kc * 32 + c * 8;
        CP16(sb + SW64((uint32_t)(r * 64 + c * 16)), Xh + g);
    }
    #pragma unroll
    for (int i = 0; i < 2; i++) {
        int slot = i * 256 + tid;
        int kr = slot >> 4, c = slot & 15;
        size_t g = (size_t)(kc * 32 + kr) * D_MODEL + n0 + c * 8;
        uint32_t so = SW256((uint32_t)(kr * 256 + c * 16));
        CP16(sb + 8192 + so, Wh + g);
        CP16(sb + 16384 + so, Wl + g);
    }
}

__global__ __launch_bounds__(256, 2)
void gemm_mma(const uint16_t* __restrict__ Xh,
              const uint16_t* __restrict__ Wh, const uint16_t* __restrict__ Wl,
              const float* __restrict__ bias, float* __restrict__ C,
              uint16_t* __restrict__ Ch, uint16_t* __restrict__ Cl,
              float scale, int mode)
{
    extern __shared__ __align__(16) uint8_t dsm[];
    const uint32_t sb0 = smem_u32(dsm);

    const int tid  = threadIdx.x;
    const int lane = tid & 31;
    const int wid  = tid >> 5;
    const int m_w  = (wid & 3) * 32;
    const int n_w  = (wid >> 2) * 64;
    const int m0   = blockIdx.y * 128;
    const int n0   = blockIdx.x * 128;

    float acc[2][8][4];
    #pragma unroll
    for (int mi = 0; mi < 2; mi++)
        #pragma unroll
        for (int nj = 0; nj < 8; nj++)
            #pragma unroll
            for (int e = 0; e < 4; e++) acc[mi][nj][e] = 0.f;

    const int a_row = lane & 15;
    const int a_ch  = lane >> 4;
    const int b_kr  = (lane & 7) + ((lane >> 3) & 1) * 8;
    const int b_nc  = lane >> 4;

    gemm_load(Xh, Wh, Wl, m0, n0, 0, sb0, tid);
    CP_COMMIT();

    for (int kc = 0; kc < 32; kc++) {
        if (kc + 1 < 32) {
            gemm_load(Xh, Wh, Wl, m0, n0, kc + 1, sb0 + ((kc + 1) & 1) * GB, tid);
            CP_COMMIT();
            CP_WAIT(1);
        } else {
            CP_WAIT(0);
        }
        __syncthreads();

        const uint32_t bAh = sb0 + (kc & 1) * GB;
        const uint32_t bBh = bAh + 8192;
        const uint32_t bBl = bAh + 16384;

        #pragma unroll
        for (int ks = 0; ks < 2; ks++) {
            uint32_t ah[2][4];
            #pragma unroll
            for (int mi = 0; mi < 2; mi++) {
                uint32_t o = (uint32_t)((m_w + mi * 16 + a_row) * 64 + ks * 32 + a_ch * 16);
                ldsm_x4(ah[mi], bAh + SW64(o));
            }
            #pragma unroll
            for (int njp = 0; njp < 4; njp++) {
                uint32_t o = (uint32_t)((ks * 16 + b_kr) * 256
                                        + (n_w + njp * 16) * 2 + b_nc * 16);
                uint32_t bh[4], bl[4];
                ldsm_x4_t(bh, bBh + SW256(o));
                ldsm_x4_t(bl, bBl + SW256(o));
                #pragma unroll
                for (int mi = 0; mi < 2; mi++) {
                    mma_f16(acc[mi][njp * 2],     ah[mi], bh);
                    mma_f16(acc[mi][njp * 2 + 1], ah[mi], bh + 2);
                    mma_f16(acc[mi][njp * 2],     ah[mi], bl);
                    mma_f16(acc[mi][njp * 2 + 1], ah[mi], bl + 2);
                }
            }
        }
        __syncthreads();
    }

    #pragma unroll
    for (int mi = 0; mi < 2; mi++) {
        #pragma unroll
        for (int nj = 0; nj < 8; nj++) {
            int col = n0 + n_w + nj * 8 + (lane & 3) * 2;
            int r0  = m0 + m_w + mi * 16 + (lane >> 2);
            float b0 = bias[col], b1 = bias[col + 1];
            float vx0 = (acc[mi][nj][0] + b0) * scale;
            float vy0 = (acc[mi][nj][1] + b1) * scale;
            float vx1 = (acc[mi][nj][2] + b0) * scale;
            float vy1 = (acc[mi][nj][3] + b1) * scale;
            if (mode == 0) {
                *(float2*)(C + (size_t)r0 * D_MODEL + col) = make_float2(vx0, vy0);
                *(float2*)(C + (size_t)(r0 + 8) * D_MODEL + col) = make_float2(vx1, vy1);
            } else if (mode == 1) {
                float hx0 = __bfloat162float(__float2bfloat16_rn(vx0));
                float hy0 = __bfloat162float(__float2bfloat16_rn(vy0));
                float hx1 = __bfloat162float(__float2bfloat16_rn(vx1));
                float hy1 = __bfloat162float(__float2bfloat16_rn(vy1));
                *(uint32_t*)(Ch + (size_t)r0 * D_MODEL + col) = pk_bf(hx0, hy0);
                *(uint32_t*)(Cl + (size_t)r0 * D_MODEL + col) = pk_bf(vx0 - hx0, vy0 - hy0);
                *(uint32_t*)(Ch + (size_t)(r0 + 8) * D_MODEL + col) = pk_bf(hx1, hy1);
                *(uint32_t*)(Cl + (size_t)(r0 + 8) * D_MODEL + col) = pk_bf(vx1 - hx1, vy1 - hy1);
            } else {
                float hx0 = __half2float(__float2half_rn(vx0));
                float hy0 = __half2float(__float2half_rn(vy0));
                float hx1 = __half2float(__float2half_rn(vx1));
                float hy1 = __half2float(__float2half_rn(vy1));
                *(uint32_t*)(Ch + (size_t)r0 * D_MODEL + col) = pk_h(hx0, hy0);
                *(uint32_t*)(Cl + (size_t)r0 * D_MODEL + col) = pk_h(vx0 - hx0, vy0 - hy0);
                *(uint32_t*)(Ch + (size_t)(r0 + 8) * D_MODEL + col) = pk_h(hx1, hy1);
                *(uint32_t*)(Cl + (size_t)(r0 + 8) * D_MODEL + col) = pk_h(vx1 - hx1, vy1 - hy1);
            }
        }
    }
}

// ===========================================================================
// Tensor-core flash attention (unchanged math), f16-hi epilogue.
// ===========================================================================
#define TILE_B 16384

__device__ __forceinline__ void attn_load_kv(
    const uint16_t* Kh, const uint16_t* Kl,
    const uint16_t* Vh, const uint16_t* Vl,
    size_t rowbase, size_t colb, uint32_t bb, int tid)
{
    #pragma unroll
    for (int i = 0; i < 4; i++) {
        int lin = i * 256 + tid;
        int r = lin >> 3, c = lin & 7;
        size_t ga = (rowbase + r) * D_MODEL + colb + c * 8;
        uint32_t so = SW128B((uint32_t)(r * 128 + c * 16));
        CP16(bb + so, Kh + ga);
        CP16(bb + TILE_B + so, Kl + ga);
        CP16(bb + 2 * TILE_B + so, Vh + ga);
        CP16(bb + 3 * TILE_B + so, Vl + ga);
    }
}

__global__ __launch_bounds__(256)
void attn_mma(const uint16_t* __restrict__ Qh, const uint16_t* __restrict__ Ql,
              const uint16_t* __restrict__ Kh, const uint16_t* __restrict__ Kl,
              const uint16_t* __restrict__ Vh, const uint16_t* __restrict__ Vl,
              uint16_t* __restrict__ Ao)
{
    extern __shared__ __align__(16) uint8_t smx[];
    const uint32_t sb0 = smem_u32(smx);

    const int qt = blockIdx.x;
    const int bh = blockIdx.y;
    const int b = bh >> 4, h = bh & 15;
    const int tid = threadIdx.x;
    const int lane = tid & 31;
    const int w = tid >> 5;

    const size_t colb = (size_t)h * HEAD_DIM;
    const size_t qrow0 = (size_t)b * SEQ + qt * 128;
    const size_t krow0 = (size_t)b * SEQ;

    attn_load_kv(Kh, Kl, Vh, Vl, krow0, colb, sb0, tid);
    CP_COMMIT();

    {
        uint8_t* q0 = smx + 4 * TILE_B;
        uint8_t* q1 = smx + 5 * TILE_B;
        #pragma unroll
        for (int i = 0; i < 4; i++) {
            int lin = i * 256 + tid;
            int r = lin >> 3, c16 = lin & 7;
            uint32_t so = SW128B((uint32_t)(r * 128 + c16 * 16));
            *(uint4*)(q0 + so) = *(const uint4*)(Qh + (qrow0 + r) * D_MODEL + colb + c16 * 8);
            *(uint4*)(q1 + so) = *(const uint4*)(Ql + (qrow0 + r) * D_MODEL + colb + c16 * 8);
        }
    }
    __syncthreads();

    uint32_t qfh[4][4], qfl[4][4];
    {
        const uint32_t bq0 = sb0 + 4 * TILE_B, bq1 = sb0 + 5 * TILE_B;
        int row = w * 16 + (lane & 15);
        #pragma unroll
        for (int u = 0; u < 4; u++) {
            uint32_t off = SW128B((uint32_t)(row * 128 + u * 32 + (lane >> 4) * 16));
            ldsm_x4(qfh[u], bq0 + off);
            ldsm_x4(qfl[u], bq1 + off);
        }
    }
    __syncthreads();

    float O[8][4];
    float Lac[4];
    #pragma unroll
    for (int t = 0; t < 8; t++)
        #pragma unroll
        for (int e = 0; e < 4; e++) O[t][e] = 0.f;
    Lac[0] = Lac[1] = Lac[2] = Lac[3] = 0.f;
    float m0 = -1e30f, m1 = -1e30f;

    const uint32_t ones2[2] = {0x3C003C00u, 0x3C003C00u};

    for (int kt = 0; kt < SEQ / 128; kt++) {
        if (kt + 1 < SEQ / 128) {
            attn_load_kv(Kh, Kl, Vh, Vl, krow0 + (kt + 1) * 128, colb,
                         sb0 + ((kt + 1) & 1) * 4 * TILE_B, tid);
            CP_COMMIT();
            CP_WAIT(1);
        } else {
            CP_WAIT(0);
        }
        __syncthreads();

        const uint32_t bK0 = sb0 + (kt & 1) * 4 * TILE_B;
        const uint32_t bK1 = bK0 + TILE_B;
        const uint32_t bV0 = bK0 + 2 * TILE_B;
        const uint32_t bV1 = bK0 + 3 * TILE_B;

        float sacc[16][4];
        #pragma unroll
        for (int t = 0; t < 16; t++)
            #pragma unroll
            for (int e = 0; e < 4; e++) sacc[t][e] = 0.f;

        #pragma unroll
        for (int u = 0; u < 4; u++) {
            #pragma unroll
            for (int tp = 0; tp < 8; tp++) {
                int row = tp * 16 + ((lane >> 4) << 3) + (lane & 7);
                uint32_t off = SW128B((uint32_t)(row * 128 + u * 32 + ((lane >> 3) & 1) * 16));
                uint32_t kh[4], kl[4];
                ldsm_x4(kh, bK0 + off);
                ldsm_x4(kl, bK1 + off);
                mma_bf16(sacc[2 * tp],     qfh[u], kh);
                mma_bf16(sacc[2 * tp + 1], qfh[u], kh + 2);
                mma_bf16(sacc[2 * tp],     qfh[u], kl);
                mma_bf16(sacc[2 * tp + 1], qfh[u], kl + 2);
                mma_bf16(sacc[2 * tp],     qfl[u], kh);
                mma_bf16(sacc[2 * tp + 1], qfl[u], kh + 2);
            }
        }

        float mx0 = sacc[0][0], mx1 = sacc[0][2];
        #pragma unroll
        for (int t = 0; t < 16; t++) {
            mx0 = fmaxf(mx0, fmaxf(sacc[t][0], sacc[t][1]));
            mx1 = fmaxf(mx1, fmaxf(sacc[t][2], sacc[t][3]));
        }
        mx0 = fmaxf(mx0, __shfl_xor_sync(0xffffffffu, mx0, 1));
        mx0 = fmaxf(mx0, __shfl_xor_sync(0xffffffffu, mx0, 2));
        mx1 = fmaxf(mx1, __shfl_xor_sync(0xffffffffu, mx1, 1));
        mx1 = fmaxf(mx1, __shfl_xor_sync(0xffffffffu, mx1, 2));

        float mn0 = fmaxf(m0, mx0), mn1 = fmaxf(m1, mx1);
        float c0 = exp2f(m0 - mn0), c1 = exp2f(m1 - mn1);
        m0 = mn0; m1 = mn1;

        #pragma unroll
        for (int t = 0; t < 8; t++) {
            O[t][0] *= c0; O[t][1] *= c0;
            O[t][2] *= c1; O[t][3] *= c1;
        }
        Lac[0] *= c0; Lac[1] *= c0; Lac[2] *= c1; Lac[3] *= c1;

        uint32_t P[8][4];
        #pragma unroll
        for (int t = 0; t < 16; t++) {
            uint32_t x01 = ex2_f16x2(cvt_f16x2(sacc[t][1] - mn0, sacc[t][0] - mn0));
            uint32_t x23 = ex2_f16x2(cvt_f16x2(sacc[t][3] - mn1, sacc[t][2] - mn1));
            if (t & 1) { P[t >> 1][2] = x01; P[t >> 1][3] = x23; }
            else       { P[t >> 1][0] = x01; P[t >> 1][1] = x23; }
        }

        #pragma unroll
        for (int u = 0; u < 8; u++) mma_f16(Lac, P[u], ones2);

        #pragma unroll
        for (int v = 0; v < 4; v++) {
            #pragma unroll
            for (int u = 0; u < 8; u++) {
                int row = u * 16 + ((lane >> 3) & 1) * 8 + (lane & 7);
                uint32_t off = SW128B((uint32_t)(row * 128 + (2 * v + (lane >> 4)) * 16));
                uint32_t vh[4], vl[4];
                ldsm_x4_t(vh, bV0 + off);
                ldsm_x4_t(vl, bV1 + off);
                mma_f16(O[2 * v],     P[u], vh);
                mma_f16(O[2 * v + 1], P[u], vh + 2);
                mma_f16(O[2 * v],     P[u], vl);
                mma_f16(O[2 * v + 1], P[u], vl + 2);
            }
        }
        __syncthreads();
    }

    // ---- normalize + store as f16 hi (feeds 2-term O-projection) ----
    float inv0 = 1.0f / Lac[0];
    float inv1 = 1.0f / Lac[2];
    size_t r0 = qrow0 + w * 16 + (lane >> 2);
    size_t r1 = r0 + 8;
    #pragma unroll
    for (int t = 0; t < 8; t++) {
        size_t col = colb + t * 8 + (lane & 3) * 2;
        *(uint32_t*)(Ao + r0 * D_MODEL + col) = pk_h(O[t][0] * inv0, O[t][1] * inv0);
        *(uint32_t*)(Ao + r1 * D_MODEL + col) = pk_h(O[t][2] * inv1, O[t][3] * inv1);
    }
}

// ---------------------------------------------------------------------------
extern "C" void kernel_launch(void* const* d_in, const int* in_sizes, int n_in,
                              void* d_out, int out_size)
{
    const float* query = (const float*)d_in[0];
    const float* key   = (const float*)d_in[1];
    const float* value = (const float*)d_in[2];
    const float* Wq    = (const float*)d_in[3];
    const float* bq    = (const float*)d_in[4];
    const float* Wk    = (const float*)d_in[5];
    const float* bk    = (const float*)d_in[6];
    const float* Wv    = (const float*)d_in[7];
    const float* bv    = (const float*)d_in[8];
    const float* Wo    = (const float*)d_in[9];
    const float* bo    = (const float*)d_in[10];
    float* out = (float*)d_out;

    uint16_t *Qh, *Ql, *Kh, *Kl, *Vh, *Vl, *Ao, *Xq, *Xk, *Xv;
    uint16_t *Wqh, *Wql, *Wkh, *Wkl, *Wvh, *Wvl, *Woh, *Wol;
    cudaGetSymbolAddress((void**)&Qh, g_Qh);
    cudaGetSymbolAddress((void**)&Ql, g_Ql);
    cudaGetSymbolAddress((void**)&Kh, g_Kh);
    cudaGetSymbolAddress((void**)&Kl, g_Kl);
    cudaGetSymbolAddress((void**)&Vh, g_Vh);
    cudaGetSymbolAddress((void**)&Vl, g_Vl);
    cudaGetSymbolAddress((void**)&Ao, g_Ao);
    cudaGetSymbolAddress((void**)&Xq, g_Xq);
    cudaGetSymbolAddress((void**)&Xk, g_Xk);
    cudaGetSymbolAddress((void**)&Xv, g_Xv);
    cudaGetSymbolAddress((void**)&Wqh, g_Wqh);
    cudaGetSymbolAddress((void**)&Wql, g_Wql);
    cudaGetSymbolAddress((void**)&Wkh, g_Wkh);
    cudaGetSymbolAddress((void**)&Wkl, g_Wkl);
    cudaGetSymbolAddress((void**)&Wvh, g_Wvh);
    cudaGetSymbolAddress((void**)&Wvl, g_Wvl);
    cudaGetSymbolAddress((void**)&Woh, g_Woh);
    cudaGetSymbolAddress((void**)&Wol, g_Wol);

    cudaFuncSetAttribute(gemm_mma,
                         cudaFuncAttributeMaxDynamicSharedMemorySize, 2 * GB);
    cudaFuncSetAttribute(attn_mma,
                         cudaFuncAttributeMaxDynamicSharedMemorySize, 8 * TILE_B);

    dim3 gg(D_MODEL / 128, M_TOT / 128);   // (8, 32)

    cvt_x3<<<3 * NX4 / 256, 256>>>((const float4*)query, (const float4*)key,
                                   (const float4*)value,
                                   (uint2*)Xq, (uint2*)Xk, (uint2*)Xv);
    cvt_w4<<<4 * NW4 / 256, 256>>>((const float4*)Wq, (const float4*)Wk,
                                   (const float4*)Wv, (const float4*)Wo,
                                   (uint2*)Wqh, (uint2*)Wql, (uint2*)Wkh, (uint2*)Wkl,
                                   (uint2*)Wvh, (uint2*)Wvl, (uint2*)Woh, (uint2*)Wol);

    gemm_mma<<<gg, 256, 2 * GB>>>(Xq, Wqh, Wql, bq, nullptr, Qh, Ql, QSCALE, 1);
    gemm_mma<<<gg, 256, 2 * GB>>>(Xk, Wkh, Wkl, bk, nullptr, Kh, Kl, 1.0f, 1);
    gemm_mma<<<gg, 256, 2 * GB>>>(Xv, Wvh, Wvl, bv, nullptr, Vh, Vl, 1.0f, 2);

    attn_mma<<<dim3(SEQ / 128, B_SZ * N_HEADS), 256, 8 * TILE_B>>>(
        Qh, Ql, Kh, Kl, Vh, Vl, Ao);

    gemm_mma<<<gg, 256, 2 * GB>>>(Ao, Woh, Wol, bo, out, nullptr, nullptr, 1.0f, 0);
}

// round 8
// speedup vs baseline: 6.9375x; 1.1382x over previous
#include <cuda_runtime.h>
#include <cuda_bf16.h>
#include <cuda_fp16.h>
#include <stdint.h>
#include <math.h>

#define D_MODEL 1024
#define N_HEADS 16
#define HEAD_DIM 64
#define B_SZ 2
#define SEQ 2048
#define M_TOT (B_SZ * SEQ)   // 4096

// Q pre-scale: 1/sqrt(64) * log2(e)  (softmax done in base-2)
#define QSCALE 0.1803368801111204f

// Scratch (allocation-free rule: device globals)
__device__ uint16_t g_Qh[(size_t)M_TOT * D_MODEL];   // bf16
__device__ uint16_t g_Ql[(size_t)M_TOT * D_MODEL];   // bf16
__device__ uint16_t g_Kh[(size_t)M_TOT * D_MODEL];   // bf16
__device__ uint16_t g_Kl[(size_t)M_TOT * D_MODEL];   // bf16
__device__ uint16_t g_Vh[(size_t)M_TOT * D_MODEL];   // f16 (hi only)
__device__ uint16_t g_Ao[(size_t)M_TOT * D_MODEL];   // f16 (attn out, hi only)
__device__ uint16_t g_Xq[(size_t)M_TOT * D_MODEL];   // f16
__device__ uint16_t g_Xk[(size_t)M_TOT * D_MODEL];   // f16
__device__ uint16_t g_Xv[(size_t)M_TOT * D_MODEL];   // f16
__device__ uint16_t g_Wqh[(size_t)D_MODEL * D_MODEL], g_Wql[(size_t)D_MODEL * D_MODEL];
__device__ uint16_t g_Wkh[(size_t)D_MODEL * D_MODEL], g_Wkl[(size_t)D_MODEL * D_MODEL];
__device__ uint16_t g_Wvh[(size_t)D_MODEL * D_MODEL], g_Wvl[(size_t)D_MODEL * D_MODEL];
__device__ uint16_t g_Woh[(size_t)D_MODEL * D_MODEL], g_Wol[(size_t)D_MODEL * D_MODEL];

// ===========================================================================
// helpers
// ===========================================================================
__device__ __forceinline__ uint32_t smem_u32(const void* p) {
    uint32_t a;
    asm("{ .reg .u64 t; cvta.to.shared.u64 t, %1; cvt.u32.u64 %0, t; }"
        : "=r"(a) : "l"(p));
    return a;
}

#define SW64(o)   ((o) ^ (((o) >> 3) & 0x30))
#define SW256(o)  ((o) ^ (((o) >> 4) & 0x70))
#define SW128B(o) ((o) ^ (((o) >> 3) & 0x70))

#define CP16(s, g) \
    asm volatile("cp.async.cg.shared.global [%0], [%1], 16;" :: "r"(s), "l"(g))
#define CP_COMMIT() asm volatile("cp.async.commit_group;" ::: "memory")
#define CP_WAIT(n)  asm volatile("cp.async.wait_group %0;" :: "n"(n) : "memory")

__device__ __forceinline__ void ldsm_x4(uint32_t* r, uint32_t a) {
    asm volatile("ldmatrix.sync.aligned.m8n8.x4.shared.b16 {%0,%1,%2,%3}, [%4];"
                 : "=r"(r[0]), "=r"(r[1]), "=r"(r[2]), "=r"(r[3]) : "r"(a));
}
__device__ __forceinline__ void ldsm_x4_t(uint32_t* r, uint32_t a) {
    asm volatile("ldmatrix.sync.aligned.m8n8.x4.trans.shared.b16 {%0,%1,%2,%3}, [%4];"
                 : "=r"(r[0]), "=r"(r[1]), "=r"(r[2]), "=r"(r[3]) : "r"(a));
}
__device__ __forceinline__ void mma_bf16(float* c, const uint32_t* a, const uint32_t* b) {
    asm volatile("mma.sync.aligned.m16n8k16.row.col.f32.bf16.bf16.f32 "
                 "{%0,%1,%2,%3}, {%4,%5,%6,%7}, {%8,%9}, {%0,%1,%2,%3};"
                 : "+f"(c[0]), "+f"(c[1]), "+f"(c[2]), "+f"(c[3])
                 : "r"(a[0]), "r"(a[1]), "r"(a[2]), "r"(a[3]),
                   "r"(b[0]), "r"(b[1]));
}
__device__ __forceinline__ void mma_f16(float* c, const uint32_t* a, const uint32_t* b) {
    asm volatile("mma.sync.aligned.m16n8k16.row.col.f32.f16.f16.f32 "
                 "{%0,%1,%2,%3}, {%4,%5,%6,%7}, {%8,%9}, {%0,%1,%2,%3};"
                 : "+f"(c[0]), "+f"(c[1]), "+f"(c[2]), "+f"(c[3])
                 : "r"(a[0]), "r"(a[1]), "r"(a[2]), "r"(a[3]),
                   "r"(b[0]), "r"(b[1]));
}
__device__ __forceinline__ uint32_t cvt_f16x2(float hi, float lo) {
    uint32_t d;
    asm("cvt.rn.f16x2.f32 %0, %1, %2;" : "=r"(d) : "f"(hi), "f"(lo));
    return d;
}
__device__ __forceinline__ uint32_t ex2_f16x2(uint32_t x) {
    uint32_t d;
    asm("ex2.approx.f16x2 %0, %1;" : "=r"(d) : "r"(x));
    return d;
}
__device__ __forceinline__ uint32_t pk_bf(float a, float b) {
    __nv_bfloat162 t = __floats2bfloat162_rn(a, b);
    return *(uint32_t*)&t;
}
__device__ __forceinline__ uint32_t pk_h(float a, float b) {
    __half2 t = __floats2half2_rn(a, b);
    return *(uint32_t*)&t;
}
__device__ __forceinline__ void cvt_hl_f16(float4 v, uint2& hi, uint2& lo) {
    __half2 h01 = __floats2half2_rn(v.x, v.y);
    __half2 h23 = __floats2half2_rn(v.z, v.w);
    float f0 = __half2float(__low2half(h01));
    float f1 = __half2float(__high2half(h01));
    float f2 = __half2float(__low2half(h23));
    float f3 = __half2float(__high2half(h23));
    __half2 l01 = __floats2half2_rn(v.x - f0, v.y - f1);
    __half2 l23 = __floats2half2_rn(v.z - f2, v.w - f3);
    hi = make_uint2(*(uint32_t*)&h01, *(uint32_t*)&h23);
    lo = make_uint2(*(uint32_t*)&l01, *(uint32_t*)&l23);
}

// ===========================================================================
// Batched conversion: 3 activations (f16 hi) + 4 weights (f16 hi/lo), 1 launch
// ===========================================================================
#define NX4 (M_TOT * D_MODEL / 4)   // 1M float4 per activation tensor
#define NW4 (D_MODEL * D_MODEL / 4) // 256K float4 per weight

__global__ __launch_bounds__(256)
void cvt_all(const float4* __restrict__ q, const float4* __restrict__ k,
             const float4* __restrict__ v,
             const float4* __restrict__ w0, const float4* __restrict__ w1,
             const float4* __restrict__ w2, const float4* __restrict__ w3,
             uint2* __restrict__ oq, uint2* __restrict__ ok, uint2* __restrict__ ov,
             uint2* __restrict__ h0, uint2* __restrict__ l0,
             uint2* __restrict__ h1, uint2* __restrict__ l1,
             uint2* __restrict__ h2, uint2* __restrict__ l2,
             uint2* __restrict__ h3, uint2* __restrict__ l3)
{
    int g = blockIdx.x * 256 + threadIdx.x;
    if (g < 3 * NX4) {
        int sel = g / NX4, i = g - sel * NX4;
        const float4* src = (sel == 0) ? q : (sel == 1) ? k : v;
        uint2* dst = (sel == 0) ? oq : (sel == 1) ? ok : ov;
        float4 x = src[i];
        __half2 a = __floats2half2_rn(x.x, x.y);
        __half2 b = __floats2half2_rn(x.z, x.w);
        dst[i] = make_uint2(*(uint32_t*)&a, *(uint32_t*)&b);
    } else {
        int g2 = g - 3 * NX4;
        int sel = g2 / NW4, i = g2 - sel * NW4;
        const float4* src = (sel == 0) ? w0 : (sel == 1) ? w1 : (sel == 2) ? w2 : w3;
        uint2* H = (sel == 0) ? h0 : (sel == 1) ? h1 : (sel == 2) ? h2 : h3;
        uint2* L = (sel == 0) ? l0 : (sel == 1) ? l1 : (sel == 2) ? l2 : l3;
        uint2 hi, lo;
        cvt_hl_f16(src[i], hi, lo);
        H[i] = hi;
        L[i] = lo;
    }
}

// ===========================================================================
// GEMM core: f16 2-term (Xh*Wh + Xh*Wl), cp.async double-buffered.
// Block 128x128, kc=32. Stage 24KB: Ah@0, Bh@8K, Bl@16K.
// ===========================================================================
#define GB 24576

__device__ __forceinline__ void gemm_load(
    const uint16_t* Xh, const uint16_t* Wh, const uint16_t* Wl,
    int m0, int n0, int kc, uint32_t sb, int tid)
{
    #pragma unroll
    for (int i = 0; i < 2; i++) {
        int slot = i * 256 + tid;
        int r = slot >> 2, c = slot & 3;
        size_t g = (size_t)(m0 + r) * D_MODEL + kc * 32 + c * 8;
        CP16(sb + SW64((uint32_t)(r * 64 + c * 16)), Xh + g);
    }
    #pragma unroll
    for (int i = 0; i < 2; i++) {
        int slot = i * 256 + tid;
        int kr = slot >> 4, c = slot & 15;
        size_t g = (size_t)(kc * 32 + kr) * D_MODEL + n0 + c * 8;
        uint32_t so = SW256((uint32_t)(kr * 256 + c * 16));
        CP16(sb + 8192 + so, Wh + g);
        CP16(sb + 16384 + so, Wl + g);
    }
}

__device__ __forceinline__ void gemm_core(
    const uint16_t* Xh, const uint16_t* Wh, const uint16_t* Wl,
    uint32_t sb0, int m0, int n0, int tid, float acc[2][8][4])
{
    const int lane = tid & 31;
    const int wid  = tid >> 5;
    const int m_w  = (wid & 3) * 32;
    const int n_w  = (wid >> 2) * 64;
    const int a_row = lane & 15;
    const int a_ch  = lane >> 4;
    const int b_kr  = (lane & 7) + ((lane >> 3) & 1) * 8;
    const int b_nc  = lane >> 4;

    gemm_load(Xh, Wh, Wl, m0, n0, 0, sb0, tid);
    CP_COMMIT();

    for (int kc = 0; kc < 32; kc++) {
        if (kc + 1 < 32) {
            gemm_load(Xh, Wh, Wl, m0, n0, kc + 1, sb0 + ((kc + 1) & 1) * GB, tid);
            CP_COMMIT();
            CP_WAIT(1);
        } else {
            CP_WAIT(0);
        }
        __syncthreads();

        const uint32_t bAh = sb0 + (kc & 1) * GB;
        const uint32_t bBh = bAh + 8192;
        const uint32_t bBl = bAh + 16384;

        #pragma unroll
        for (int ks = 0; ks < 2; ks++) {
            uint32_t ah[2][4];
            #pragma unroll
            for (int mi = 0; mi < 2; mi++) {
                uint32_t o = (uint32_t)((m_w + mi * 16 + a_row) * 64 + ks * 32 + a_ch * 16);
                ldsm_x4(ah[mi], bAh + SW64(o));
            }
            #pragma unroll
            for (int njp = 0; njp < 4; njp++) {
                uint32_t o = (uint32_t)((ks * 16 + b_kr) * 256
                                        + (n_w + njp * 16) * 2 + b_nc * 16);
                uint32_t bh[4], bl[4];
                ldsm_x4_t(bh, bBh + SW256(o));
                ldsm_x4_t(bl, bBl + SW256(o));
                #pragma unroll
                for (int mi = 0; mi < 2; mi++) {
                    mma_f16(acc[mi][njp * 2],     ah[mi], bh);
                    mma_f16(acc[mi][njp * 2 + 1], ah[mi], bh + 2);
                    mma_f16(acc[mi][njp * 2],     ah[mi], bl);
                    mma_f16(acc[mi][njp * 2 + 1], ah[mi], bl + 2);
                }
            }
        }
        __syncthreads();
    }
}

// ---- batched QKV projection: grid.z selects tensor ----
__global__ __launch_bounds__(256, 2)
void gemm_qkv(const uint16_t* __restrict__ Xq, const uint16_t* __restrict__ Xk,
              const uint16_t* __restrict__ Xv,
              const uint16_t* __restrict__ Wqh, const uint16_t* __restrict__ Wql,
              const uint16_t* __restrict__ Wkh, const uint16_t* __restrict__ Wkl,
              const uint16_t* __restrict__ Wvh, const uint16_t* __restrict__ Wvl,
              const float* __restrict__ bq, const float* __restrict__ bk,
              const float* __restrict__ bv,
              uint16_t* __restrict__ Qh, uint16_t* __restrict__ Ql,
              uint16_t* __restrict__ Kh, uint16_t* __restrict__ Kl,
              uint16_t* __restrict__ Vh)
{
    extern __shared__ __align__(16) uint8_t dsm[];
    const uint32_t sb0 = smem_u32(dsm);
    const int tid = threadIdx.x;
    const int lane = tid & 31;
    const int wid = tid >> 5;
    const int m0 = blockIdx.y * 128;
    const int n0 = blockIdx.x * 128;
    const int z = blockIdx.z;

    const uint16_t* Xh = (z == 0) ? Xq : (z == 1) ? Xk : Xv;
    const uint16_t* Wh = (z == 0) ? Wqh : (z == 1) ? Wkh : Wvh;
    const uint16_t* Wl = (z == 0) ? Wql : (z == 1) ? Wkl : Wvl;
    const float* bias = (z == 0) ? bq : (z == 1) ? bk : bv;
    const float scale = (z == 0) ? QSCALE : 1.0f;

    float acc[2][8][4];
    #pragma unroll
    for (int mi = 0; mi < 2; mi++)
        #pragma unroll
        for (int nj = 0; nj < 8; nj++)
            #pragma unroll
            for (int e = 0; e < 4; e++) acc[mi][nj][e] = 0.f;

    gemm_core(Xh, Wh, Wl, sb0, m0, n0, tid, acc);

    const int m_w = (wid & 3) * 32;
    const int n_w = (wid >> 2) * 64;
    #pragma unroll
    for (int mi = 0; mi < 2; mi++) {
        #pragma unroll
        for (int nj = 0; nj < 8; nj++) {
            int col = n0 + n_w + nj * 8 + (lane & 3) * 2;
            int r0  = m0 + m_w + mi * 16 + (lane >> 2);
            float b0 = bias[col], b1 = bias[col + 1];
            float vx0 = (acc[mi][nj][0] + b0) * scale;
            float vy0 = (acc[mi][nj][1] + b1) * scale;
            float vx1 = (acc[mi][nj][2] + b0) * scale;
            float vy1 = (acc[mi][nj][3] + b1) * scale;
            if (z < 2) {
                uint16_t* Ch = (z == 0) ? Qh : Kh;
                uint16_t* Cl = (z == 0) ? Ql : Kl;
                float hx0 = __bfloat162float(__float2bfloat16_rn(vx0));
                float hy0 = __bfloat162float(__float2bfloat16_rn(vy0));
                float hx1 = __bfloat162float(__float2bfloat16_rn(vx1));
                float hy1 = __bfloat162float(__float2bfloat16_rn(vy1));
                *(uint32_t*)(Ch + (size_t)r0 * D_MODEL + col) = pk_bf(hx0, hy0);
                *(uint32_t*)(Cl + (size_t)r0 * D_MODEL + col) = pk_bf(vx0 - hx0, vy0 - hy0);
                *(uint32_t*)(Ch + (size_t)(r0 + 8) * D_MODEL + col) = pk_bf(hx1, hy1);
                *(uint32_t*)(Cl + (size_t)(r0 + 8) * D_MODEL + col) = pk_bf(vx1 - hx1, vy1 - hy1);
            } else {
                *(uint32_t*)(Vh + (size_t)r0 * D_MODEL + col) = pk_h(vx0, vy0);
                *(uint32_t*)(Vh + (size_t)(r0 + 8) * D_MODEL + col) = pk_h(vx1, vy1);
            }
        }
    }
}

// ---- O projection: fp32 out ----
__global__ __launch_bounds__(256, 2)
void gemm_o(const uint16_t* __restrict__ Xh,
            const uint16_t* __restrict__ Wh, const uint16_t* __restrict__ Wl,
            const float* __restrict__ bias, float* __restrict__ C)
{
    extern __shared__ __align__(16) uint8_t dsm[];
    const uint32_t sb0 = smem_u32(dsm);
    const int tid = threadIdx.x;
    const int lane = tid & 31;
    const int wid = tid >> 5;
    const int m0 = blockIdx.y * 128;
    const int n0 = blockIdx.x * 128;

    float acc[2][8][4];
    #pragma unroll
    for (int mi = 0; mi < 2; mi++)
        #pragma unroll
        for (int nj = 0; nj < 8; nj++)
            #pragma unroll
            for (int e = 0; e < 4; e++) acc[mi][nj][e] = 0.f;

    gemm_core(Xh, Wh, Wl, sb0, m0, n0, tid, acc);

    const int m_w = (wid & 3) * 32;
    const int n_w = (wid >> 2) * 64;
    #pragma unroll
    for (int mi = 0; mi < 2; mi++) {
        #pragma unroll
        for (int nj = 0; nj < 8; nj++) {
            int col = n0 + n_w + nj * 8 + (lane & 3) * 2;
            int r0  = m0 + m_w + mi * 16 + (lane >> 2);
            float b0 = bias[col], b1 = bias[col + 1];
            *(float2*)(C + (size_t)r0 * D_MODEL + col) =
                make_float2(acc[mi][nj][0] + b0, acc[mi][nj][1] + b1);
            *(float2*)(C + (size_t)(r0 + 8) * D_MODEL + col) =
                make_float2(acc[mi][nj][2] + b0, acc[mi][nj][3] + b1);
        }
    }
}

// ===========================================================================
// Tensor-core flash attention. K bf16 hi/lo (3-term S), V f16 hi-only PV.
// Buffers: 2 x {Kh,Kl,Vh} = 6 x 16KB = 96KB dynamic smem.
// ===========================================================================
#define TILE_B 16384

__device__ __forceinline__ void attn_load_kv(
    const uint16_t* Kh, const uint16_t* Kl, const uint16_t* Vh,
    size_t rowbase, size_t colb, uint32_t bb, int tid)
{
    #pragma unroll
    for (int i = 0; i < 4; i++) {
        int lin = i * 256 + tid;
        int r = lin >> 3, c = lin & 7;
        size_t ga = (rowbase + r) * D_MODEL + colb + c * 8;
        uint32_t so = SW128B((uint32_t)(r * 128 + c * 16));
        CP16(bb + so, Kh + ga);
        CP16(bb + TILE_B + so, Kl + ga);
        CP16(bb + 2 * TILE_B + so, Vh + ga);
    }
}

__global__ __launch_bounds__(256)
void attn_mma(const uint16_t* __restrict__ Qh, const uint16_t* __restrict__ Ql,
              const uint16_t* __restrict__ Kh, const uint16_t* __restrict__ Kl,
              const uint16_t* __restrict__ Vh, uint16_t* __restrict__ Ao)
{
    extern __shared__ __align__(16) uint8_t smx[];
    const uint32_t sb0 = smem_u32(smx);

    const int qt = blockIdx.x;
    const int bh = blockIdx.y;
    const int b = bh >> 4, h = bh & 15;
    const int tid = threadIdx.x;
    const int lane = tid & 31;
    const int w = tid >> 5;

    const size_t colb = (size_t)h * HEAD_DIM;
    const size_t qrow0 = (size_t)b * SEQ + qt * 128;
    const size_t krow0 = (size_t)b * SEQ;

    attn_load_kv(Kh, Kl, Vh, krow0, colb, sb0, tid);
    CP_COMMIT();

    // stage Q (hi/lo) in buffer-1 area (overwritten by first prefetch later)
    {
        uint8_t* q0 = smx + 3 * TILE_B;
        uint8_t* q1 = smx + 4 * TILE_B;
        #pragma unroll
        for (int i = 0; i < 4; i++) {
            int lin = i * 256 + tid;
            int r = lin >> 3, c16 = lin & 7;
            uint32_t so = SW128B((uint32_t)(r * 128 + c16 * 16));
            *(uint4*)(q0 + so) = *(const uint4*)(Qh + (qrow0 + r) * D_MODEL + colb + c16 * 8);
            *(uint4*)(q1 + so) = *(const uint4*)(Ql + (qrow0 + r) * D_MODEL + colb + c16 * 8);
        }
    }
    __syncthreads();

    uint32_t qfh[4][4], qfl[4][4];
    {
        const uint32_t bq0 = sb0 + 3 * TILE_B, bq1 = sb0 + 4 * TILE_B;
        int row = w * 16 + (lane & 15);
        #pragma unroll
        for (int u = 0; u < 4; u++) {
            uint32_t off = SW128B((uint32_t)(row * 128 + u * 32 + (lane >> 4) * 16));
            ldsm_x4(qfh[u], bq0 + off);
            ldsm_x4(qfl[u], bq1 + off);
        }
    }
    __syncthreads();   // frags extracted before buffer-1 is overwritten

    float O[8][4];
    float Lac[4];
    #pragma unroll
    for (int t = 0; t < 8; t++)
        #pragma unroll
        for (int e = 0; e < 4; e++) O[t][e] = 0.f;
    Lac[0] = Lac[1] = Lac[2] = Lac[3] = 0.f;
    float m0 = -1e30f, m1 = -1e30f;

    const uint32_t ones2[2] = {0x3C003C00u, 0x3C003C00u};

    for (int kt = 0; kt < SEQ / 128; kt++) {
        if (kt + 1 < SEQ / 128) {
            attn_load_kv(Kh, Kl, Vh, krow0 + (kt + 1) * 128, colb,
                         sb0 + ((kt + 1) & 1) * 3 * TILE_B, tid);
            CP_COMMIT();
            CP_WAIT(1);
        } else {
            CP_WAIT(0);
        }
        __syncthreads();

        const uint32_t bK0 = sb0 + (kt & 1) * 3 * TILE_B;
        const uint32_t bK1 = bK0 + TILE_B;
        const uint32_t bV0 = bK0 + 2 * TILE_B;

        float sacc[16][4];
        #pragma unroll
        for (int t = 0; t < 16; t++)
            #pragma unroll
            for (int e = 0; e < 4; e++) sacc[t][e] = 0.f;

        #pragma unroll
        for (int u = 0; u < 4; u++) {
            #pragma unroll
            for (int tp = 0; tp < 8; tp++) {
                int row = tp * 16 + ((lane >> 4) << 3) + (lane & 7);
                uint32_t off = SW128B((uint32_t)(row * 128 + u * 32 + ((lane >> 3) & 1) * 16));
                uint32_t kh[4], kl[4];
                ldsm_x4(kh, bK0 + off);
                ldsm_x4(kl, bK1 + off);
                mma_bf16(sacc[2 * tp],     qfh[u], kh);
                mma_bf16(sacc[2 * tp + 1], qfh[u], kh + 2);
                mma_bf16(sacc[2 * tp],     qfh[u], kl);
                mma_bf16(sacc[2 * tp + 1], qfh[u], kl + 2);
                mma_bf16(sacc[2 * tp],     qfl[u], kh);
                mma_bf16(sacc[2 * tp + 1], qfl[u], kh + 2);
            }
        }

        float mx0 = sacc[0][0], mx1 = sacc[0][2];
        #pragma unroll
        for (int t = 0; t < 16; t++) {
            mx0 = fmaxf(mx0, fmaxf(sacc[t][0], sacc[t][1]));
            mx1 = fmaxf(mx1, fmaxf(sacc[t][2], sacc[t][3]));
        }
        mx0 = fmaxf(mx0, __shfl_xor_sync(0xffffffffu, mx0, 1));
        mx0 = fmaxf(mx0, __shfl_xor_sync(0xffffffffu, mx0, 2));
        mx1 = fmaxf(mx1, __shfl_xor_sync(0xffffffffu, mx1, 1));
        mx1 = fmaxf(mx1, __shfl_xor_sync(0xffffffffu, mx1, 2));

        float mn0 = fmaxf(m0, mx0), mn1 = fmaxf(m1, mx1);
        float c0 = exp2f(m0 - mn0), c1 = exp2f(m1 - mn1);
        m0 = mn0; m1 = mn1;

        #pragma unroll
        for (int t = 0; t < 8; t++) {
            O[t][0] *= c0; O[t][1] *= c0;
            O[t][2] *= c1; O[t][3] *= c1;
        }
        Lac[0] *= c0; Lac[1] *= c0; Lac[2] *= c1; Lac[3] *= c1;

        uint32_t P[8][4];
        #pragma unroll
        for (int t = 0; t < 16; t++) {
            uint32_t x01 = ex2_f16x2(cvt_f16x2(sacc[t][1] - mn0, sacc[t][0] - mn0));
            uint32_t x23 = ex2_f16x2(cvt_f16x2(sacc[t][3] - mn1, sacc[t][2] - mn1));
            if (t & 1) { P[t >> 1][2] = x01; P[t >> 1][3] = x23; }
            else       { P[t >> 1][0] = x01; P[t >> 1][1] = x23; }
        }

        #pragma unroll
        for (int u = 0; u < 8; u++) mma_f16(Lac, P[u], ones2);

        #pragma unroll
        for (int v = 0; v < 4; v++) {
            #pragma unroll
            for (int u = 0; u < 8; u++) {
                int row = u * 16 + ((lane >> 3) & 1) * 8 + (lane & 7);
                uint32_t off = SW128B((uint32_t)(row * 128 + (2 * v + (lane >> 4)) * 16));
                uint32_t vh[4];
                ldsm_x4_t(vh, bV0 + off);
                mma_f16(O[2 * v],     P[u], vh);
                mma_f16(O[2 * v + 1], P[u], vh + 2);
            }
        }
        __syncthreads();
    }

    float inv0 = 1.0f / Lac[0];
    float inv1 = 1.0f / Lac[2];
    size_t r0 = qrow0 + w * 16 + (lane >> 2);
    size_t r1 = r0 + 8;
    #pragma unroll
    for (int t = 0; t < 8; t++) {
        size_t col = colb + t * 8 + (lane & 3) * 2;
        *(uint32_t*)(Ao + r0 * D_MODEL + col) = pk_h(O[t][0] * inv0, O[t][1] * inv0);
        *(uint32_t*)(Ao + r1 * D_MODEL + col) = pk_h(O[t][2] * inv1, O[t][3] * inv1);
    }
}

// ---------------------------------------------------------------------------
extern "C" void kernel_launch(void* const* d_in, const int* in_sizes, int n_in,
                              void* d_out, int out_size)
{
    const float* query = (const float*)d_in[0];
    const float* key   = (const float*)d_in[1];
    const float* value = (const float*)d_in[2];
    const float* Wq    = (const float*)d_in[3];
    const float* bq    = (const float*)d_in[4];
    const float* Wk    = (const float*)d_in[5];
    const float* bk    = (const float*)d_in[6];
    const float* Wv    = (const float*)d_in[7];
    const float* bv    = (const float*)d_in[8];
    const float* Wo    = (const float*)d_in[9];
    const float* bo    = (const float*)d_in[10];
    float* out = (float*)d_out;

    uint16_t *Qh, *Ql, *Kh, *Kl, *Vh, *Ao, *Xq, *Xk, *Xv;
    uint16_t *Wqh, *Wql, *Wkh, *Wkl, *Wvh, *Wvl, *Woh, *Wol;
    cudaGetSymbolAddress((void**)&Qh, g_Qh);
    cudaGetSymbolAddress((void**)&Ql, g_Ql);
    cudaGetSymbolAddress((void**)&Kh, g_Kh);
    cudaGetSymbolAddress((void**)&Kl, g_Kl);
    cudaGetSymbolAddress((void**)&Vh, g_Vh);
    cudaGetSymbolAddress((void**)&Ao, g_Ao);
    cudaGetSymbolAddress((void**)&Xq, g_Xq);
    cudaGetSymbolAddress((void**)&Xk, g_Xk);
    cudaGetSymbolAddress((void**)&Xv, g_Xv);
    cudaGetSymbolAddress((void**)&Wqh, g_Wqh);
    cudaGetSymbolAddress((void**)&Wql, g_Wql);
    cudaGetSymbolAddress((void**)&Wkh, g_Wkh);
    cudaGetSymbolAddress((void**)&Wkl, g_Wkl);
    cudaGetSymbolAddress((void**)&Wvh, g_Wvh);
    cudaGetSymbolAddress((void**)&Wvl, g_Wvl);
    cudaGetSymbolAddress((void**)&Woh, g_Woh);
    cudaGetSymbolAddress((void**)&Wol, g_Wol);

    cudaFuncSetAttribute(gemm_qkv,
                         cudaFuncAttributeMaxDynamicSharedMemorySize, 2 * GB);
    cudaFuncSetAttribute(gemm_o,
                         cudaFuncAttributeMaxDynamicSharedMemorySize, 2 * GB);
    cudaFuncSetAttribute(attn_mma,
                         cudaFuncAttributeMaxDynamicSharedMemorySize, 6 * TILE_B);

    const int n_cvt = 3 * NX4 + 4 * NW4;   // 4,194,304 threads
    cvt_all<<<n_cvt / 256, 256>>>(
        (const float4*)query, (const float4*)key, (const float4*)value,
        (const float4*)Wq, (const float4*)Wk, (const float4*)Wv, (const float4*)Wo,
        (uint2*)Xq, (uint2*)Xk, (uint2*)Xv,
        (uint2*)Wqh, (uint2*)Wql, (uint2*)Wkh, (uint2*)Wkl,
        (uint2*)Wvh, (uint2*)Wvl, (uint2*)Woh, (uint2*)Wol);

    gemm_qkv<<<dim3(D_MODEL / 128, M_TOT / 128, 3), 256, 2 * GB>>>(
        Xq, Xk, Xv, Wqh, Wql, Wkh, Wkl, Wvh, Wvl, bq, bk, bv,
        Qh, Ql, Kh, Kl, Vh);

    attn_mma<<<dim3(SEQ / 128, B_SZ * N_HEADS), 256, 6 * TILE_B>>>(
        Qh, Ql, Kh, Kl, Vh, Ao);

    gemm_o<<<dim3(D_MODEL / 128, M_TOT / 128), 256, 2 * GB>>>(Ao, Woh, Wol, bo, out);
}

// round 9
// speedup vs baseline: 8.6815x; 1.2514x over previous
#include <cuda_runtime.h>
#include <cuda_bf16.h>
#include <cuda_fp16.h>
#include <stdint.h>
#include <math.h>

#define D_MODEL 1024
#define N_HEADS 16
#define HEAD_DIM 64
#define B_SZ 2
#define SEQ 2048
#define M_TOT (B_SZ * SEQ)   // 4096

// Q pre-scale: 1/sqrt(64) * log2(e)  (softmax done in base-2)
#define QSCALE 0.1803368801111204f

// Scratch (allocation-free rule: device globals)
__device__ uint16_t g_Qh[(size_t)M_TOT * D_MODEL];   // bf16
__device__ uint16_t g_Ql[(size_t)M_TOT * D_MODEL];   // bf16
__device__ uint16_t g_Kh[(size_t)M_TOT * D_MODEL];   // bf16
__device__ uint16_t g_Kl[(size_t)M_TOT * D_MODEL];   // bf16
__device__ uint16_t g_Vh[(size_t)M_TOT * D_MODEL];   // f16 (hi only)
__device__ uint16_t g_Ao[(size_t)M_TOT * D_MODEL];   // f16 (attn out, hi only)
__device__ uint16_t g_Xq[(size_t)M_TOT * D_MODEL];   // f16
__device__ uint16_t g_Xk[(size_t)M_TOT * D_MODEL];   // f16
__device__ uint16_t g_Xv[(size_t)M_TOT * D_MODEL];   // f16
__device__ uint16_t g_Wq16[(size_t)D_MODEL * D_MODEL];  // f16
__device__ uint16_t g_Wk16[(size_t)D_MODEL * D_MODEL];  // f16
__device__ uint16_t g_Wv16[(size_t)D_MODEL * D_MODEL];  // f16
__device__ uint16_t g_Wo16[(size_t)D_MODEL * D_MODEL];  // f16

// ===========================================================================
// helpers
// ===========================================================================
__device__ __forceinline__ uint32_t smem_u32(const void* p) {
    uint32_t a;
    asm("{ .reg .u64 t; cvta.to.shared.u64 t, %1; cvt.u32.u64 %0, t; }"
        : "=r"(a) : "l"(p));
    return a;
}

#define SW64(o)   ((o) ^ (((o) >> 3) & 0x30))
#define SW256(o)  ((o) ^ (((o) >> 4) & 0x70))
#define SW128B(o) ((o) ^ (((o) >> 3) & 0x70))

#define CP16(s, g) \
    asm volatile("cp.async.cg.shared.global [%0], [%1], 16;" :: "r"(s), "l"(g))
#define CP_COMMIT() asm volatile("cp.async.commit_group;" ::: "memory")
#define CP_WAIT(n)  asm volatile("cp.async.wait_group %0;" :: "n"(n) : "memory")

__device__ __forceinline__ void ldsm_x4(uint32_t* r, uint32_t a) {
    asm volatile("ldmatrix.sync.aligned.m8n8.x4.shared.b16 {%0,%1,%2,%3}, [%4];"
                 : "=r"(r[0]), "=r"(r[1]), "=r"(r[2]), "=r"(r[3]) : "r"(a));
}
__device__ __forceinline__ void ldsm_x4_t(uint32_t* r, uint32_t a) {
    asm volatile("ldmatrix.sync.aligned.m8n8.x4.trans.shared.b16 {%0,%1,%2,%3}, [%4];"
                 : "=r"(r[0]), "=r"(r[1]), "=r"(r[2]), "=r"(r[3]) : "r"(a));
}
__device__ __forceinline__ void mma_bf16(float* c, const uint32_t* a, const uint32_t* b) {
    asm volatile("mma.sync.aligned.m16n8k16.row.col.f32.bf16.bf16.f32 "
                 "{%0,%1,%2,%3}, {%4,%5,%6,%7}, {%8,%9}, {%0,%1,%2,%3};"
                 : "+f"(c[0]), "+f"(c[1]), "+f"(c[2]), "+f"(c[3])
                 : "r"(a[0]), "r"(a[1]), "r"(a[2]), "r"(a[3]),
                   "r"(b[0]), "r"(b[1]));
}
__device__ __forceinline__ void mma_f16(float* c, const uint32_t* a, const uint32_t* b) {
    asm volatile("mma.sync.aligned.m16n8k16.row.col.f32.f16.f16.f32 "
                 "{%0,%1,%2,%3}, {%4,%5,%6,%7}, {%8,%9}, {%0,%1,%2,%3};"
                 : "+f"(c[0]), "+f"(c[1]), "+f"(c[2]), "+f"(c[3])
                 : "r"(a[0]), "r"(a[1]), "r"(a[2]), "r"(a[3]),
                   "r"(b[0]), "r"(b[1]));
}
__device__ __forceinline__ uint32_t cvt_f16x2(float hi, float lo) {
    uint32_t d;
    asm("cvt.rn.f16x2.f32 %0, %1, %2;" : "=r"(d) : "f"(hi), "f"(lo));
    return d;
}
__device__ __forceinline__ uint32_t ex2_f16x2(uint32_t x) {
    uint32_t d;
    asm("ex2.approx.f16x2 %0, %1;" : "=r"(d) : "r"(x));
    return d;
}
__device__ __forceinline__ uint32_t pk_bf(float a, float b) {
    __nv_bfloat162 t = __floats2bfloat162_rn(a, b);
    return *(uint32_t*)&t;
}
__device__ __forceinline__ uint32_t pk_h(float a, float b) {
    __half2 t = __floats2half2_rn(a, b);
    return *(uint32_t*)&t;
}

// ===========================================================================
// Batched conversion: 7 fp32 tensors -> f16 hi, 1 launch
// ===========================================================================
#define NX4 (M_TOT * D_MODEL / 4)   // 1M float4 per activation tensor
#define NW4 (D_MODEL * D_MODEL / 4) // 256K float4 per weight

__global__ __launch_bounds__(256)
void cvt_all(const float4* __restrict__ q, const float4* __restrict__ k,
             const float4* __restrict__ v,
             const float4* __restrict__ w0, const float4* __restrict__ w1,
             const float4* __restrict__ w2, const float4* __restrict__ w3,
             uint2* __restrict__ oq, uint2* __restrict__ ok, uint2* __restrict__ ov,
             uint2* __restrict__ ow0, uint2* __restrict__ ow1,
             uint2* __restrict__ ow2, uint2* __restrict__ ow3)
{
    int g = blockIdx.x * 256 + threadIdx.x;
    const float4* src;
    uint2* dst;
    int i;
    if (g < 3 * NX4) {
        int sel = g / NX4;
        i = g - sel * NX4;
        src = (sel == 0) ? q : (sel == 1) ? k : v;
        dst = (sel == 0) ? oq : (sel == 1) ? ok : ov;
    } else {
        int g2 = g - 3 * NX4;
        int sel = g2 / NW4;
        i = g2 - sel * NW4;
        src = (sel == 0) ? w0 : (sel == 1) ? w1 : (sel == 2) ? w2 : w3;
        dst = (sel == 0) ? ow0 : (sel == 1) ? ow1 : (sel == 2) ? ow2 : ow3;
    }
    float4 x = src[i];
    __half2 a = __floats2half2_rn(x.x, x.y);
    __half2 b = __floats2half2_rn(x.z, x.w);
    dst[i] = make_uint2(*(uint32_t*)&a, *(uint32_t*)&b);
}

// ===========================================================================
// GEMM core: single-term f16 (Xh*Wh), 3-stage cp.async pipeline.
// Block 128x128, kc=32. Stage 16KB: A@0, B@8K.
// ===========================================================================
#define GB 16384

__device__ __forceinline__ void gemm_load(
    const uint16_t* Xh, const uint16_t* Wh,
    int m0, int n0, int kc, uint32_t sb, int tid)
{
    #pragma unroll
    for (int i = 0; i < 2; i++) {
        int slot = i * 256 + tid;
        int r = slot >> 2, c = slot & 3;
        size_t g = (size_t)(m0 + r) * D_MODEL + kc * 32 + c * 8;
        CP16(sb + SW64((uint32_t)(r * 64 + c * 16)), Xh + g);
    }
    #pragma unroll
    for (int i = 0; i < 2; i++) {
        int slot = i * 256 + tid;
        int kr = slot >> 4, c = slot & 15;
        size_t g = (size_t)(kc * 32 + kr) * D_MODEL + n0 + c * 8;
        CP16(sb + 8192 + SW256((uint32_t)(kr * 256 + c * 16)), Wh + g);
    }
}

__device__ __forceinline__ void gemm_core(
    const uint16_t* Xh, const uint16_t* Wh,
    uint32_t sb0, int m0, int n0, int tid, float acc[2][8][4])
{
    const int lane = tid & 31;
    const int wid  = tid >> 5;
    const int m_w  = (wid & 3) * 32;
    const int n_w  = (wid >> 2) * 64;
    const int a_row = lane & 15;
    const int a_ch  = lane >> 4;
    const int b_kr  = (lane & 7) + ((lane >> 3) & 1) * 8;
    const int b_nc  = lane >> 4;

    gemm_load(Xh, Wh, m0, n0, 0, sb0, tid);
    CP_COMMIT();
    gemm_load(Xh, Wh, m0, n0, 1, sb0 + GB, tid);
    CP_COMMIT();

    int put = 2;
    for (int kc = 0; kc < 32; kc++) {
        if (kc + 2 < 32) {
            gemm_load(Xh, Wh, m0, n0, kc + 2, sb0 + (put % 3) * GB, tid);
            put++;
            CP_COMMIT();
            CP_WAIT(2);
        } else if (kc + 1 < 32) {
            CP_WAIT(1);
        } else {
            CP_WAIT(0);
        }
        __syncthreads();

        const uint32_t bA = sb0 + (kc % 3) * GB;
        const uint32_t bB = bA + 8192;

        #pragma unroll
        for (int ks = 0; ks < 2; ks++) {
            uint32_t ah[2][4];
            #pragma unroll
            for (int mi = 0; mi < 2; mi++) {
                uint32_t o = (uint32_t)((m_w + mi * 16 + a_row) * 64 + ks * 32 + a_ch * 16);
                ldsm_x4(ah[mi], bA + SW64(o));
            }
            #pragma unroll
            for (int njp = 0; njp < 4; njp++) {
                uint32_t o = (uint32_t)((ks * 16 + b_kr) * 256
                                        + (n_w + njp * 16) * 2 + b_nc * 16);
                uint32_t bh[4];
                ldsm_x4_t(bh, bB + SW256(o));
                #pragma unroll
                for (int mi = 0; mi < 2; mi++) {
                    mma_f16(acc[mi][njp * 2],     ah[mi], bh);
                    mma_f16(acc[mi][njp * 2 + 1], ah[mi], bh + 2);
                }
            }
        }
        __syncthreads();
    }
}

// ---- batched QKV projection: grid.z selects tensor ----
__global__ __launch_bounds__(256, 2)
void gemm_qkv(const uint16_t* __restrict__ Xq, const uint16_t* __restrict__ Xk,
              const uint16_t* __restrict__ Xv,
              const uint16_t* __restrict__ Wq16, const uint16_t* __restrict__ Wk16,
              const uint16_t* __restrict__ Wv16,
              const float* __restrict__ bq, const float* __restrict__ bk,
              const float* __restrict__ bv,
              uint16_t* __restrict__ Qh, uint16_t* __restrict__ Ql,
              uint16_t* __restrict__ Kh, uint16_t* __restrict__ Kl,
              uint16_t* __restrict__ Vh)
{
    extern __shared__ __align__(16) uint8_t dsm[];
    const uint32_t sb0 = smem_u32(dsm);
    const int tid = threadIdx.x;
    const int lane = tid & 31;
    const int wid = tid >> 5;
    const int m0 = blockIdx.y * 128;
    const int n0 = blockIdx.x * 128;
    const int z = blockIdx.z;

    const uint16_t* Xh = (z == 0) ? Xq : (z == 1) ? Xk : Xv;
    const uint16_t* Wh = (z == 0) ? Wq16 : (z == 1) ? Wk16 : Wv16;
    const float* bias = (z == 0) ? bq : (z == 1) ? bk : bv;
    const float scale = (z == 0) ? QSCALE : 1.0f;

    float acc[2][8][4];
    #pragma unroll
    for (int mi = 0; mi < 2; mi++)
        #pragma unroll
        for (int nj = 0; nj < 8; nj++)
            #pragma unroll
            for (int e = 0; e < 4; e++) acc[mi][nj][e] = 0.f;

    gemm_core(Xh, Wh, sb0, m0, n0, tid, acc);

    const int m_w = (wid & 3) * 32;
    const int n_w = (wid >> 2) * 64;
    #pragma unroll
    for (int mi = 0; mi < 2; mi++) {
        #pragma unroll
        for (int nj = 0; nj < 8; nj++) {
            int col = n0 + n_w + nj * 8 + (lane & 3) * 2;
            int r0  = m0 + m_w + mi * 16 + (lane >> 2);
            float b0 = bias[col], b1 = bias[col + 1];
            float vx0 = (acc[mi][nj][0] + b0) * scale;
            float vy0 = (acc[mi][nj][1] + b1) * scale;
            float vx1 = (acc[mi][nj][2] + b0) * scale;
            float vy1 = (acc[mi][nj][3] + b1) * scale;
            if (z < 2) {
                uint16_t* Ch = (z == 0) ? Qh : Kh;
                uint16_t* Cl = (z == 0) ? Ql : Kl;
                float hx0 = __bfloat162float(__float2bfloat16_rn(vx0));
                float hy0 = __bfloat162float(__float2bfloat16_rn(vy0));
                float hx1 = __bfloat162float(__float2bfloat16_rn(vx1));
                float hy1 = __bfloat162float(__float2bfloat16_rn(vy1));
                *(uint32_t*)(Ch + (size_t)r0 * D_MODEL + col) = pk_bf(hx0, hy0);
                *(uint32_t*)(Cl + (size_t)r0 * D_MODEL + col) = pk_bf(vx0 - hx0, vy0 - hy0);
                *(uint32_t*)(Ch + (size_t)(r0 + 8) * D_MODEL + col) = pk_bf(hx1, hy1);
                *(uint32_t*)(Cl + (size_t)(r0 + 8) * D_MODEL + col) = pk_bf(vx1 - hx1, vy1 - hy1);
            } else {
                *(uint32_t*)(Vh + (size_t)r0 * D_MODEL + col) = pk_h(vx0, vy0);
                *(uint32_t*)(Vh + (size_t)(r0 + 8) * D_MODEL + col) = pk_h(vx1, vy1);
            }
        }
    }
}

// ---- O projection: fp32 out ----
__global__ __launch_bounds__(256, 2)
void gemm_o(const uint16_t* __restrict__ Xh, const uint16_t* __restrict__ Wh,
            const float* __restrict__ bias, float* __restrict__ C)
{
    extern __shared__ __align__(16) uint8_t dsm[];
    const uint32_t sb0 = smem_u32(dsm);
    const int tid = threadIdx.x;
    const int lane = tid & 31;
    const int wid = tid >> 5;
    const int m0 = blockIdx.y * 128;
    const int n0 = blockIdx.x * 128;

    float acc[2][8][4];
    #pragma unroll
    for (int mi = 0; mi < 2; mi++)
        #pragma unroll
        for (int nj = 0; nj < 8; nj++)
            #pragma unroll
            for (int e = 0; e < 4; e++) acc[mi][nj][e] = 0.f;

    gemm_core(Xh, Wh, sb0, m0, n0, tid, acc);

    const int m_w = (wid & 3) * 32;
    const int n_w = (wid >> 2) * 64;
    #pragma unroll
    for (int mi = 0; mi < 2; mi++) {
        #pragma unroll
        for (int nj = 0; nj < 8; nj++) {
            int col = n0 + n_w + nj * 8 + (lane & 3) * 2;
            int r0  = m0 + m_w + mi * 16 + (lane >> 2);
            float b0 = bias[col], b1 = bias[col + 1];
            *(float2*)(C + (size_t)r0 * D_MODEL + col) =
                make_float2(acc[mi][nj][0] + b0, acc[mi][nj][1] + b1);
            *(float2*)(C + (size_t)(r0 + 8) * D_MODEL + col) =
                make_float2(acc[mi][nj][2] + b0, acc[mi][nj][3] + b1);
        }
    }
}

// ===========================================================================
// Tensor-core flash attention: 128-thread CTAs (q-tile 64), 2 CTAs/SM.
// K bf16 hi/lo (3-term S), V f16 hi-only. 2 x {Kh,Kl,Vh} = 96KB smem.
// ===========================================================================
#define TILE_B 16384

__device__ __forceinline__ void attn_load_kv(
    const uint16_t* Kh, const uint16_t* Kl, const uint16_t* Vh,
    size_t rowbase, size_t colb, uint32_t bb, int tid)
{
    #pragma unroll
    for (int i = 0; i < 8; i++) {
        int lin = i * 128 + tid;
        int r = lin >> 3, c = lin & 7;
        size_t ga = (rowbase + r) * D_MODEL + colb + c * 8;
        uint32_t so = SW128B((uint32_t)(r * 128 + c * 16));
        CP16(bb + so, Kh + ga);
        CP16(bb + TILE_B + so, Kl + ga);
        CP16(bb + 2 * TILE_B + so, Vh + ga);
    }
}

__global__ __launch_bounds__(128, 2)
void attn_mma(const uint16_t* __restrict__ Qh, const uint16_t* __restrict__ Ql,
              const uint16_t* __restrict__ Kh, const uint16_t* __restrict__ Kl,
              const uint16_t* __restrict__ Vh, uint16_t* __restrict__ Ao)
{
    extern __shared__ __align__(16) uint8_t smx[];
    const uint32_t sb0 = smem_u32(smx);

    const int qt = blockIdx.x;
    const int bh = blockIdx.y;
    const int b = bh >> 4, h = bh & 15;
    const int tid = threadIdx.x;
    const int lane = tid & 31;
    const int w = tid >> 5;          // 0..3

    const size_t colb = (size_t)h * HEAD_DIM;
    const size_t qrow0 = (size_t)b * SEQ + qt * 64;
    const size_t krow0 = (size_t)b * SEQ;

    attn_load_kv(Kh, Kl, Vh, krow0, colb, sb0, tid);
    CP_COMMIT();

    // stage Q (hi/lo, 64 rows) in buffer-1 tiles 3,4 (overwritten later)
    {
        uint8_t* q0 = smx + 3 * TILE_B;
        uint8_t* q1 = smx + 4 * TILE_B;
        #pragma unroll
        for (int i = 0; i < 4; i++) {
            int lin = i * 128 + tid;
            int r = lin >> 3, c16 = lin & 7;
            uint32_t so = SW128B((uint32_t)(r * 128 + c16 * 16));
            *(uint4*)(q0 + so) = *(const uint4*)(Qh + (qrow0 + r) * D_MODEL + colb + c16 * 8);
            *(uint4*)(q1 + so) = *(const uint4*)(Ql + (qrow0 + r) * D_MODEL + colb + c16 * 8);
        }
    }
    __syncthreads();

    uint32_t qfh[4][4], qfl[4][4];
    {
        const uint32_t bq0 = sb0 + 3 * TILE_B, bq1 = sb0 + 4 * TILE_B;
        int row = w * 16 + (lane & 15);
        #pragma unroll
        for (int u = 0; u < 4; u++) {
            uint32_t off = SW128B((uint32_t)(row * 128 + u * 32 + (lane >> 4) * 16));
            ldsm_x4(qfh[u], bq0 + off);
            ldsm_x4(qfl[u], bq1 + off);
        }
    }
    __syncthreads();   // frags extracted before buffer-1 is overwritten

    float O[8][4];
    float Lac[4];
    #pragma unroll
    for (int t = 0; t < 8; t++)
        #pragma unroll
        for (int e = 0; e < 4; e++) O[t][e] = 0.f;
    Lac[0] = Lac[1] = Lac[2] = Lac[3] = 0.f;
    float m0 = -1e30f, m1 = -1e30f;

    const uint32_t ones2[2] = {0x3C003C00u, 0x3C003C00u};

    for (int kt = 0; kt < SEQ / 128; kt++) {
        if (kt + 1 < SEQ / 128) {
            attn_load_kv(Kh, Kl, Vh, krow0 + (kt + 1) * 128, colb,
                         sb0 + ((kt + 1) & 1) * 3 * TILE_B, tid);
            CP_COMMIT();
            CP_WAIT(1);
        } else {
            CP_WAIT(0);
        }
        __syncthreads();

        const uint32_t bK0 = sb0 + (kt & 1) * 3 * TILE_B;
        const uint32_t bK1 = bK0 + TILE_B;
        const uint32_t bV0 = bK0 + 2 * TILE_B;

        float sacc[16][4];
        #pragma unroll
        for (int t = 0; t < 16; t++)
            #pragma unroll
            for (int e = 0; e < 4; e++) sacc[t][e] = 0.f;

        #pragma unroll
        for (int u = 0; u < 4; u++) {
            #pragma unroll
            for (int tp = 0; tp < 8; tp++) {
                int row = tp * 16 + ((lane >> 4) << 3) + (lane & 7);
                uint32_t off = SW128B((uint32_t)(row * 128 + u * 32 + ((lane >> 3) & 1) * 16));
                uint32_t kh[4], kl[4];
                ldsm_x4(kh, bK0 + off);
                ldsm_x4(kl, bK1 + off);
                mma_bf16(sacc[2 * tp],     qfh[u], kh);
                mma_bf16(sacc[2 * tp + 1], qfh[u], kh + 2);
                mma_bf16(sacc[2 * tp],     qfh[u], kl);
                mma_bf16(sacc[2 * tp + 1], qfh[u], kl + 2);
                mma_bf16(sacc[2 * tp],     qfl[u], kh);
                mma_bf16(sacc[2 * tp + 1], qfl[u], kh + 2);
            }
        }

        float mx0 = sacc[0][0], mx1 = sacc[0][2];
        #pragma unroll
        for (int t = 0; t < 16; t++) {
            mx0 = fmaxf(mx0, fmaxf(sacc[t][0], sacc[t][1]));
            mx1 = fmaxf(mx1, fmaxf(sacc[t][2], sacc[t][3]));
        }
        mx0 = fmaxf(mx0, __shfl_xor_sync(0xffffffffu, mx0, 1));
        mx0 = fmaxf(mx0, __shfl_xor_sync(0xffffffffu, mx0, 2));
        mx1 = fmaxf(mx1, __shfl_xor_sync(0xffffffffu, mx1, 1));
        mx1 = fmaxf(mx1, __shfl_xor_sync(0xffffffffu, mx1, 2));

        float mn0 = fmaxf(m0, mx0), mn1 = fmaxf(m1, mx1);
        float c0 = exp2f(m0 - mn0), c1 = exp2f(m1 - mn1);
        m0 = mn0; m1 = mn1;

        #pragma unroll
        for (int t = 0; t < 8; t++) {
            O[t][0] *= c0; O[t][1] *= c0;
            O[t][2] *= c1; O[t][3] *= c1;
        }
        Lac[0] *= c0; Lac[1] *= c0; Lac[2] *= c1; Lac[3] *= c1;

        uint32_t P[8][4];
        #pragma unroll
        for (int t = 0; t < 16; t++) {
            uint32_t x01 = ex2_f16x2(cvt_f16x2(sacc[t][1] - mn0, sacc[t][0] - mn0));
            uint32_t x23 = ex2_f16x2(cvt_f16x2(sacc[t][3] - mn1, sacc[t][2] - mn1));
            if (t & 1) { P[t >> 1][2] = x01; P[t >> 1][3] = x23; }
            else       { P[t >> 1][0] = x01; P[t >> 1][1] = x23; }
        }

        #pragma unroll
        for (int u = 0; u < 8; u++) mma_f16(Lac, P[u], ones2);

        #pragma unroll
        for (int v = 0; v < 4; v++) {
            #pragma unroll
            for (int u = 0; u < 8; u++) {
                int row = u * 16 + ((lane >> 3) & 1) * 8 + (lane & 7);
                uint32_t off = SW128B((uint32_t)(row * 128 + (2 * v + (lane >> 4)) * 16));
                uint32_t vh[4];
                ldsm_x4_t(vh, bV0 + off);
                mma_f16(O[2 * v],     P[u], vh);
                mma_f16(O[2 * v + 1], P[u], vh + 2);
            }
        }
        __syncthreads();
    }

    float inv0 = 1.0f / Lac[0];
    float inv1 = 1.0f / Lac[2];
    size_t r0 = qrow0 + w * 16 + (lane >> 2);
    size_t r1 = r0 + 8;
    #pragma unroll
    for (int t = 0; t < 8; t++) {
        size_t col = colb + t * 8 + (lane & 3) * 2;
        *(uint32_t*)(Ao + r0 * D_MODEL + col) = pk_h(O[t][0] * inv0, O[t][1] * inv0);
        *(uint32_t*)(Ao + r1 * D_MODEL + col) = pk_h(O[t][2] * inv1, O[t][3] * inv1);
    }
}

// ---------------------------------------------------------------------------
extern "C" void kernel_launch(void* const* d_in, const int* in_sizes, int n_in,
                              void* d_out, int out_size)
{
    const float* query = (const float*)d_in[0];
    const float* key   = (const float*)d_in[1];
    const float* value = (const float*)d_in[2];
    const float* Wq    = (const float*)d_in[3];
    const float* bq    = (const float*)d_in[4];
    const float* Wk    = (const float*)d_in[5];
    const float* bk    = (const float*)d_in[6];
    const float* Wv    = (const float*)d_in[7];
    const float* bv    = (const float*)d_in[8];
    const float* Wo    = (const float*)d_in[9];
    const float* bo    = (const float*)d_in[10];
    float* out = (float*)d_out;

    uint16_t *Qh, *Ql, *Kh, *Kl, *Vh, *Ao, *Xq, *Xk, *Xv;
    uint16_t *Wq16, *Wk16, *Wv16, *Wo16;
    cudaGetSymbolAddress((void**)&Qh, g_Qh);
    cudaGetSymbolAddress((void**)&Ql, g_Ql);
    cudaGetSymbolAddress((void**)&Kh, g_Kh);
    cudaGetSymbolAddress((void**)&Kl, g_Kl);
    cudaGetSymbolAddress((void**)&Vh, g_Vh);
    cudaGetSymbolAddress((void**)&Ao, g_Ao);
    cudaGetSymbolAddress((void**)&Xq, g_Xq);
    cudaGetSymbolAddress((void**)&Xk, g_Xk);
    cudaGetSymbolAddress((void**)&Xv, g_Xv);
    cudaGetSymbolAddress((void**)&Wq16, g_Wq16);
    cudaGetSymbolAddress((void**)&Wk16, g_Wk16);
    cudaGetSymbolAddress((void**)&Wv16, g_Wv16);
    cudaGetSymbolAddress((void**)&Wo16, g_Wo16);

    cudaFuncSetAttribute(gemm_qkv,
                         cudaFuncAttributeMaxDynamicSharedMemorySize, 3 * GB);
    cudaFuncSetAttribute(gemm_o,
                         cudaFuncAttributeMaxDynamicSharedMemorySize, 3 * GB);
    cudaFuncSetAttribute(attn_mma,
                         cudaFuncAttributeMaxDynamicSharedMemorySize, 6 * TILE_B);

    const int n_cvt = 3 * NX4 + 4 * NW4;   // 4,194,304 threads
    cvt_all<<<n_cvt / 256, 256>>>(
        (const float4*)query, (const float4*)key, (const float4*)value,
        (const float4*)Wq, (const float4*)Wk, (const float4*)Wv, (const float4*)Wo,
        (uint2*)Xq, (uint2*)Xk, (uint2*)Xv,
        (uint2*)Wq16, (uint2*)Wk16, (uint2*)Wv16, (uint2*)Wo16);

    gemm_qkv<<<dim3(D_MODEL / 128, M_TOT / 128, 3), 256, 3 * GB>>>(
        Xq, Xk, Xv, Wq16, Wk16, Wv16, bq, bk, bv, Qh, Ql, Kh, Kl, Vh);

    attn_mma<<<dim3(SEQ / 64, B_SZ * N_HEADS), 128, 6 * TILE_B>>>(
        Qh, Ql, Kh, Kl, Vh, Ao);

    gemm_o<<<dim3(D_MODEL / 128, M_TOT / 128), 256, 3 * GB>>>(Ao, Wo16, bo, out);
}

// round 10
// speedup vs baseline: 9.2147x; 1.0614x over previous
#include <cuda_runtime.h>
#include <cuda_bf16.h>
#include <cuda_fp16.h>
#include <stdint.h>
#include <math.h>

#define D_MODEL 1024
#define N_HEADS 16
#define HEAD_DIM 64
#define B_SZ 2
#define SEQ 2048
#define M_TOT (B_SZ * SEQ)   // 4096

// Q pre-scale: 1/sqrt(64) * log2(e)  (softmax done in base-2)
#define QSCALE 0.1803368801111204f

// Scratch (allocation-free rule: device globals)
__device__ uint16_t g_Qh[(size_t)M_TOT * D_MODEL];   // bf16
__device__ uint16_t g_Ql[(size_t)M_TOT * D_MODEL];   // bf16
__device__ uint16_t g_Kh[(size_t)M_TOT * D_MODEL];   // bf16
__device__ uint16_t g_Kl[(size_t)M_TOT * D_MODEL];   // bf16
__device__ uint16_t g_Vh[(size_t)M_TOT * D_MODEL];   // f16 (hi only)
__device__ uint16_t g_Ao[(size_t)M_TOT * D_MODEL];   // f16 (attn out, hi only)
__device__ uint16_t g_Xq[(size_t)M_TOT * D_MODEL];   // f16
__device__ uint16_t g_Xk[(size_t)M_TOT * D_MODEL];   // f16
__device__ uint16_t g_Xv[(size_t)M_TOT * D_MODEL];   // f16
__device__ uint16_t g_Wq16[(size_t)D_MODEL * D_MODEL];  // f16
__device__ uint16_t g_Wk16[(size_t)D_MODEL * D_MODEL];  // f16
__device__ uint16_t g_Wv16[(size_t)D_MODEL * D_MODEL];  // f16
__device__ uint16_t g_Wo16[(size_t)D_MODEL * D_MODEL];  // f16

// ===========================================================================
// helpers
// ===========================================================================
__device__ __forceinline__ uint32_t smem_u32(const void* p) {
    uint32_t a;
    asm("{ .reg .u64 t; cvta.to.shared.u64 t, %1; cvt.u32.u64 %0, t; }"
        : "=r"(a) : "l"(p));
    return a;
}

#define SW256(o)  ((o) ^ (((o) >> 4) & 0x70))
#define SW128B(o) ((o) ^ (((o) >> 3) & 0x70))

#define CP16(s, g) \
    asm volatile("cp.async.cg.shared.global [%0], [%1], 16;" :: "r"(s), "l"(g))
#define CP_COMMIT() asm volatile("cp.async.commit_group;" ::: "memory")
#define CP_WAIT(n)  asm volatile("cp.async.wait_group %0;" :: "n"(n) : "memory")

__device__ __forceinline__ void ldsm_x4(uint32_t* r, uint32_t a) {
    asm volatile("ldmatrix.sync.aligned.m8n8.x4.shared.b16 {%0,%1,%2,%3}, [%4];"
                 : "=r"(r[0]), "=r"(r[1]), "=r"(r[2]), "=r"(r[3]) : "r"(a));
}
__device__ __forceinline__ void ldsm_x4_t(uint32_t* r, uint32_t a) {
    asm volatile("ldmatrix.sync.aligned.m8n8.x4.trans.shared.b16 {%0,%1,%2,%3}, [%4];"
                 : "=r"(r[0]), "=r"(r[1]), "=r"(r[2]), "=r"(r[3]) : "r"(a));
}
__device__ __forceinline__ void mma_bf16(float* c, const uint32_t* a, const uint32_t* b) {
    asm volatile("mma.sync.aligned.m16n8k16.row.col.f32.bf16.bf16.f32 "
                 "{%0,%1,%2,%3}, {%4,%5,%6,%7}, {%8,%9}, {%0,%1,%2,%3};"
                 : "+f"(c[0]), "+f"(c[1]), "+f"(c[2]), "+f"(c[3])
                 : "r"(a[0]), "r"(a[1]), "r"(a[2]), "r"(a[3]),
                   "r"(b[0]), "r"(b[1]));
}
__device__ __forceinline__ void mma_f16(float* c, const uint32_t* a, const uint32_t* b) {
    asm volatile("mma.sync.aligned.m16n8k16.row.col.f32.f16.f16.f32 "
                 "{%0,%1,%2,%3}, {%4,%5,%6,%7}, {%8,%9}, {%0,%1,%2,%3};"
                 : "+f"(c[0]), "+f"(c[1]), "+f"(c[2]), "+f"(c[3])
                 : "r"(a[0]), "r"(a[1]), "r"(a[2]), "r"(a[3]),
                   "r"(b[0]), "r"(b[1]));
}
__device__ __forceinline__ uint32_t cvt_f16x2(float hi, float lo) {
    uint32_t d;
    asm("cvt.rn.f16x2.f32 %0, %1, %2;" : "=r"(d) : "f"(hi), "f"(lo));
    return d;
}
__device__ __forceinline__ uint32_t ex2_f16x2(uint32_t x) {
    uint32_t d;
    asm("ex2.approx.f16x2 %0, %1;" : "=r"(d) : "r"(x));
    return d;
}
__device__ __forceinline__ uint32_t pk_bf(float a, float b) {
    __nv_bfloat162 t = __floats2bfloat162_rn(a, b);
    return *(uint32_t*)&t;
}
__device__ __forceinline__ uint32_t pk_h(float a, float b) {
    __half2 t = __floats2half2_rn(a, b);
    return *(uint32_t*)&t;
}

// ===========================================================================
// Batched conversion: 7 fp32 tensors -> f16 hi, 1 launch
// ===========================================================================
#define NX4 (M_TOT * D_MODEL / 4)   // 1M float4 per activation tensor
#define NW4 (D_MODEL * D_MODEL / 4) // 256K float4 per weight

__global__ __launch_bounds__(256)
void cvt_all(const float4* __restrict__ q, const float4* __restrict__ k,
             const float4* __restrict__ v,
             const float4* __restrict__ w0, const float4* __restrict__ w1,
             const float4* __restrict__ w2, const float4* __restrict__ w3,
             uint2* __restrict__ oq, uint2* __restrict__ ok, uint2* __restrict__ ov,
             uint2* __restrict__ ow0, uint2* __restrict__ ow1,
             uint2* __restrict__ ow2, uint2* __restrict__ ow3)
{
    int g = blockIdx.x * 256 + threadIdx.x;
    const float4* src;
    uint2* dst;
    int i;
    if (g < 3 * NX4) {
        int sel = g / NX4;
        i = g - sel * NX4;
        src = (sel == 0) ? q : (sel == 1) ? k : v;
        dst = (sel == 0) ? oq : (sel == 1) ? ok : ov;
    } else {
        int g2 = g - 3 * NX4;
        int sel = g2 / NW4;
        i = g2 - sel * NW4;
        src = (sel == 0) ? w0 : (sel == 1) ? w1 : (sel == 2) ? w2 : w3;
        dst = (sel == 0) ? ow0 : (sel == 1) ? ow1 : (sel == 2) ? ow2 : ow3;
    }
    float4 x = src[i];
    __half2 a = __floats2half2_rn(x.x, x.y);
    __half2 b = __floats2half2_rn(x.z, x.w);
    dst[i] = make_uint2(*(uint32_t*)&a, *(uint32_t*)&b);
}

// ===========================================================================
// GEMM core: single-term f16 (Xh*Wh), 3-stage cp.async pipeline, kc=64,
// ONE barrier per iteration (prefetch issued after the barrier, into the
// buffer the barrier just proved drained). Stage 32KB: A@0 (128x64 f16,
// 128B rows, SW128B), B@16K (64x128 f16, 256B rows, SW256).
// ===========================================================================
#define GB 32768

__device__ __forceinline__ void gemm_load(
    const uint16_t* Xh, const uint16_t* Wh,
    int m0, int n0, int kc, uint32_t sb, int tid)
{
    #pragma unroll
    for (int i = 0; i < 4; i++) {
        int slot = i * 256 + tid;
        int r = slot >> 3, c = slot & 7;
        size_t g = (size_t)(m0 + r) * D_MODEL + kc * 64 + c * 8;
        CP16(sb + SW128B((uint32_t)(r * 128 + c * 16)), Xh + g);
    }
    #pragma unroll
    for (int i = 0; i < 4; i++) {
        int slot = i * 256 + tid;
        int kr = slot >> 4, c = slot & 15;
        size_t g = (size_t)(kc * 64 + kr) * D_MODEL + n0 + c * 8;
        CP16(sb + 16384 + SW256((uint32_t)(kr * 256 + c * 16)), Wh + g);
    }
}

__device__ __forceinline__ void gemm_core(
    const uint16_t* Xh, const uint16_t* Wh,
    uint32_t sb0, int m0, int n0, int tid, float acc[2][8][4])
{
    const int lane = tid & 31;
    const int wid  = tid >> 5;
    const int m_w  = (wid & 3) * 32;
    const int n_w  = (wid >> 2) * 64;
    const int a_row = lane & 15;
    const int a_ch  = lane >> 4;
    const int b_kr  = (lane & 7) + ((lane >> 3) & 1) * 8;
    const int b_nc  = lane >> 4;

    gemm_load(Xh, Wh, m0, n0, 0, sb0, tid);
    CP_COMMIT();
    gemm_load(Xh, Wh, m0, n0, 1, sb0 + GB, tid);
    CP_COMMIT();

    for (int kc = 0; kc < 16; kc++) {
        if (kc < 15) { CP_WAIT(1); } else { CP_WAIT(0); }
        __syncthreads();
        if (kc + 2 < 16) {
            // target buffer (kc+2)%3 == (kc-1)%3, drained per the barrier above
            gemm_load(Xh, Wh, m0, n0, kc + 2, sb0 + ((kc + 2) % 3) * GB, tid);
            CP_COMMIT();
        }

        const uint32_t bA = sb0 + (kc % 3) * GB;
        const uint32_t bB = bA + 16384;

        #pragma unroll
        for (int ks = 0; ks < 4; ks++) {
            uint32_t ah[2][4];
            #pragma unroll
            for (int mi = 0; mi < 2; mi++) {
                uint32_t o = (uint32_t)((m_w + mi * 16 + a_row) * 128
                                        + ks * 32 + a_ch * 16);
                ldsm_x4(ah[mi], bA + SW128B(o));
            }
            #pragma unroll
            for (int njp = 0; njp < 4; njp++) {
                uint32_t o = (uint32_t)((ks * 16 + b_kr) * 256
                                        + (n_w + njp * 16) * 2 + b_nc * 16);
                uint32_t bh[4];
                ldsm_x4_t(bh, bB + SW256(o));
                #pragma unroll
                for (int mi = 0; mi < 2; mi++) {
                    mma_f16(acc[mi][njp * 2],     ah[mi], bh);
                    mma_f16(acc[mi][njp * 2 + 1], ah[mi], bh + 2);
                }
            }
        }
    }
}

// ---- batched QKV projection: grid.z selects tensor ----
__global__ __launch_bounds__(256, 2)
void gemm_qkv(const uint16_t* __restrict__ Xq, const uint16_t* __restrict__ Xk,
              const uint16_t* __restrict__ Xv,
              const uint16_t* __restrict__ Wq16, const uint16_t* __restrict__ Wk16,
              const uint16_t* __restrict__ Wv16,
              const float* __restrict__ bq, const float* __restrict__ bk,
              const float* __restrict__ bv,
              uint16_t* __restrict__ Qh, uint16_t* __restrict__ Ql,
              uint16_t* __restrict__ Kh, uint16_t* __restrict__ Kl,
              uint16_t* __restrict__ Vh)
{
    extern __shared__ __align__(16) uint8_t dsm[];
    const uint32_t sb0 = smem_u32(dsm);
    const int tid = threadIdx.x;
    const int lane = tid & 31;
    const int wid = tid >> 5;
    const int m0 = blockIdx.y * 128;
    const int n0 = blockIdx.x * 128;
    const int z = blockIdx.z;

    const uint16_t* Xh = (z == 0) ? Xq : (z == 1) ? Xk : Xv;
    const uint16_t* Wh = (z == 0) ? Wq16 : (z == 1) ? Wk16 : Wv16;
    const float* bias = (z == 0) ? bq : (z == 1) ? bk : bv;
    const float scale = (z == 0) ? QSCALE : 1.0f;

    float acc[2][8][4];
    #pragma unroll
    for (int mi = 0; mi < 2; mi++)
        #pragma unroll
        for (int nj = 0; nj < 8; nj++)
            #pragma unroll
            for (int e = 0; e < 4; e++) acc[mi][nj][e] = 0.f;

    gemm_core(Xh, Wh, sb0, m0, n0, tid, acc);

    const int m_w = (wid & 3) * 32;
    const int n_w = (wid >> 2) * 64;
    #pragma unroll
    for (int mi = 0; mi < 2; mi++) {
        #pragma unroll
        for (int nj = 0; nj < 8; nj++) {
            int col = n0 + n_w + nj * 8 + (lane & 3) * 2;
            int r0  = m0 + m_w + mi * 16 + (lane >> 2);
            float b0 = bias[col], b1 = bias[col + 1];
            float vx0 = (acc[mi][nj][0] + b0) * scale;
            float vy0 = (acc[mi][nj][1] + b1) * scale;
            float vx1 = (acc[mi][nj][2] + b0) * scale;
            float vy1 = (acc[mi][nj][3] + b1) * scale;
            if (z < 2) {
                uint16_t* Ch = (z == 0) ? Qh : Kh;
                uint16_t* Cl = (z == 0) ? Ql : Kl;
                float hx0 = __bfloat162float(__float2bfloat16_rn(vx0));
                float hy0 = __bfloat162float(__float2bfloat16_rn(vy0));
                float hx1 = __bfloat162float(__float2bfloat16_rn(vx1));
                float hy1 = __bfloat162float(__float2bfloat16_rn(vy1));
                *(uint32_t*)(Ch + (size_t)r0 * D_MODEL + col) = pk_bf(hx0, hy0);
                *(uint32_t*)(Cl + (size_t)r0 * D_MODEL + col) = pk_bf(vx0 - hx0, vy0 - hy0);
                *(uint32_t*)(Ch + (size_t)(r0 + 8) * D_MODEL + col) = pk_bf(hx1, hy1);
                *(uint32_t*)(Cl + (size_t)(r0 + 8) * D_MODEL + col) = pk_bf(vx1 - hx1, vy1 - hy1);
            } else {
                *(uint32_t*)(Vh + (size_t)r0 * D_MODEL + col) = pk_h(vx0, vy0);
                *(uint32_t*)(Vh + (size_t)(r0 + 8) * D_MODEL + col) = pk_h(vx1, vy1);
            }
        }
    }
}

// ---- O projection: fp32 out ----
__global__ __launch_bounds__(256, 2)
void gemm_o(const uint16_t* __restrict__ Xh, const uint16_t* __restrict__ Wh,
            const float* __restrict__ bias, float* __restrict__ C)
{
    extern __shared__ __align__(16) uint8_t dsm[];
    const uint32_t sb0 = smem_u32(dsm);
    const int tid = threadIdx.x;
    const int lane = tid & 31;
    const int wid = tid >> 5;
    const int m0 = blockIdx.y * 128;
    const int n0 = blockIdx.x * 128;

    float acc[2][8][4];
    #pragma unroll
    for (int mi = 0; mi < 2; mi++)
        #pragma unroll
        for (int nj = 0; nj < 8; nj++)
            #pragma unroll
            for (int e = 0; e < 4; e++) acc[mi][nj][e] = 0.f;

    gemm_core(Xh, Wh, sb0, m0, n0, tid, acc);

    const int m_w = (wid & 3) * 32;
    const int n_w = (wid >> 2) * 64;
    #pragma unroll
    for (int mi = 0; mi < 2; mi++) {
        #pragma unroll
        for (int nj = 0; nj < 8; nj++) {
            int col = n0 + n_w + nj * 8 + (lane & 3) * 2;
            int r0  = m0 + m_w + mi * 16 + (lane >> 2);
            float b0 = bias[col], b1 = bias[col + 1];
            *(float2*)(C + (size_t)r0 * D_MODEL + col) =
                make_float2(acc[mi][nj][0] + b0, acc[mi][nj][1] + b1);
            *(float2*)(C + (size_t)(r0 + 8) * D_MODEL + col) =
                make_float2(acc[mi][nj][2] + b0, acc[mi][nj][3] + b1);
        }
    }
}

// ===========================================================================
// Tensor-core flash attention: 128-thread CTAs (q-tile 64), 2 CTAs/SM.
// K bf16 hi/lo (3-term S), V f16 hi-only. 2 x {Kh,Kl,Vh} = 96KB smem.
// Single barrier per kt (prefetch after barrier).
// ===========================================================================
#define TILE_B 16384

__device__ __forceinline__ void attn_load_kv(
    const uint16_t* Kh, const uint16_t* Kl, const uint16_t* Vh,
    size_t rowbase, size_t colb, uint32_t bb, int tid)
{
    #pragma unroll
    for (int i = 0; i < 8; i++) {
        int lin = i * 128 + tid;
        int r = lin >> 3, c = lin & 7;
        size_t ga = (rowbase + r) * D_MODEL + colb + c * 8;
        uint32_t so = SW128B((uint32_t)(r * 128 + c * 16));
        CP16(bb + so, Kh + ga);
        CP16(bb + TILE_B + so, Kl + ga);
        CP16(bb + 2 * TILE_B + so, Vh + ga);
    }
}

__global__ __launch_bounds__(128, 2)
void attn_mma(const uint16_t* __restrict__ Qh, const uint16_t* __restrict__ Ql,
              const uint16_t* __restrict__ Kh, const uint16_t* __restrict__ Kl,
              const uint16_t* __restrict__ Vh, uint16_t* __restrict__ Ao)
{
    extern __shared__ __align__(16) uint8_t smx[];
    const uint32_t sb0 = smem_u32(smx);

    const int qt = blockIdx.x;
    const int bh = blockIdx.y;
    const int b = bh >> 4, h = bh & 15;
    const int tid = threadIdx.x;
    const int lane = tid & 31;
    const int w = tid >> 5;          // 0..3

    const size_t colb = (size_t)h * HEAD_DIM;
    const size_t qrow0 = (size_t)b * SEQ + qt * 64;
    const size_t krow0 = (size_t)b * SEQ;

    attn_load_kv(Kh, Kl, Vh, krow0, colb, sb0, tid);
    CP_COMMIT();

    // stage Q (hi/lo, 64 rows) in buffer-1 tiles 3,4 (overwritten later)
    {
        uint8_t* q0 = smx + 3 * TILE_B;
        uint8_t* q1 = smx + 4 * TILE_B;
        #pragma unroll
        for (int i = 0; i < 4; i++) {
            int lin = i * 128 + tid;
            int r = lin >> 3, c16 = lin & 7;
            uint32_t so = SW128B((uint32_t)(r * 128 + c16 * 16));
            *(uint4*)(q0 + so) = *(const uint4*)(Qh + (qrow0 + r) * D_MODEL + colb + c16 * 8);
            *(uint4*)(q1 + so) = *(const uint4*)(Ql + (qrow0 + r) * D_MODEL + colb + c16 * 8);
        }
    }
    __syncthreads();

    uint32_t qfh[4][4], qfl[4][4];
    {
        const uint32_t bq0 = sb0 + 3 * TILE_B, bq1 = sb0 + 4 * TILE_B;
        int row = w * 16 + (lane & 15);
        #pragma unroll
        for (int u = 0; u < 4; u++) {
            uint32_t off = SW128B((uint32_t)(row * 128 + u * 32 + (lane >> 4) * 16));
            ldsm_x4(qfh[u], bq0 + off);
            ldsm_x4(qfl[u], bq1 + off);
        }
    }

    float O[8][4];
    float Lac[4];
    #pragma unroll
    for (int t = 0; t < 8; t++)
        #pragma unroll
        for (int e = 0; e < 4; e++) O[t][e] = 0.f;
    Lac[0] = Lac[1] = Lac[2] = Lac[3] = 0.f;
    float m0 = -1e30f, m1 = -1e30f;

    const uint32_t ones2[2] = {0x3C003C00u, 0x3C003C00u};

    for (int kt = 0; kt < SEQ / 128; kt++) {
        CP_WAIT(0);
        __syncthreads();   // tile kt resident; all threads done with kt-1
        if (kt + 1 < SEQ / 128) {
            attn_load_kv(Kh, Kl, Vh, krow0 + (kt + 1) * 128, colb,
                         sb0 + ((kt + 1) & 1) * 3 * TILE_B, tid);
            CP_COMMIT();
        }

        const uint32_t bK0 = sb0 + (kt & 1) * 3 * TILE_B;
        const uint32_t bK1 = bK0 + TILE_B;
        const uint32_t bV0 = bK0 + 2 * TILE_B;

        float sacc[16][4];
        #pragma unroll
        for (int t = 0; t < 16; t++)
            #pragma unroll
            for (int e = 0; e < 4; e++) sacc[t][e] = 0.f;

        #pragma unroll
        for (int u = 0; u < 4; u++) {
            #pragma unroll
            for (int tp = 0; tp < 8; tp++) {
                int row = tp * 16 + ((lane >> 4) << 3) + (lane & 7);
                uint32_t off = SW128B((uint32_t)(row * 128 + u * 32 + ((lane >> 3) & 1) * 16));
                uint32_t kh[4], kl[4];
                ldsm_x4(kh, bK0 + off);
                ldsm_x4(kl, bK1 + off);
                mma_bf16(sacc[2 * tp],     qfh[u], kh);
                mma_bf16(sacc[2 * tp + 1], qfh[u], kh + 2);
                mma_bf16(sacc[2 * tp],     qfh[u], kl);
                mma_bf16(sacc[2 * tp + 1], qfh[u], kl + 2);
                mma_bf16(sacc[2 * tp],     qfl[u], kh);
                mma_bf16(sacc[2 * tp + 1], qfl[u], kh + 2);
            }
        }

        float mx0 = sacc[0][0], mx1 = sacc[0][2];
        #pragma unroll
        for (int t = 0; t < 16; t++) {
            mx0 = fmaxf(mx0, fmaxf(sacc[t][0], sacc[t][1]));
            mx1 = fmaxf(mx1, fmaxf(sacc[t][2], sacc[t][3]));
        }
        mx0 = fmaxf(mx0, __shfl_xor_sync(0xffffffffu, mx0, 1));
        mx0 = fmaxf(mx0, __shfl_xor_sync(0xffffffffu, mx0, 2));
        mx1 = fmaxf(mx1, __shfl_xor_sync(0xffffffffu, mx1, 1));
        mx1 = fmaxf(mx1, __shfl_xor_sync(0xffffffffu, mx1, 2));

        float mn0 = fmaxf(m0, mx0), mn1 = fmaxf(m1, mx1);
        float c0 = exp2f(m0 - mn0), c1 = exp2f(m1 - mn1);
        m0 = mn0; m1 = mn1;

        #pragma unroll
        for (int t = 0; t < 8; t++) {
            O[t][0] *= c0; O[t][1] *= c0;
            O[t][2] *= c1; O[t][3] *= c1;
        }
        Lac[0] *= c0; Lac[1] *= c0; Lac[2] *= c1; Lac[3] *= c1;

        uint32_t P[8][4];
        #pragma unroll
        for (int t = 0; t < 16; t++) {
            uint32_t x01 = ex2_f16x2(cvt_f16x2(sacc[t][1] - mn0, sacc[t][0] - mn0));
            uint32_t x23 = ex2_f16x2(cvt_f16x2(sacc[t][3] - mn1, sacc[t][2] - mn1));
            if (t & 1) { P[t >> 1][2] = x01; P[t >> 1][3] = x23; }
            else       { P[t >> 1][0] = x01; P[t >> 1][1] = x23; }
        }

        #pragma unroll
        for (int u = 0; u < 8; u++) mma_f16(Lac, P[u], ones2);

        // PV: batch all 8 V ldsm per d-block before the 16 mmas
        #pragma unroll
        for (int v = 0; v < 4; v++) {
            uint32_t vh[8][4];
            #pragma unroll
            for (int u = 0; u < 8; u++) {
                int row = u * 16 + ((lane >> 3) & 1) * 8 + (lane & 7);
                uint32_t off = SW128B((uint32_t)(row * 128 + (2 * v + (lane >> 4)) * 16));
                ldsm_x4_t(vh[u], bV0 + off);
            }
            #pragma unroll
            for (int u = 0; u < 8; u++) {
                mma_f16(O[2 * v],     P[u], vh[u]);
                mma_f16(O[2 * v + 1], P[u], vh[u] + 2);
            }
        }
    }

    float inv0 = 1.0f / Lac[0];
    float inv1 = 1.0f / Lac[2];
    size_t r0 = qrow0 + w * 16 + (lane >> 2);
    size_t r1 = r0 + 8;
    #pragma unroll
    for (int t = 0; t < 8; t++) {
        size_t col = colb + t * 8 + (lane & 3) * 2;
        *(uint32_t*)(Ao + r0 * D_MODEL + col) = pk_h(O[t][0] * inv0, O[t][1] * inv0);
        *(uint32_t*)(Ao + r1 * D_MODEL + col) = pk_h(O[t][2] * inv1, O[t][3] * inv1);
    }
}

// ---------------------------------------------------------------------------
extern "C" void kernel_launch(void* const* d_in, const int* in_sizes, int n_in,
                              void* d_out, int out_size)
{
    const float* query = (const float*)d_in[0];
    const float* key   = (const float*)d_in[1];
    const float* value = (const float*)d_in[2];
    const float* Wq    = (const float*)d_in[3];
    const float* bq    = (const float*)d_in[4];
    const float* Wk    = (const float*)d_in[5];
    const float* bk    = (const float*)d_in[6];
    const float* Wv    = (const float*)d_in[7];
    const float* bv    = (const float*)d_in[8];
    const float* Wo    = (const float*)d_in[9];
    const float* bo    = (const float*)d_in[10];
    float* out = (float*)d_out;

    uint16_t *Qh, *Ql, *Kh, *Kl, *Vh, *Ao, *Xq, *Xk, *Xv;
    uint16_t *Wq16, *Wk16, *Wv16, *Wo16;
    cudaGetSymbolAddress((void**)&Qh, g_Qh);
    cudaGetSymbolAddress((void**)&Ql, g_Ql);
    cudaGetSymbolAddress((void**)&Kh, g_Kh);
    cudaGetSymbolAddress((void**)&Kl, g_Kl);
    cudaGetSymbolAddress((void**)&Vh, g_Vh);
    cudaGetSymbolAddress((void**)&Ao, g_Ao);
    cudaGetSymbolAddress((void**)&Xq, g_Xq);
    cudaGetSymbolAddress((void**)&Xk, g_Xk);
    cudaGetSymbolAddress((void**)&Xv, g_Xv);
    cudaGetSymbolAddress((void**)&Wq16, g_Wq16);
    cudaGetSymbolAddress((void**)&Wk16, g_Wk16);
    cudaGetSymbolAddress((void**)&Wv16, g_Wv16);
    cudaGetSymbolAddress((void**)&Wo16, g_Wo16);

    cudaFuncSetAttribute(gemm_qkv,
                         cudaFuncAttributeMaxDynamicSharedMemorySize, 3 * GB);
    cudaFuncSetAttribute(gemm_o,
                         cudaFuncAttributeMaxDynamicSharedMemorySize, 3 * GB);
    cudaFuncSetAttribute(attn_mma,
                         cudaFuncAttributeMaxDynamicSharedMemorySize, 6 * TILE_B);

    const int n_cvt = 3 * NX4 + 4 * NW4;   // 4,194,304 threads
    cvt_all<<<n_cvt / 256, 256>>>(
        (const float4*)query, (const float4*)key, (const float4*)value,
        (const float4*)Wq, (const float4*)Wk, (const float4*)Wv, (const float4*)Wo,
        (uint2*)Xq, (uint2*)Xk, (uint2*)Xv,
        (uint2*)Wq16, (uint2*)Wk16, (uint2*)Wv16, (uint2*)Wo16);

    gemm_qkv<<<dim3(D_MODEL / 128, M_TOT / 128, 3), 256, 3 * GB>>>(
        Xq, Xk, Xv, Wq16, Wk16, Wv16, bq, bk, bv, Qh, Ql, Kh, Kl, Vh);

    attn_mma<<<dim3(SEQ / 64, B_SZ * N_HEADS), 128, 6 * TILE_B>>>(
        Qh, Ql, Kh, Kl, Vh, Ao);

    gemm_o<<<dim3(D_MODEL / 128, M_TOT / 128), 256, 3 * GB>>>(Ao, Wo16, bo, out);
}

// round 11
// speedup vs baseline: 9.4807x; 1.0289x over previous
#include <cuda_runtime.h>
#include <cuda_bf16.h>
#include <cuda_fp16.h>
#include <stdint.h>
#include <math.h>

#define D_MODEL 1024
#define N_HEADS 16
#define HEAD_DIM 64
#define B_SZ 2
#define SEQ 2048
#define M_TOT (B_SZ * SEQ)   // 4096

// Q pre-scale: 1/sqrt(64) * log2(e)  (softmax done in base-2)
#define QSCALE 0.1803368801111204f

// Scratch (allocation-free rule: device globals)
__device__ uint16_t g_Qh[(size_t)M_TOT * D_MODEL];   // bf16
__device__ uint16_t g_Ql[(size_t)M_TOT * D_MODEL];   // bf16
__device__ uint16_t g_Kh[(size_t)M_TOT * D_MODEL];   // bf16
__device__ uint16_t g_Kl[(size_t)M_TOT * D_MODEL];   // bf16
__device__ uint16_t g_Vh[(size_t)M_TOT * D_MODEL];   // f16 (hi only)
__device__ uint16_t g_Ao[(size_t)M_TOT * D_MODEL];   // f16 (attn out, hi only)
__device__ uint16_t g_Xq[(size_t)M_TOT * D_MODEL];   // f16
__device__ uint16_t g_Xk[(size_t)M_TOT * D_MODEL];   // f16
__device__ uint16_t g_Xv[(size_t)M_TOT * D_MODEL];   // f16
__device__ uint16_t g_Wq16[(size_t)D_MODEL * D_MODEL];  // f16
__device__ uint16_t g_Wk16[(size_t)D_MODEL * D_MODEL];  // f16
__device__ uint16_t g_Wv16[(size_t)D_MODEL * D_MODEL];  // f16
__device__ uint16_t g_Wo16[(size_t)D_MODEL * D_MODEL];  // f16

// ===========================================================================
// helpers
// ===========================================================================
__device__ __forceinline__ uint32_t smem_u32(const void* p) {
    uint32_t a;
    asm("{ .reg .u64 t; cvta.to.shared.u64 t, %1; cvt.u32.u64 %0, t; }"
        : "=r"(a) : "l"(p));
    return a;
}

#define SW256(o)  ((o) ^ (((o) >> 4) & 0x70))
#define SW128B(o) ((o) ^ (((o) >> 3) & 0x70))

#define CP16(s, g) \
    asm volatile("cp.async.cg.shared.global [%0], [%1], 16;" :: "r"(s), "l"(g))
#define CP_COMMIT() asm volatile("cp.async.commit_group;" ::: "memory")
#define CP_WAIT(n)  asm volatile("cp.async.wait_group %0;" :: "n"(n) : "memory")

__device__ __forceinline__ void ldsm_x4(uint32_t* r, uint32_t a) {
    asm volatile("ldmatrix.sync.aligned.m8n8.x4.shared.b16 {%0,%1,%2,%3}, [%4];"
                 : "=r"(r[0]), "=r"(r[1]), "=r"(r[2]), "=r"(r[3]) : "r"(a));
}
__device__ __forceinline__ void ldsm_x4_t(uint32_t* r, uint32_t a) {
    asm volatile("ldmatrix.sync.aligned.m8n8.x4.trans.shared.b16 {%0,%1,%2,%3}, [%4];"
                 : "=r"(r[0]), "=r"(r[1]), "=r"(r[2]), "=r"(r[3]) : "r"(a));
}
__device__ __forceinline__ void mma_bf16(float* c, const uint32_t* a, const uint32_t* b) {
    asm volatile("mma.sync.aligned.m16n8k16.row.col.f32.bf16.bf16.f32 "
                 "{%0,%1,%2,%3}, {%4,%5,%6,%7}, {%8,%9}, {%0,%1,%2,%3};"
                 : "+f"(c[0]), "+f"(c[1]), "+f"(c[2]), "+f"(c[3])
                 : "r"(a[0]), "r"(a[1]), "r"(a[2]), "r"(a[3]),
                   "r"(b[0]), "r"(b[1]));
}
__device__ __forceinline__ void mma_f16(float* c, const uint32_t* a, const uint32_t* b) {
    asm volatile("mma.sync.aligned.m16n8k16.row.col.f32.f16.f16.f32 "
                 "{%0,%1,%2,%3}, {%4,%5,%6,%7}, {%8,%9}, {%0,%1,%2,%3};"
                 : "+f"(c[0]), "+f"(c[1]), "+f"(c[2]), "+f"(c[3])
                 : "r"(a[0]), "r"(a[1]), "r"(a[2]), "r"(a[3]),
                   "r"(b[0]), "r"(b[1]));
}
__device__ __forceinline__ uint32_t cvt_f16x2(float hi, float lo) {
    uint32_t d;
    asm("cvt.rn.f16x2.f32 %0, %1, %2;" : "=r"(d) : "f"(hi), "f"(lo));
    return d;
}
__device__ __forceinline__ uint32_t ex2_f16x2(uint32_t x) {
    uint32_t d;
    asm("ex2.approx.f16x2 %0, %1;" : "=r"(d) : "r"(x));
    return d;
}
__device__ __forceinline__ uint32_t pk_bf(float a, float b) {
    __nv_bfloat162 t = __floats2bfloat162_rn(a, b);
    return *(uint32_t*)&t;
}
__device__ __forceinline__ uint32_t pk_h(float a, float b) {
    __half2 t = __floats2half2_rn(a, b);
    return *(uint32_t*)&t;
}

// ===========================================================================
// Batched conversion: 7 fp32 tensors -> f16 hi, 1 launch
// ===========================================================================
#define NX4 (M_TOT * D_MODEL / 4)   // 1M float4 per activation tensor
#define NW4 (D_MODEL * D_MODEL / 4) // 256K float4 per weight

__global__ __launch_bounds__(256)
void cvt_all(const float4* __restrict__ q, const float4* __restrict__ k,
             const float4* __restrict__ v,
             const float4* __restrict__ w0, const float4* __restrict__ w1,
             const float4* __restrict__ w2, const float4* __restrict__ w3,
             uint2* __restrict__ oq, uint2* __restrict__ ok, uint2* __restrict__ ov,
             uint2* __restrict__ ow0, uint2* __restrict__ ow1,
             uint2* __restrict__ ow2, uint2* __restrict__ ow3)
{
    int g = blockIdx.x * 256 + threadIdx.x;
    const float4* src;
    uint2* dst;
    int i;
    if (g < 3 * NX4) {
        int sel = g / NX4;
        i = g - sel * NX4;
        src = (sel == 0) ? q : (sel == 1) ? k : v;
        dst = (sel == 0) ? oq : (sel == 1) ? ok : ov;
    } else {
        int g2 = g - 3 * NX4;
        int sel = g2 / NW4;
        i = g2 - sel * NW4;
        src = (sel == 0) ? w0 : (sel == 1) ? w1 : (sel == 2) ? w2 : w3;
        dst = (sel == 0) ? ow0 : (sel == 1) ? ow1 : (sel == 2) ? ow2 : ow3;
    }
    float4 x = src[i];
    __half2 a = __floats2half2_rn(x.x, x.y);
    __half2 b = __floats2half2_rn(x.z, x.w);
    dst[i] = make_uint2(*(uint32_t*)&a, *(uint32_t*)&b);
}

// ===========================================================================
// GEMM core: single-term f16 (Xh*Wh), 3-stage cp.async pipeline, kc=64,
// one barrier per iteration. Stage 32KB: A@0 (128x64 f16, SW128B rows),
// B@16K (64x128 f16, SW256 rows). FROZEN (reg-cap-bound at occ 2).
// ===========================================================================
#define GB 32768

__device__ __forceinline__ void gemm_load(
    const uint16_t* Xh, const uint16_t* Wh,
    int m0, int n0, int kc, uint32_t sb, int tid)
{
    #pragma unroll
    for (int i = 0; i < 4; i++) {
        int slot = i * 256 + tid;
        int r = slot >> 3, c = slot & 7;
        size_t g = (size_t)(m0 + r) * D_MODEL + kc * 64 + c * 8;
        CP16(sb + SW128B((uint32_t)(r * 128 + c * 16)), Xh + g);
    }
    #pragma unroll
    for (int i = 0; i < 4; i++) {
        int slot = i * 256 + tid;
        int kr = slot >> 4, c = slot & 15;
        size_t g = (size_t)(kc * 64 + kr) * D_MODEL + n0 + c * 8;
        CP16(sb + 16384 + SW256((uint32_t)(kr * 256 + c * 16)), Wh + g);
    }
}

__device__ __forceinline__ void gemm_core(
    const uint16_t* Xh, const uint16_t* Wh,
    uint32_t sb0, int m0, int n0, int tid, float acc[2][8][4])
{
    const int lane = tid & 31;
    const int wid  = tid >> 5;
    const int m_w  = (wid & 3) * 32;
    const int n_w  = (wid >> 2) * 64;
    const int a_row = lane & 15;
    const int a_ch  = lane >> 4;
    const int b_kr  = (lane & 7) + ((lane >> 3) & 1) * 8;
    const int b_nc  = lane >> 4;

    gemm_load(Xh, Wh, m0, n0, 0, sb0, tid);
    CP_COMMIT();
    gemm_load(Xh, Wh, m0, n0, 1, sb0 + GB, tid);
    CP_COMMIT();

    for (int kc = 0; kc < 16; kc++) {
        if (kc < 15) { CP_WAIT(1); } else { CP_WAIT(0); }
        __syncthreads();
        if (kc + 2 < 16) {
            gemm_load(Xh, Wh, m0, n0, kc + 2, sb0 + ((kc + 2) % 3) * GB, tid);
            CP_COMMIT();
        }

        const uint32_t bA = sb0 + (kc % 3) * GB;
        const uint32_t bB = bA + 16384;

        #pragma unroll
        for (int ks = 0; ks < 4; ks++) {
            uint32_t ah[2][4];
            #pragma unroll
            for (int mi = 0; mi < 2; mi++) {
                uint32_t o = (uint32_t)((m_w + mi * 16 + a_row) * 128
                                        + ks * 32 + a_ch * 16);
                ldsm_x4(ah[mi], bA + SW128B(o));
            }
            #pragma unroll
            for (int njp = 0; njp < 4; njp++) {
                uint32_t o = (uint32_t)((ks * 16 + b_kr) * 256
                                        + (n_w + njp * 16) * 2 + b_nc * 16);
                uint32_t bh[4];
                ldsm_x4_t(bh, bB + SW256(o));
                #pragma unroll
                for (int mi = 0; mi < 2; mi++) {
                    mma_f16(acc[mi][njp * 2],     ah[mi], bh);
                    mma_f16(acc[mi][njp * 2 + 1], ah[mi], bh + 2);
                }
            }
        }
    }
}

// ---- batched QKV projection: grid.z selects tensor ----
__global__ __launch_bounds__(256, 2)
void gemm_qkv(const uint16_t* __restrict__ Xq, const uint16_t* __restrict__ Xk,
              const uint16_t* __restrict__ Xv,
              const uint16_t* __restrict__ Wq16, const uint16_t* __restrict__ Wk16,
              const uint16_t* __restrict__ Wv16,
              const float* __restrict__ bq, const float* __restrict__ bk,
              const float* __restrict__ bv,
              uint16_t* __restrict__ Qh, uint16_t* __restrict__ Ql,
              uint16_t* __restrict__ Kh, uint16_t* __restrict__ Kl,
              uint16_t* __restrict__ Vh)
{
    extern __shared__ __align__(16) uint8_t dsm[];
    const uint32_t sb0 = smem_u32(dsm);
    const int tid = threadIdx.x;
    const int lane = tid & 31;
    const int wid = tid >> 5;
    const int m0 = blockIdx.y * 128;
    const int n0 = blockIdx.x * 128;
    const int z = blockIdx.z;

    const uint16_t* Xh = (z == 0) ? Xq : (z == 1) ? Xk : Xv;
    const uint16_t* Wh = (z == 0) ? Wq16 : (z == 1) ? Wk16 : Wv16;
    const float* bias = (z == 0) ? bq : (z == 1) ? bk : bv;
    const float scale = (z == 0) ? QSCALE : 1.0f;

    float acc[2][8][4];
    #pragma unroll
    for (int mi = 0; mi < 2; mi++)
        #pragma unroll
        for (int nj = 0; nj < 8; nj++)
            #pragma unroll
            for (int e = 0; e < 4; e++) acc[mi][nj][e] = 0.f;

    gemm_core(Xh, Wh, sb0, m0, n0, tid, acc);

    const int m_w = (wid & 3) * 32;
    const int n_w = (wid >> 2) * 64;
    #pragma unroll
    for (int mi = 0; mi < 2; mi++) {
        #pragma unroll
        for (int nj = 0; nj < 8; nj++) {
            int col = n0 + n_w + nj * 8 + (lane & 3) * 2;
            int r0  = m0 + m_w + mi * 16 + (lane >> 2);
            float b0 = bias[col], b1 = bias[col + 1];
            float vx0 = (acc[mi][nj][0] + b0) * scale;
            float vy0 = (acc[mi][nj][1] + b1) * scale;
            float vx1 = (acc[mi][nj][2] + b0) * scale;
            float vy1 = (acc[mi][nj][3] + b1) * scale;
            if (z < 2) {
                uint16_t* Ch = (z == 0) ? Qh : Kh;
                uint16_t* Cl = (z == 0) ? Ql : Kl;
                float hx0 = __bfloat162float(__float2bfloat16_rn(vx0));
                float hy0 = __bfloat162float(__float2bfloat16_rn(vy0));
                float hx1 = __bfloat162float(__float2bfloat16_rn(vx1));
                float hy1 = __bfloat162float(__float2bfloat16_rn(vy1));
                *(uint32_t*)(Ch + (size_t)r0 * D_MODEL + col) = pk_bf(hx0, hy0);
                *(uint32_t*)(Cl + (size_t)r0 * D_MODEL + col) = pk_bf(vx0 - hx0, vy0 - hy0);
                *(uint32_t*)(Ch + (size_t)(r0 + 8) * D_MODEL + col) = pk_bf(hx1, hy1);
                *(uint32_t*)(Cl + (size_t)(r0 + 8) * D_MODEL + col) = pk_bf(vx1 - hx1, vy1 - hy1);
            } else {
                *(uint32_t*)(Vh + (size_t)r0 * D_MODEL + col) = pk_h(vx0, vy0);
                *(uint32_t*)(Vh + (size_t)(r0 + 8) * D_MODEL + col) = pk_h(vx1, vy1);
            }
        }
    }
}

// ---- O projection: fp32 out ----
__global__ __launch_bounds__(256, 2)
void gemm_o(const uint16_t* __restrict__ Xh, const uint16_t* __restrict__ Wh,
            const float* __restrict__ bias, float* __restrict__ C)
{
    extern __shared__ __align__(16) uint8_t dsm[];
    const uint32_t sb0 = smem_u32(dsm);
    const int tid = threadIdx.x;
    const int lane = tid & 31;
    const int wid = tid >> 5;
    const int m0 = blockIdx.y * 128;
    const int n0 = blockIdx.x * 128;

    float acc[2][8][4];
    #pragma unroll
    for (int mi = 0; mi < 2; mi++)
        #pragma unroll
        for (int nj = 0; nj < 8; nj++)
            #pragma unroll
            for (int e = 0; e < 4; e++) acc[mi][nj][e] = 0.f;

    gemm_core(Xh, Wh, sb0, m0, n0, tid, acc);

    const int m_w = (wid & 3) * 32;
    const int n_w = (wid >> 2) * 64;
    #pragma unroll
    for (int mi = 0; mi < 2; mi++) {
        #pragma unroll
        for (int nj = 0; nj < 8; nj++) {
            int col = n0 + n_w + nj * 8 + (lane & 3) * 2;
            int r0  = m0 + m_w + mi * 16 + (lane >> 2);
            float b0 = bias[col], b1 = bias[col + 1];
            *(float2*)(C + (size_t)r0 * D_MODEL + col) =
                make_float2(acc[mi][nj][0] + b0, acc[mi][nj][1] + b1);
            *(float2*)(C + (size_t)(r0 + 8) * D_MODEL + col) =
                make_float2(acc[mi][nj][2] + b0, acc[mi][nj][3] + b1);
        }
    }
}

// ===========================================================================
// Tensor-core flash attention: 128-thread CTAs (q-tile 64), 2 CTAs/SM.
// K bf16 hi/lo (3-term S), V f16 hi-only. 2 x {Kh,Kl,Vh} = 96KB smem.
// R11: S-phase tp-pair unroll (acc reuse distance 4), PV u-outer/v-inner
// (acc reuse distance 8). Per-accumulator mma order preserved -> results
// are bit-identical to R10.
// ===========================================================================
#define TILE_B 16384

__device__ __forceinline__ void attn_load_kv(
    const uint16_t* Kh, const uint16_t* Kl, const uint16_t* Vh,
    size_t rowbase, size_t colb, uint32_t bb, int tid)
{
    #pragma unroll
    for (int i = 0; i < 8; i++) {
        int lin = i * 128 + tid;
        int r = lin >> 3, c = lin & 7;
        size_t ga = (rowbase + r) * D_MODEL + colb + c * 8;
        uint32_t so = SW128B((uint32_t)(r * 128 + c * 16));
        CP16(bb + so, Kh + ga);
        CP16(bb + TILE_B + so, Kl + ga);
        CP16(bb + 2 * TILE_B + so, Vh + ga);
    }
}

__global__ __launch_bounds__(128, 2)
void attn_mma(const uint16_t* __restrict__ Qh, const uint16_t* __restrict__ Ql,
              const uint16_t* __restrict__ Kh, const uint16_t* __restrict__ Kl,
              const uint16_t* __restrict__ Vh, uint16_t* __restrict__ Ao)
{
    extern __shared__ __align__(16) uint8_t smx[];
    const uint32_t sb0 = smem_u32(smx);

    const int qt = blockIdx.x;
    const int bh = blockIdx.y;
    const int b = bh >> 4, h = bh & 15;
    const int tid = threadIdx.x;
    const int lane = tid & 31;
    const int w = tid >> 5;          // 0..3

    const size_t colb = (size_t)h * HEAD_DIM;
    const size_t qrow0 = (size_t)b * SEQ + qt * 64;
    const size_t krow0 = (size_t)b * SEQ;

    attn_load_kv(Kh, Kl, Vh, krow0, colb, sb0, tid);
    CP_COMMIT();

    // stage Q (hi/lo, 64 rows) in buffer-1 tiles 3,4 (overwritten later)
    {
        uint8_t* q0 = smx + 3 * TILE_B;
        uint8_t* q1 = smx + 4 * TILE_B;
        #pragma unroll
        for (int i = 0; i < 4; i++) {
            int lin = i * 128 + tid;
            int r = lin >> 3, c16 = lin & 7;
            uint32_t so = SW128B((uint32_t)(r * 128 + c16 * 16));
            *(uint4*)(q0 + so) = *(const uint4*)(Qh + (qrow0 + r) * D_MODEL + colb + c16 * 8);
            *(uint4*)(q1 + so) = *(const uint4*)(Ql + (qrow0 + r) * D_MODEL + colb + c16 * 8);
        }
    }
    __syncthreads();

    uint32_t qfh[4][4], qfl[4][4];
    {
        const uint32_t bq0 = sb0 + 3 * TILE_B, bq1 = sb0 + 4 * TILE_B;
        int row = w * 16 + (lane & 15);
        #pragma unroll
        for (int u = 0; u < 4; u++) {
            uint32_t off = SW128B((uint32_t)(row * 128 + u * 32 + (lane >> 4) * 16));
            ldsm_x4(qfh[u], bq0 + off);
            ldsm_x4(qfl[u], bq1 + off);
        }
    }

    float O[8][4];
    float Lac[4];
    #pragma unroll
    for (int t = 0; t < 8; t++)
        #pragma unroll
        for (int e = 0; e < 4; e++) O[t][e] = 0.f;
    Lac[0] = Lac[1] = Lac[2] = Lac[3] = 0.f;
    float m0 = -1e30f, m1 = -1e30f;

    const uint32_t ones2[2] = {0x3C003C00u, 0x3C003C00u};

    for (int kt = 0; kt < SEQ / 128; kt++) {
        CP_WAIT(0);
        __syncthreads();   // tile kt resident; all threads done with kt-1
        if (kt + 1 < SEQ / 128) {
            attn_load_kv(Kh, Kl, Vh, krow0 + (kt + 1) * 128, colb,
                         sb0 + ((kt + 1) & 1) * 3 * TILE_B, tid);
            CP_COMMIT();
        }

        const uint32_t bK0 = sb0 + (kt & 1) * 3 * TILE_B;
        const uint32_t bK1 = bK0 + TILE_B;
        const uint32_t bV0 = bK0 + 2 * TILE_B;

        float sacc[16][4];
        #pragma unroll
        for (int t = 0; t < 16; t++)
            #pragma unroll
            for (int e = 0; e < 4; e++) sacc[t][e] = 0.f;

        // ---- S = Q@K^T : tp-pair unroll, round-robin over 4 accumulators.
        // Per-acc term order (qh*kh, qh*kl, ql*kh) identical to before.
        #pragma unroll
        for (int u = 0; u < 4; u++) {
            #pragma unroll
            for (int g2 = 0; g2 < 4; g2++) {
                int tpA = 2 * g2, tpB = 2 * g2 + 1;
                int rowA = tpA * 16 + ((lane >> 4) << 3) + (lane & 7);
                int rowB = tpB * 16 + ((lane >> 4) << 3) + (lane & 7);
                uint32_t offA = SW128B((uint32_t)(rowA * 128 + u * 32 + ((lane >> 3) & 1) * 16));
                uint32_t offB = SW128B((uint32_t)(rowB * 128 + u * 32 + ((lane >> 3) & 1) * 16));
                uint32_t khA[4], klA[4], khB[4], klB[4];
                ldsm_x4(khA, bK0 + offA);
                ldsm_x4(klA, bK1 + offA);
                ldsm_x4(khB, bK0 + offB);
                ldsm_x4(klB, bK1 + offB);
                float* a0 = sacc[4 * g2 + 0];
                float* a1 = sacc[4 * g2 + 1];
                float* a2 = sacc[4 * g2 + 2];
                float* a3 = sacc[4 * g2 + 3];
                mma_bf16(a0, qfh[u], khA);
                mma_bf16(a1, qfh[u], khA + 2);
                mma_bf16(a2, qfh[u], khB);
                mma_bf16(a3, qfh[u], khB + 2);
                mma_bf16(a0, qfh[u], klA);
                mma_bf16(a1, qfh[u], klA + 2);
                mma_bf16(a2, qfh[u], klB);
                mma_bf16(a3, qfh[u], klB + 2);
                mma_bf16(a0, qfl[u], khA);
                mma_bf16(a1, qfl[u], khA + 2);
                mma_bf16(a2, qfl[u], khB);
                mma_bf16(a3, qfl[u], khB + 2);
            }
        }

        float mx0 = sacc[0][0], mx1 = sacc[0][2];
        #pragma unroll
        for (int t = 0; t < 16; t++) {
            mx0 = fmaxf(mx0, fmaxf(sacc[t][0], sacc[t][1]));
            mx1 = fmaxf(mx1, fmaxf(sacc[t][2], sacc[t][3]));
        }
        mx0 = fmaxf(mx0, __shfl_xor_sync(0xffffffffu, mx0, 1));
        mx0 = fmaxf(mx0, __shfl_xor_sync(0xffffffffu, mx0, 2));
        mx1 = fmaxf(mx1, __shfl_xor_sync(0xffffffffu, mx1, 1));
        mx1 = fmaxf(mx1, __shfl_xor_sync(0xffffffffu, mx1, 2));

        float mn0 = fmaxf(m0, mx0), mn1 = fmaxf(m1, mx1);
        float c0 = exp2f(m0 - mn0), c1 = exp2f(m1 - mn1);
        m0 = mn0; m1 = mn1;

        #pragma unroll
        for (int t = 0; t < 8; t++) {
            O[t][0] *= c0; O[t][1] *= c0;
            O[t][2] *= c1; O[t][3] *= c1;
        }
        Lac[0] *= c0; Lac[1] *= c0; Lac[2] *= c1; Lac[3] *= c1;

        uint32_t P[8][4];
        #pragma unroll
        for (int t = 0; t < 16; t++) {
            uint32_t x01 = ex2_f16x2(cvt_f16x2(sacc[t][1] - mn0, sacc[t][0] - mn0));
            uint32_t x23 = ex2_f16x2(cvt_f16x2(sacc[t][3] - mn1, sacc[t][2] - mn1));
            if (t & 1) { P[t >> 1][2] = x01; P[t >> 1][3] = x23; }
            else       { P[t >> 1][0] = x01; P[t >> 1][1] = x23; }
        }

        #pragma unroll
        for (int u = 0; u < 8; u++) mma_f16(Lac, P[u], ones2);

        // ---- O += P @ V : u-outer / v-inner, 8 distinct accs per u.
        // Per-acc u-order identical to before -> bit-identical.
        #pragma unroll
        for (int u = 0; u < 8; u++) {
            int row = u * 16 + ((lane >> 3) & 1) * 8 + (lane & 7);
            uint32_t vh[4][4];
            #pragma unroll
            for (int v = 0; v < 4; v++) {
                uint32_t off = SW128B((uint32_t)(row * 128 + (2 * v + (lane >> 4)) * 16));
                ldsm_x4_t(vh[v], bV0 + off);
            }
            #pragma unroll
            for (int v = 0; v < 4; v++) {
                mma_f16(O[2 * v],     P[u], vh[v]);
                mma_f16(O[2 * v + 1], P[u], vh[v] + 2);
            }
        }
    }

    float inv0 = 1.0f / Lac[0];
    float inv1 = 1.0f / Lac[2];
    size_t r0 = qrow0 + w * 16 + (lane >> 2);
    size_t r1 = r0 + 8;
    #pragma unroll
    for (int t = 0; t < 8; t++) {
        size_t col = colb + t * 8 + (lane & 3) * 2;
        *(uint32_t*)(Ao + r0 * D_MODEL + col) = pk_h(O[t][0] * inv0, O[t][1] * inv0);
        *(uint32_t*)(Ao + r1 * D_MODEL + col) = pk_h(O[t][2] * inv1, O[t][3] * inv1);
    }
}

// ---------------------------------------------------------------------------
extern "C" void kernel_launch(void* const* d_in, const int* in_sizes, int n_in,
                              void* d_out, int out_size)
{
    const float* query = (const float*)d_in[0];
    const float* key   = (const float*)d_in[1];
    const float* value = (const float*)d_in[2];
    const float* Wq    = (const float*)d_in[3];
    const float* bq    = (const float*)d_in[4];
    const float* Wk    = (const float*)d_in[5];
    const float* bk    = (const float*)d_in[6];
    const float* Wv    = (const float*)d_in[7];
    const float* bv    = (const float*)d_in[8];
    const float* Wo    = (const float*)d_in[9];
    const float* bo    = (const float*)d_in[10];
    float* out = (float*)d_out;

    uint16_t *Qh, *Ql, *Kh, *Kl, *Vh, *Ao, *Xq, *Xk, *Xv;
    uint16_t *Wq16, *Wk16, *Wv16, *Wo16;
    cudaGetSymbolAddress((void**)&Qh, g_Qh);
    cudaGetSymbolAddress((void**)&Ql, g_Ql);
    cudaGetSymbolAddress((void**)&Kh, g_Kh);
    cudaGetSymbolAddress((void**)&Kl, g_Kl);
    cudaGetSymbolAddress((void**)&Vh, g_Vh);
    cudaGetSymbolAddress((void**)&Ao, g_Ao);
    cudaGetSymbolAddress((void**)&Xq, g_Xq);
    cudaGetSymbolAddress((void**)&Xk, g_Xk);
    cudaGetSymbolAddress((void**)&Xv, g_Xv);
    cudaGetSymbolAddress((void**)&Wq16, g_Wq16);
    cudaGetSymbolAddress((void**)&Wk16, g_Wk16);
    cudaGetSymbolAddress((void**)&Wv16, g_Wv16);
    cudaGetSymbolAddress((void**)&Wo16, g_Wo16);

    cudaFuncSetAttribute(gemm_qkv,
                         cudaFuncAttributeMaxDynamicSharedMemorySize, 3 * GB);
    cudaFuncSetAttribute(gemm_o,
                         cudaFuncAttributeMaxDynamicSharedMemorySize, 3 * GB);
    cudaFuncSetAttribute(attn_mma,
                         cudaFuncAttributeMaxDynamicSharedMemorySize, 6 * TILE_B);

    const int n_cvt = 3 * NX4 + 4 * NW4;   // 4,194,304 threads
    cvt_all<<<n_cvt / 256, 256>>>(
        (const float4*)query, (const float4*)key, (const float4*)value,
        (const float4*)Wq, (const float4*)Wk, (const float4*)Wv, (const float4*)Wo,
        (uint2*)Xq, (uint2*)Xk, (uint2*)Xv,
        (uint2*)Wq16, (uint2*)Wk16, (uint2*)Wv16, (uint2*)Wo16);

    gemm_qkv<<<dim3(D_MODEL / 128, M_TOT / 128, 3), 256, 3 * GB>>>(
        Xq, Xk, Xv, Wq16, Wk16, Wv16, bq, bk, bv, Qh, Ql, Kh, Kl, Vh);

    attn_mma<<<dim3(SEQ / 64, B_SZ * N_HEADS), 128, 6 * TILE_B>>>(
        Qh, Ql, Kh, Kl, Vh, Ao);

    gemm_o<<<dim3(D_MODEL / 128, M_TOT / 128), 256, 3 * GB>>>(Ao, Wo16, bo, out);
}

// round 12
// speedup vs baseline: 10.2090x; 1.0768x over previous
#include <cuda_runtime.h>
#include <cuda_bf16.h>
#include <cuda_fp16.h>
#include <stdint.h>
#include <math.h>

#define D_MODEL 1024
#define N_HEADS 16
#define HEAD_DIM 64
#define B_SZ 2
#define SEQ 2048
#define M_TOT (B_SZ * SEQ)   // 4096

// Q pre-scale: 1/sqrt(64) * log2(e)  (softmax done in base-2)
#define QSCALE 0.1803368801111204f

// Scratch (allocation-free rule: device globals)
__device__ uint16_t g_Qh[(size_t)M_TOT * D_MODEL];   // f16 (hi only)
__device__ uint16_t g_Kh[(size_t)M_TOT * D_MODEL];   // f16 hi
__device__ uint16_t g_Kl[(size_t)M_TOT * D_MODEL];   // f16 lo (residual)
__device__ uint16_t g_Vh[(size_t)M_TOT * D_MODEL];   // f16 (hi only)
__device__ uint16_t g_Ao[(size_t)M_TOT * D_MODEL];   // f16 (attn out, hi only)
__device__ uint16_t g_Xq[(size_t)M_TOT * D_MODEL];   // f16
__device__ uint16_t g_Xk[(size_t)M_TOT * D_MODEL];   // f16
__device__ uint16_t g_Xv[(size_t)M_TOT * D_MODEL];   // f16
__device__ uint16_t g_Wq16[(size_t)D_MODEL * D_MODEL];  // f16
__device__ uint16_t g_Wk16[(size_t)D_MODEL * D_MODEL];  // f16
__device__ uint16_t g_Wv16[(size_t)D_MODEL * D_MODEL];  // f16
__device__ uint16_t g_Wo16[(size_t)D_MODEL * D_MODEL];  // f16

// ===========================================================================
// helpers
// ===========================================================================
__device__ __forceinline__ uint32_t smem_u32(const void* p) {
    uint32_t a;
    asm("{ .reg .u64 t; cvta.to.shared.u64 t, %1; cvt.u32.u64 %0, t; }"
        : "=r"(a) : "l"(p));
    return a;
}

#define SW256(o)  ((o) ^ (((o) >> 4) & 0x70))
#define SW128B(o) ((o) ^ (((o) >> 3) & 0x70))

#define CP16(s, g) \
    asm volatile("cp.async.cg.shared.global [%0], [%1], 16;" :: "r"(s), "l"(g))
#define CP_COMMIT() asm volatile("cp.async.commit_group;" ::: "memory")
#define CP_WAIT(n)  asm volatile("cp.async.wait_group %0;" :: "n"(n) : "memory")

__device__ __forceinline__ void ldsm_x4(uint32_t* r, uint32_t a) {
    asm volatile("ldmatrix.sync.aligned.m8n8.x4.shared.b16 {%0,%1,%2,%3}, [%4];"
                 : "=r"(r[0]), "=r"(r[1]), "=r"(r[2]), "=r"(r[3]) : "r"(a));
}
__device__ __forceinline__ void ldsm_x4_t(uint32_t* r, uint32_t a) {
    asm volatile("ldmatrix.sync.aligned.m8n8.x4.trans.shared.b16 {%0,%1,%2,%3}, [%4];"
                 : "=r"(r[0]), "=r"(r[1]), "=r"(r[2]), "=r"(r[3]) : "r"(a));
}
__device__ __forceinline__ void mma_f16(float* c, const uint32_t* a, const uint32_t* b) {
    asm volatile("mma.sync.aligned.m16n8k16.row.col.f32.f16.f16.f32 "
                 "{%0,%1,%2,%3}, {%4,%5,%6,%7}, {%8,%9}, {%0,%1,%2,%3};"
                 : "+f"(c[0]), "+f"(c[1]), "+f"(c[2]), "+f"(c[3])
                 : "r"(a[0]), "r"(a[1]), "r"(a[2]), "r"(a[3]),
                   "r"(b[0]), "r"(b[1]));
}
__device__ __forceinline__ uint32_t cvt_f16x2(float hi, float lo) {
    uint32_t d;
    asm("cvt.rn.f16x2.f32 %0, %1, %2;" : "=r"(d) : "f"(hi), "f"(lo));
    return d;
}
__device__ __forceinline__ uint32_t ex2_f16x2(uint32_t x) {
    uint32_t d;
    asm("ex2.approx.f16x2 %0, %1;" : "=r"(d) : "r"(x));
    return d;
}
__device__ __forceinline__ uint32_t pk_h(float a, float b) {
    __half2 t = __floats2half2_rn(a, b);
    return *(uint32_t*)&t;
}

// ===========================================================================
// Batched conversion: 7 fp32 tensors -> f16 hi, 1 launch
// ===========================================================================
#define NX4 (M_TOT * D_MODEL / 4)   // 1M float4 per activation tensor
#define NW4 (D_MODEL * D_MODEL / 4) // 256K float4 per weight

__global__ __launch_bounds__(256)
void cvt_all(const float4* __restrict__ q, const float4* __restrict__ k,
             const float4* __restrict__ v,
             const float4* __restrict__ w0, const float4* __restrict__ w1,
             const float4* __restrict__ w2, const float4* __restrict__ w3,
             uint2* __restrict__ oq, uint2* __restrict__ ok, uint2* __restrict__ ov,
             uint2* __restrict__ ow0, uint2* __restrict__ ow1,
             uint2* __restrict__ ow2, uint2* __restrict__ ow3)
{
    int g = blockIdx.x * 256 + threadIdx.x;
    const float4* src;
    uint2* dst;
    int i;
    if (g < 3 * NX4) {
        int sel = g / NX4;
        i = g - sel * NX4;
        src = (sel == 0) ? q : (sel == 1) ? k : v;
        dst = (sel == 0) ? oq : (sel == 1) ? ok : ov;
    } else {
        int g2 = g - 3 * NX4;
        int sel = g2 / NW4;
        i = g2 - sel * NW4;
        src = (sel == 0) ? w0 : (sel == 1) ? w1 : (sel == 2) ? w2 : w3;
        dst = (sel == 0) ? ow0 : (sel == 1) ? ow1 : (sel == 2) ? ow2 : ow3;
    }
    float4 x = src[i];
    __half2 a = __floats2half2_rn(x.x, x.y);
    __half2 b = __floats2half2_rn(x.z, x.w);
    dst[i] = make_uint2(*(uint32_t*)&a, *(uint32_t*)&b);
}

// ===========================================================================
// GEMM core: single-term f16 (Xh*Wh), 3-stage cp.async pipeline, kc=64,
// one barrier per iteration. Stage 32KB: A@0 (128x64 f16, SW128B rows),
// B@16K (64x128 f16, SW256 rows). FROZEN (reg-cap-bound at occ 2).
// ===========================================================================
#define GB 32768

__device__ __forceinline__ void gemm_load(
    const uint16_t* Xh, const uint16_t* Wh,
    int m0, int n0, int kc, uint32_t sb, int tid)
{
    #pragma unroll
    for (int i = 0; i < 4; i++) {
        int slot = i * 256 + tid;
        int r = slot >> 3, c = slot & 7;
        size_t g = (size_t)(m0 + r) * D_MODEL + kc * 64 + c * 8;
        CP16(sb + SW128B((uint32_t)(r * 128 + c * 16)), Xh + g);
    }
    #pragma unroll
    for (int i = 0; i < 4; i++) {
        int slot = i * 256 + tid;
        int kr = slot >> 4, c = slot & 15;
        size_t g = (size_t)(kc * 64 + kr) * D_MODEL + n0 + c * 8;
        CP16(sb + 16384 + SW256((uint32_t)(kr * 256 + c * 16)), Wh + g);
    }
}

__device__ __forceinline__ void gemm_core(
    const uint16_t* Xh, const uint16_t* Wh,
    uint32_t sb0, int m0, int n0, int tid, float acc[2][8][4])
{
    const int lane = tid & 31;
    const int wid  = tid >> 5;
    const int m_w  = (wid & 3) * 32;
    const int n_w  = (wid >> 2) * 64;
    const int a_row = lane & 15;
    const int a_ch  = lane >> 4;
    const int b_kr  = (lane & 7) + ((lane >> 3) & 1) * 8;
    const int b_nc  = lane >> 4;

    gemm_load(Xh, Wh, m0, n0, 0, sb0, tid);
    CP_COMMIT();
    gemm_load(Xh, Wh, m0, n0, 1, sb0 + GB, tid);
    CP_COMMIT();

    for (int kc = 0; kc < 16; kc++) {
        if (kc < 15) { CP_WAIT(1); } else { CP_WAIT(0); }
        __syncthreads();
        if (kc + 2 < 16) {
            gemm_load(Xh, Wh, m0, n0, kc + 2, sb0 + ((kc + 2) % 3) * GB, tid);
            CP_COMMIT();
        }

        const uint32_t bA = sb0 + (kc % 3) * GB;
        const uint32_t bB = bA + 16384;

        #pragma unroll
        for (int ks = 0; ks < 4; ks++) {
            uint32_t ah[2][4];
            #pragma unroll
            for (int mi = 0; mi < 2; mi++) {
                uint32_t o = (uint32_t)((m_w + mi * 16 + a_row) * 128
                                        + ks * 32 + a_ch * 16);
                ldsm_x4(ah[mi], bA + SW128B(o));
            }
            #pragma unroll
            for (int njp = 0; njp < 4; njp++) {
                uint32_t o = (uint32_t)((ks * 16 + b_kr) * 256
                                        + (n_w + njp * 16) * 2 + b_nc * 16);
                uint32_t bh[4];
                ldsm_x4_t(bh, bB + SW256(o));
                #pragma unroll
                for (int mi = 0; mi < 2; mi++) {
                    mma_f16(acc[mi][njp * 2],     ah[mi], bh);
                    mma_f16(acc[mi][njp * 2 + 1], ah[mi], bh + 2);
                }
            }
        }
    }
}

// ---- batched QKV projection: grid.z selects tensor ----
__global__ __launch_bounds__(256, 2)
void gemm_qkv(const uint16_t* __restrict__ Xq, const uint16_t* __restrict__ Xk,
              const uint16_t* __restrict__ Xv,
              const uint16_t* __restrict__ Wq16, const uint16_t* __restrict__ Wk16,
              const uint16_t* __restrict__ Wv16,
              const float* __restrict__ bq, const float* __restrict__ bk,
              const float* __restrict__ bv,
              uint16_t* __restrict__ Qh,
              uint16_t* __restrict__ Kh, uint16_t* __restrict__ Kl,
              uint16_t* __restrict__ Vh)
{
    extern __shared__ __align__(16) uint8_t dsm[];
    const uint32_t sb0 = smem_u32(dsm);
    const int tid = threadIdx.x;
    const int lane = tid & 31;
    const int wid = tid >> 5;
    const int m0 = blockIdx.y * 128;
    const int n0 = blockIdx.x * 128;
    const int z = blockIdx.z;

    const uint16_t* Xh = (z == 0) ? Xq : (z == 1) ? Xk : Xv;
    const uint16_t* Wh = (z == 0) ? Wq16 : (z == 1) ? Wk16 : Wv16;
    const float* bias = (z == 0) ? bq : (z == 1) ? bk : bv;
    const float scale = (z == 0) ? QSCALE : 1.0f;

    float acc[2][8][4];
    #pragma unroll
    for (int mi = 0; mi < 2; mi++)
        #pragma unroll
        for (int nj = 0; nj < 8; nj++)
            #pragma unroll
            for (int e = 0; e < 4; e++) acc[mi][nj][e] = 0.f;

    gemm_core(Xh, Wh, sb0, m0, n0, tid, acc);

    const int m_w = (wid & 3) * 32;
    const int n_w = (wid >> 2) * 64;
    #pragma unroll
    for (int mi = 0; mi < 2; mi++) {
        #pragma unroll
        for (int nj = 0; nj < 8; nj++) {
            int col = n0 + n_w + nj * 8 + (lane & 3) * 2;
            int r0  = m0 + m_w + mi * 16 + (lane >> 2);
            float b0 = bias[col], b1 = bias[col + 1];
            float vx0 = (acc[mi][nj][0] + b0) * scale;
            float vy0 = (acc[mi][nj][1] + b1) * scale;
            float vx1 = (acc[mi][nj][2] + b0) * scale;
            float vy1 = (acc[mi][nj][3] + b1) * scale;
            if (z == 1) {
                // K: f16 hi + residual lo (2-term S consumes both)
                float hx0 = __half2float(__float2half_rn(vx0));
                float hy0 = __half2float(__float2half_rn(vy0));
                float hx1 = __half2float(__float2half_rn(vx1));
                float hy1 = __half2float(__float2half_rn(vy1));
                *(uint32_t*)(Kh + (size_t)r0 * D_MODEL + col) = pk_h(hx0, hy0);
                *(uint32_t*)(Kl + (size_t)r0 * D_MODEL + col) = pk_h(vx0 - hx0, vy0 - hy0);
                *(uint32_t*)(Kh + (size_t)(r0 + 8) * D_MODEL + col) = pk_h(hx1, hy1);
                *(uint32_t*)(Kl + (size_t)(r0 + 8) * D_MODEL + col) = pk_h(vx1 - hx1, vy1 - hy1);
            } else {
                // Q (scaled) and V: f16 hi only
                uint16_t* Ch = (z == 0) ? Qh : Vh;
                *(uint32_t*)(Ch + (size_t)r0 * D_MODEL + col) = pk_h(vx0, vy0);
                *(uint32_t*)(Ch + (size_t)(r0 + 8) * D_MODEL + col) = pk_h(vx1, vy1);
            }
        }
    }
}

// ---- O projection: fp32 out ----
__global__ __launch_bounds__(256, 2)
void gemm_o(const uint16_t* __restrict__ Xh, const uint16_t* __restrict__ Wh,
            const float* __restrict__ bias, float* __restrict__ C)
{
    extern __shared__ __align__(16) uint8_t dsm[];
    const uint32_t sb0 = smem_u32(dsm);
    const int tid = threadIdx.x;
    const int lane = tid & 31;
    const int wid = tid >> 5;
    const int m0 = blockIdx.y * 128;
    const int n0 = blockIdx.x * 128;

    float acc[2][8][4];
    #pragma unroll
    for (int mi = 0; mi < 2; mi++)
        #pragma unroll
        for (int nj = 0; nj < 8; nj++)
            #pragma unroll
            for (int e = 0; e < 4; e++) acc[mi][nj][e] = 0.f;

    gemm_core(Xh, Wh, sb0, m0, n0, tid, acc);

    const int m_w = (wid & 3) * 32;
    const int n_w = (wid >> 2) * 64;
    #pragma unroll
    for (int mi = 0; mi < 2; mi++) {
        #pragma unroll
        for (int nj = 0; nj < 8; nj++) {
            int col = n0 + n_w + nj * 8 + (lane & 3) * 2;
            int r0  = m0 + m_w + mi * 16 + (lane >> 2);
            float b0 = bias[col], b1 = bias[col + 1];
            *(float2*)(C + (size_t)r0 * D_MODEL + col) =
                make_float2(acc[mi][nj][0] + b0, acc[mi][nj][1] + b1);
            *(float2*)(C + (size_t)(r0 + 8) * D_MODEL + col) =
                make_float2(acc[mi][nj][2] + b0, acc[mi][nj][3] + b1);
        }
    }
}

// ===========================================================================
// Tensor-core flash attention: 128-thread CTAs (q-tile 64), 2 CTAs/SM.
// S = Qh16 @ (Kh16 + Kl16)^T  -- 2-term f16. V f16 hi-only PV.
// 2 x {Kh,Kl,Vh} = 96KB smem. Single barrier per kt.
// ===========================================================================
#define TILE_B 16384

__device__ __forceinline__ void attn_load_kv(
    const uint16_t* Kh, const uint16_t* Kl, const uint16_t* Vh,
    size_t rowbase, size_t colb, uint32_t bb, int tid)
{
    #pragma unroll
    for (int i = 0; i < 8; i++) {
        int lin = i * 128 + tid;
        int r = lin >> 3, c = lin & 7;
        size_t ga = (rowbase + r) * D_MODEL + colb + c * 8;
        uint32_t so = SW128B((uint32_t)(r * 128 + c * 16));
        CP16(bb + so, Kh + ga);
        CP16(bb + TILE_B + so, Kl + ga);
        CP16(bb + 2 * TILE_B + so, Vh + ga);
    }
}

__global__ __launch_bounds__(128, 2)
void attn_mma(const uint16_t* __restrict__ Qh,
              const uint16_t* __restrict__ Kh, const uint16_t* __restrict__ Kl,
              const uint16_t* __restrict__ Vh, uint16_t* __restrict__ Ao)
{
    extern __shared__ __align__(16) uint8_t smx[];
    const uint32_t sb0 = smem_u32(smx);

    const int qt = blockIdx.x;
    const int bh = blockIdx.y;
    const int b = bh >> 4, h = bh & 15;
    const int tid = threadIdx.x;
    const int lane = tid & 31;
    const int w = tid >> 5;          // 0..3

    const size_t colb = (size_t)h * HEAD_DIM;
    const size_t qrow0 = (size_t)b * SEQ + qt * 64;
    const size_t krow0 = (size_t)b * SEQ;

    attn_load_kv(Kh, Kl, Vh, krow0, colb, sb0, tid);
    CP_COMMIT();

    // stage Q (f16 hi, 64 rows) in buffer-1 tile 3 (overwritten later)
    {
        uint8_t* q0 = smx + 3 * TILE_B;
        #pragma unroll
        for (int i = 0; i < 4; i++) {
            int lin = i * 128 + tid;
            int r = lin >> 3, c16 = lin & 7;
            uint32_t so = SW128B((uint32_t)(r * 128 + c16 * 16));
            *(uint4*)(q0 + so) = *(const uint4*)(Qh + (qrow0 + r) * D_MODEL + colb + c16 * 8);
        }
    }
    __syncthreads();

    uint32_t qfh[4][4];
    {
        const uint32_t bq0 = sb0 + 3 * TILE_B;
        int row = w * 16 + (lane & 15);
        #pragma unroll
        for (int u = 0; u < 4; u++) {
            uint32_t off = SW128B((uint32_t)(row * 128 + u * 32 + (lane >> 4) * 16));
            ldsm_x4(qfh[u], bq0 + off);
        }
    }

    float O[8][4];
    float Lac[4];
    #pragma unroll
    for (int t = 0; t < 8; t++)
        #pragma unroll
        for (int e = 0; e < 4; e++) O[t][e] = 0.f;
    Lac[0] = Lac[1] = Lac[2] = Lac[3] = 0.f;
    float m0 = -1e30f, m1 = -1e30f;

    const uint32_t ones2[2] = {0x3C003C00u, 0x3C003C00u};

    for (int kt = 0; kt < SEQ / 128; kt++) {
        CP_WAIT(0);
        __syncthreads();   // tile kt resident; all threads done with kt-1
        if (kt + 1 < SEQ / 128) {
            attn_load_kv(Kh, Kl, Vh, krow0 + (kt + 1) * 128, colb,
                         sb0 + ((kt + 1) & 1) * 3 * TILE_B, tid);
            CP_COMMIT();
        }

        const uint32_t bK0 = sb0 + (kt & 1) * 3 * TILE_B;
        const uint32_t bK1 = bK0 + TILE_B;
        const uint32_t bV0 = bK0 + 2 * TILE_B;

        float sacc[16][4];
        #pragma unroll
        for (int t = 0; t < 16; t++)
            #pragma unroll
            for (int e = 0; e < 4; e++) sacc[t][e] = 0.f;

        // ---- S = Qh @ (Kh + Kl)^T : 2-term f16, 4-acc round robin ----
        #pragma unroll
        for (int u = 0; u < 4; u++) {
            #pragma unroll
            for (int g2 = 0; g2 < 4; g2++) {
                int tpA = 2 * g2, tpB = 2 * g2 + 1;
                int rowA = tpA * 16 + ((lane >> 4) << 3) + (lane & 7);
                int rowB = tpB * 16 + ((lane >> 4) << 3) + (lane & 7);
                uint32_t offA = SW128B((uint32_t)(rowA * 128 + u * 32 + ((lane >> 3) & 1) * 16));
                uint32_t offB = SW128B((uint32_t)(rowB * 128 + u * 32 + ((lane >> 3) & 1) * 16));
                uint32_t khA[4], klA[4], khB[4], klB[4];
                ldsm_x4(khA, bK0 + offA);
                ldsm_x4(klA, bK1 + offA);
                ldsm_x4(khB, bK0 + offB);
                ldsm_x4(klB, bK1 + offB);
                float* a0 = sacc[4 * g2 + 0];
                float* a1 = sacc[4 * g2 + 1];
                float* a2 = sacc[4 * g2 + 2];
                float* a3 = sacc[4 * g2 + 3];
                mma_f16(a0, qfh[u], khA);
                mma_f16(a1, qfh[u], khA + 2);
                mma_f16(a2, qfh[u], khB);
                mma_f16(a3, qfh[u], khB + 2);
                mma_f16(a0, qfh[u], klA);
                mma_f16(a1, qfh[u], klA + 2);
                mma_f16(a2, qfh[u], klB);
                mma_f16(a3, qfh[u], klB + 2);
            }
        }

        float mx0 = sacc[0][0], mx1 = sacc[0][2];
        #pragma unroll
        for (int t = 0; t < 16; t++) {
            mx0 = fmaxf(mx0, fmaxf(sacc[t][0], sacc[t][1]));
            mx1 = fmaxf(mx1, fmaxf(sacc[t][2], sacc[t][3]));
        }
        mx0 = fmaxf(mx0, __shfl_xor_sync(0xffffffffu, mx0, 1));
        mx0 = fmaxf(mx0, __shfl_xor_sync(0xffffffffu, mx0, 2));
        mx1 = fmaxf(mx1, __shfl_xor_sync(0xffffffffu, mx1, 1));
        mx1 = fmaxf(mx1, __shfl_xor_sync(0xffffffffu, mx1, 2));

        float mn0 = fmaxf(m0, mx0), mn1 = fmaxf(m1, mx1);
        float c0 = exp2f(m0 - mn0), c1 = exp2f(m1 - mn1);
        m0 = mn0; m1 = mn1;

        #pragma unroll
        for (int t = 0; t < 8; t++) {
            O[t][0] *= c0; O[t][1] *= c0;
            O[t][2] *= c1; O[t][3] *= c1;
        }
        Lac[0] *= c0; Lac[1] *= c0; Lac[2] *= c1; Lac[3] *= c1;

        uint32_t P[8][4];
        #pragma unroll
        for (int t = 0; t < 16; t++) {
            uint32_t x01 = ex2_f16x2(cvt_f16x2(sacc[t][1] - mn0, sacc[t][0] - mn0));
            uint32_t x23 = ex2_f16x2(cvt_f16x2(sacc[t][3] - mn1, sacc[t][2] - mn1));
            if (t & 1) { P[t >> 1][2] = x01; P[t >> 1][3] = x23; }
            else       { P[t >> 1][0] = x01; P[t >> 1][1] = x23; }
        }

        #pragma unroll
        for (int u = 0; u < 8; u++) mma_f16(Lac, P[u], ones2);

        // ---- O += P @ V : u-outer / v-inner, 8 distinct accs per u ----
        #pragma unroll
        for (int u = 0; u < 8; u++) {
            int row = u * 16 + ((lane >> 3) & 1) * 8 + (lane & 7);
            uint32_t vh[4][4];
            #pragma unroll
            for (int v = 0; v < 4; v++) {
                uint32_t off = SW128B((uint32_t)(row * 128 + (2 * v + (lane >> 4)) * 16));
                ldsm_x4_t(vh[v], bV0 + off);
            }
            #pragma unroll
            for (int v = 0; v < 4; v++) {
                mma_f16(O[2 * v],     P[u], vh[v]);
                mma_f16(O[2 * v + 1], P[u], vh[v] + 2);
            }
        }
    }

    float inv0 = 1.0f / Lac[0];
    float inv1 = 1.0f / Lac[2];
    size_t r0 = qrow0 + w * 16 + (lane >> 2);
    size_t r1 = r0 + 8;
    #pragma unroll
    for (int t = 0; t < 8; t++) {
        size_t col = colb + t * 8 + (lane & 3) * 2;
        *(uint32_t*)(Ao + r0 * D_MODEL + col) = pk_h(O[t][0] * inv0, O[t][1] * inv0);
        *(uint32_t*)(Ao + r1 * D_MODEL + col) = pk_h(O[t][2] * inv1, O[t][3] * inv1);
    }
}

// ---------------------------------------------------------------------------
extern "C" void kernel_launch(void* const* d_in, const int* in_sizes, int n_in,
                              void* d_out, int out_size)
{
    const float* query = (const float*)d_in[0];
    const float* key   = (const float*)d_in[1];
    const float* value = (const float*)d_in[2];
    const float* Wq    = (const float*)d_in[3];
    const float* bq    = (const float*)d_in[4];
    const float* Wk    = (const float*)d_in[5];
    const float* bk    = (const float*)d_in[6];
    const float* Wv    = (const float*)d_in[7];
    const float* bv    = (const float*)d_in[8];
    const float* Wo    = (const float*)d_in[9];
    const float* bo    = (const float*)d_in[10];
    float* out = (float*)d_out;

    uint16_t *Qh, *Kh, *Kl, *Vh, *Ao, *Xq, *Xk, *Xv;
    uint16_t *Wq16, *Wk16, *Wv16, *Wo16;
    cudaGetSymbolAddress((void**)&Qh, g_Qh);
    cudaGetSymbolAddress((void**)&Kh, g_Kh);
    cudaGetSymbolAddress((void**)&Kl, g_Kl);
    cudaGetSymbolAddress((void**)&Vh, g_Vh);
    cudaGetSymbolAddress((void**)&Ao, g_Ao);
    cudaGetSymbolAddress((void**)&Xq, g_Xq);
    cudaGetSymbolAddress((void**)&Xk, g_Xk);
    cudaGetSymbolAddress((void**)&Xv, g_Xv);
    cudaGetSymbolAddress((void**)&Wq16, g_Wq16);
    cudaGetSymbolAddress((void**)&Wk16, g_Wk16);
    cudaGetSymbolAddress((void**)&Wv16, g_Wv16);
    cudaGetSymbolAddress((void**)&Wo16, g_Wo16);

    cudaFuncSetAttribute(gemm_qkv,
                         cudaFuncAttributeMaxDynamicSharedMemorySize, 3 * GB);
    cudaFuncSetAttribute(gemm_o,
                         cudaFuncAttributeMaxDynamicSharedMemorySize, 3 * GB);
    cudaFuncSetAttribute(attn_mma,
                         cudaFuncAttributeMaxDynamicSharedMemorySize, 6 * TILE_B);

    const int n_cvt = 3 * NX4 + 4 * NW4;   // 4,194,304 threads
    cvt_all<<<n_cvt / 256, 256>>>(
        (const float4*)query, (const float4*)key, (const float4*)value,
        (const float4*)Wq, (const float4*)Wk, (const float4*)Wv, (const float4*)Wo,
        (uint2*)Xq, (uint2*)Xk, (uint2*)Xv,
        (uint2*)Wq16, (uint2*)Wk16, (uint2*)Wv16, (uint2*)Wo16);

    gemm_qkv<<<dim3(D_MODEL / 128, M_TOT / 128, 3), 256, 3 * GB>>>(
        Xq, Xk, Xv, Wq16, Wk16, Wv16, bq, bk, bv, Qh, Kh, Kl, Vh);

    attn_mma<<<dim3(SEQ / 64, B_SZ * N_HEADS), 128, 6 * TILE_B>>>(
        Qh, Kh, Kl, Vh, Ao);

    gemm_o<<<dim3(D_MODEL / 128, M_TOT / 128), 256, 3 * GB>>>(Ao, Wo16, bo, out);
}

// round 13
// speedup vs baseline: 10.6446x; 1.0427x over previous
#include <cuda_runtime.h>
#include <cuda_bf16.h>
#include <cuda_fp16.h>
#include <stdint.h>
#include <math.h>

#define D_MODEL 1024
#define N_HEADS 16
#define HEAD_DIM 64
#define B_SZ 2
#define SEQ 2048
#define M_TOT (B_SZ * SEQ)   // 4096

// Q pre-scale: 1/sqrt(64) * log2(e)  (softmax done in base-2)
#define QSCALE 0.1803368801111204f

// Scratch (allocation-free rule: device globals)
__device__ uint16_t g_Qh[(size_t)M_TOT * D_MODEL];   // f16 (hi only)
__device__ uint16_t g_Kh[(size_t)M_TOT * D_MODEL];   // f16 hi
__device__ uint16_t g_Kl[(size_t)M_TOT * D_MODEL];   // f16 lo (residual)
__device__ uint16_t g_Vh[(size_t)M_TOT * D_MODEL];   // f16 (hi only)
__device__ uint16_t g_Ao[(size_t)M_TOT * D_MODEL];   // f16 (attn out, hi only)
__device__ uint16_t g_Xq[(size_t)M_TOT * D_MODEL];   // f16
__device__ uint16_t g_Xk[(size_t)M_TOT * D_MODEL];   // f16
__device__ uint16_t g_Xv[(size_t)M_TOT * D_MODEL];   // f16
__device__ uint16_t g_Wq16[(size_t)D_MODEL * D_MODEL];  // f16
__device__ uint16_t g_Wk16[(size_t)D_MODEL * D_MODEL];  // f16
__device__ uint16_t g_Wv16[(size_t)D_MODEL * D_MODEL];  // f16
__device__ uint16_t g_Wo16[(size_t)D_MODEL * D_MODEL];  // f16

// ===========================================================================
// helpers
// ===========================================================================
__device__ __forceinline__ uint32_t smem_u32(const void* p) {
    uint32_t a;
    asm("{ .reg .u64 t; cvta.to.shared.u64 t, %1; cvt.u32.u64 %0, t; }"
        : "=r"(a) : "l"(p));
    return a;
}

#define SW256(o)  ((o) ^ (((o) >> 4) & 0x70))
#define SW128B(o) ((o) ^ (((o) >> 3) & 0x70))

#define CP16(s, g) \
    asm volatile("cp.async.cg.shared.global [%0], [%1], 16;" :: "r"(s), "l"(g))
#define CP_COMMIT() asm volatile("cp.async.commit_group;" ::: "memory")
#define CP_WAIT(n)  asm volatile("cp.async.wait_group %0;" :: "n"(n) : "memory")

__device__ __forceinline__ void ldsm_x4(uint32_t* r, uint32_t a) {
    asm volatile("ldmatrix.sync.aligned.m8n8.x4.shared.b16 {%0,%1,%2,%3}, [%4];"
                 : "=r"(r[0]), "=r"(r[1]), "=r"(r[2]), "=r"(r[3]) : "r"(a));
}
__device__ __forceinline__ void ldsm_x4_t(uint32_t* r, uint32_t a) {
    asm volatile("ldmatrix.sync.aligned.m8n8.x4.trans.shared.b16 {%0,%1,%2,%3}, [%4];"
                 : "=r"(r[0]), "=r"(r[1]), "=r"(r[2]), "=r"(r[3]) : "r"(a));
}
__device__ __forceinline__ void mma_f16(float* c, const uint32_t* a, const uint32_t* b) {
    asm volatile("mma.sync.aligned.m16n8k16.row.col.f32.f16.f16.f32 "
                 "{%0,%1,%2,%3}, {%4,%5,%6,%7}, {%8,%9}, {%0,%1,%2,%3};"
                 : "+f"(c[0]), "+f"(c[1]), "+f"(c[2]), "+f"(c[3])
                 : "r"(a[0]), "r"(a[1]), "r"(a[2]), "r"(a[3]),
                   "r"(b[0]), "r"(b[1]));
}
__device__ __forceinline__ uint32_t cvt_f16x2(float hi, float lo) {
    uint32_t d;
    asm("cvt.rn.f16x2.f32 %0, %1, %2;" : "=r"(d) : "f"(hi), "f"(lo));
    return d;
}
__device__ __forceinline__ uint32_t ex2_f16x2(uint32_t x) {
    uint32_t d;
    asm("ex2.approx.f16x2 %0, %1;" : "=r"(d) : "r"(x));
    return d;
}
__device__ __forceinline__ uint32_t pk_h(float a, float b) {
    __half2 t = __floats2half2_rn(a, b);
    return *(uint32_t*)&t;
}

// ===========================================================================
// Batched conversion: 7 fp32 tensors -> f16 hi, 1 launch
// ===========================================================================
#define NX4 (M_TOT * D_MODEL / 4)   // 1M float4 per activation tensor
#define NW4 (D_MODEL * D_MODEL / 4) // 256K float4 per weight

__global__ __launch_bounds__(256)
void cvt_all(const float4* __restrict__ q, const float4* __restrict__ k,
             const float4* __restrict__ v,
             const float4* __restrict__ w0, const float4* __restrict__ w1,
             const float4* __restrict__ w2, const float4* __restrict__ w3,
             uint2* __restrict__ oq, uint2* __restrict__ ok, uint2* __restrict__ ov,
             uint2* __restrict__ ow0, uint2* __restrict__ ow1,
             uint2* __restrict__ ow2, uint2* __restrict__ ow3)
{
    int g = blockIdx.x * 256 + threadIdx.x;
    const float4* src;
    uint2* dst;
    int i;
    if (g < 3 * NX4) {
        int sel = g / NX4;
        i = g - sel * NX4;
        src = (sel == 0) ? q : (sel == 1) ? k : v;
        dst = (sel == 0) ? oq : (sel == 1) ? ok : ov;
    } else {
        int g2 = g - 3 * NX4;
        int sel = g2 / NW4;
        i = g2 - sel * NW4;
        src = (sel == 0) ? w0 : (sel == 1) ? w1 : (sel == 2) ? w2 : w3;
        dst = (sel == 0) ? ow0 : (sel == 1) ? ow1 : (sel == 2) ? ow2 : ow3;
    }
    float4 x = src[i];
    __half2 a = __floats2half2_rn(x.x, x.y);
    __half2 b = __floats2half2_rn(x.z, x.w);
    dst[i] = make_uint2(*(uint32_t*)&a, *(uint32_t*)&b);
}

// ===========================================================================
// GEMM core: single-term f16 (Xh*Wh), 3-stage cp.async pipeline, kc=64,
// one barrier per iteration. FROZEN (at HMMA fp32-acc issue ceiling).
// ===========================================================================
#define GB 32768

__device__ __forceinline__ void gemm_load(
    const uint16_t* Xh, const uint16_t* Wh,
    int m0, int n0, int kc, uint32_t sb, int tid)
{
    #pragma unroll
    for (int i = 0; i < 4; i++) {
        int slot = i * 256 + tid;
        int r = slot >> 3, c = slot & 7;
        size_t g = (size_t)(m0 + r) * D_MODEL + kc * 64 + c * 8;
        CP16(sb + SW128B((uint32_t)(r * 128 + c * 16)), Xh + g);
    }
    #pragma unroll
    for (int i = 0; i < 4; i++) {
        int slot = i * 256 + tid;
        int kr = slot >> 4, c = slot & 15;
        size_t g = (size_t)(kc * 64 + kr) * D_MODEL + n0 + c * 8;
        CP16(sb + 16384 + SW256((uint32_t)(kr * 256 + c * 16)), Wh + g);
    }
}

__device__ __forceinline__ void gemm_core(
    const uint16_t* Xh, const uint16_t* Wh,
    uint32_t sb0, int m0, int n0, int tid, float acc[2][8][4])
{
    const int lane = tid & 31;
    const int wid  = tid >> 5;
    const int m_w  = (wid & 3) * 32;
    const int n_w  = (wid >> 2) * 64;
    const int a_row = lane & 15;
    const int a_ch  = lane >> 4;
    const int b_kr  = (lane & 7) + ((lane >> 3) & 1) * 8;
    const int b_nc  = lane >> 4;

    gemm_load(Xh, Wh, m0, n0, 0, sb0, tid);
    CP_COMMIT();
    gemm_load(Xh, Wh, m0, n0, 1, sb0 + GB, tid);
    CP_COMMIT();

    for (int kc = 0; kc < 16; kc++) {
        if (kc < 15) { CP_WAIT(1); } else { CP_WAIT(0); }
        __syncthreads();
        if (kc + 2 < 16) {
            gemm_load(Xh, Wh, m0, n0, kc + 2, sb0 + ((kc + 2) % 3) * GB, tid);
            CP_COMMIT();
        }

        const uint32_t bA = sb0 + (kc % 3) * GB;
        const uint32_t bB = bA + 16384;

        #pragma unroll
        for (int ks = 0; ks < 4; ks++) {
            uint32_t ah[2][4];
            #pragma unroll
            for (int mi = 0; mi < 2; mi++) {
                uint32_t o = (uint32_t)((m_w + mi * 16 + a_row) * 128
                                        + ks * 32 + a_ch * 16);
                ldsm_x4(ah[mi], bA + SW128B(o));
            }
            #pragma unroll
            for (int njp = 0; njp < 4; njp++) {
                uint32_t o = (uint32_t)((ks * 16 + b_kr) * 256
                                        + (n_w + njp * 16) * 2 + b_nc * 16);
                uint32_t bh[4];
                ldsm_x4_t(bh, bB + SW256(o));
                #pragma unroll
                for (int mi = 0; mi < 2; mi++) {
                    mma_f16(acc[mi][njp * 2],     ah[mi], bh);
                    mma_f16(acc[mi][njp * 2 + 1], ah[mi], bh + 2);
                }
            }
        }
    }
}

// ---- batched QKV projection: grid.z selects tensor ----
__global__ __launch_bounds__(256, 2)
void gemm_qkv(const uint16_t* __restrict__ Xq, const uint16_t* __restrict__ Xk,
              const uint16_t* __restrict__ Xv,
              const uint16_t* __restrict__ Wq16, const uint16_t* __restrict__ Wk16,
              const uint16_t* __restrict__ Wv16,
              const float* __restrict__ bq, const float* __restrict__ bk,
              const float* __restrict__ bv,
              uint16_t* __restrict__ Qh,
              uint16_t* __restrict__ Kh, uint16_t* __restrict__ Kl,
              uint16_t* __restrict__ Vh)
{
    extern __shared__ __align__(16) uint8_t dsm[];
    const uint32_t sb0 = smem_u32(dsm);
    const int tid = threadIdx.x;
    const int lane = tid & 31;
    const int wid = tid >> 5;
    const int m0 = blockIdx.y * 128;
    const int n0 = blockIdx.x * 128;
    const int z = blockIdx.z;

    const uint16_t* Xh = (z == 0) ? Xq : (z == 1) ? Xk : Xv;
    const uint16_t* Wh = (z == 0) ? Wq16 : (z == 1) ? Wk16 : Wv16;
    const float* bias = (z == 0) ? bq : (z == 1) ? bk : bv;
    const float scale = (z == 0) ? QSCALE : 1.0f;

    float acc[2][8][4];
    #pragma unroll
    for (int mi = 0; mi < 2; mi++)
        #pragma unroll
        for (int nj = 0; nj < 8; nj++)
            #pragma unroll
            for (int e = 0; e < 4; e++) acc[mi][nj][e] = 0.f;

    gemm_core(Xh, Wh, sb0, m0, n0, tid, acc);

    const int m_w = (wid & 3) * 32;
    const int n_w = (wid >> 2) * 64;
    #pragma unroll
    for (int mi = 0; mi < 2; mi++) {
        #pragma unroll
        for (int nj = 0; nj < 8; nj++) {
            int col = n0 + n_w + nj * 8 + (lane & 3) * 2;
            int r0  = m0 + m_w + mi * 16 + (lane >> 2);
            float b0 = bias[col], b1 = bias[col + 1];
            float vx0 = (acc[mi][nj][0] + b0) * scale;
            float vy0 = (acc[mi][nj][1] + b1) * scale;
            float vx1 = (acc[mi][nj][2] + b0) * scale;
            float vy1 = (acc[mi][nj][3] + b1) * scale;
            if (z == 1) {
                float hx0 = __half2float(__float2half_rn(vx0));
                float hy0 = __half2float(__float2half_rn(vy0));
                float hx1 = __half2float(__float2half_rn(vx1));
                float hy1 = __half2float(__float2half_rn(vy1));
                *(uint32_t*)(Kh + (size_t)r0 * D_MODEL + col) = pk_h(hx0, hy0);
                *(uint32_t*)(Kl + (size_t)r0 * D_MODEL + col) = pk_h(vx0 - hx0, vy0 - hy0);
                *(uint32_t*)(Kh + (size_t)(r0 + 8) * D_MODEL + col) = pk_h(hx1, hy1);
                *(uint32_t*)(Kl + (size_t)(r0 + 8) * D_MODEL + col) = pk_h(vx1 - hx1, vy1 - hy1);
            } else {
                uint16_t* Ch = (z == 0) ? Qh : Vh;
                *(uint32_t*)(Ch + (size_t)r0 * D_MODEL + col) = pk_h(vx0, vy0);
                *(uint32_t*)(Ch + (size_t)(r0 + 8) * D_MODEL + col) = pk_h(vx1, vy1);
            }
        }
    }
}

// ---- O projection: fp32 out ----
__global__ __launch_bounds__(256, 2)
void gemm_o(const uint16_t* __restrict__ Xh, const uint16_t* __restrict__ Wh,
            const float* __restrict__ bias, float* __restrict__ C)
{
    extern __shared__ __align__(16) uint8_t dsm[];
    const uint32_t sb0 = smem_u32(dsm);
    const int tid = threadIdx.x;
    const int lane = tid & 31;
    const int wid = tid >> 5;
    const int m0 = blockIdx.y * 128;
    const int n0 = blockIdx.x * 128;

    float acc[2][8][4];
    #pragma unroll
    for (int mi = 0; mi < 2; mi++)
        #pragma unroll
        for (int nj = 0; nj < 8; nj++)
            #pragma unroll
            for (int e = 0; e < 4; e++) acc[mi][nj][e] = 0.f;

    gemm_core(Xh, Wh, sb0, m0, n0, tid, acc);

    const int m_w = (wid & 3) * 32;
    const int n_w = (wid >> 2) * 64;
    #pragma unroll
    for (int mi = 0; mi < 2; mi++) {
        #pragma unroll
        for (int nj = 0; nj < 8; nj++) {
            int col = n0 + n_w + nj * 8 + (lane & 3) * 2;
            int r0  = m0 + m_w + mi * 16 + (lane >> 2);
            float b0 = bias[col], b1 = bias[col + 1];
            *(float2*)(C + (size_t)r0 * D_MODEL + col) =
                make_float2(acc[mi][nj][0] + b0, acc[mi][nj][1] + b1);
            *(float2*)(C + (size_t)(r0 + 8) * D_MODEL + col) =
                make_float2(acc[mi][nj][2] + b0, acc[mi][nj][3] + b1);
        }
    }
}

// ===========================================================================
// Tensor-core flash attention: 128-thread CTAs (q-tile 64), KV tiles of 64
// keys -> 48KB smem -> 4 CTAs/SM (4 warps/SMSP hides softmax latency).
// S = Qh16 @ (Kh16 + Kl16)^T, V f16 hi-only PV. Single barrier per kt.
// ===========================================================================
#define TILE_B 8192   // 64 keys x 64 dims x 2B

__device__ __forceinline__ void attn_load_kv(
    const uint16_t* Kh, const uint16_t* Kl, const uint16_t* Vh,
    size_t rowbase, size_t colb, uint32_t bb, int tid)
{
    #pragma unroll
    for (int i = 0; i < 4; i++) {
        int lin = i * 128 + tid;        // 0..511 = 64 rows x 8 chunks
        int r = lin >> 3, c = lin & 7;
        size_t ga = (rowbase + r) * D_MODEL + colb + c * 8;
        uint32_t so = SW128B((uint32_t)(r * 128 + c * 16));
        CP16(bb + so, Kh + ga);
        CP16(bb + TILE_B + so, Kl + ga);
        CP16(bb + 2 * TILE_B + so, Vh + ga);
    }
}

__global__ __launch_bounds__(128, 4)
void attn_mma(const uint16_t* __restrict__ Qh,
              const uint16_t* __restrict__ Kh, const uint16_t* __restrict__ Kl,
              const uint16_t* __restrict__ Vh, uint16_t* __restrict__ Ao)
{
    extern __shared__ __align__(16) uint8_t smx[];
    const uint32_t sb0 = smem_u32(smx);

    const int qt = blockIdx.x;
    const int bh = blockIdx.y;
    const int b = bh >> 4, h = bh & 15;
    const int tid = threadIdx.x;
    const int lane = tid & 31;
    const int w = tid >> 5;          // 0..3

    const size_t colb = (size_t)h * HEAD_DIM;
    const size_t qrow0 = (size_t)b * SEQ + qt * 64;
    const size_t krow0 = (size_t)b * SEQ;

    attn_load_kv(Kh, Kl, Vh, krow0, colb, sb0, tid);
    CP_COMMIT();

    // stage Q (f16 hi, 64 rows) in buffer-1 tile 3 (overwritten later)
    {
        uint8_t* q0 = smx + 3 * TILE_B;
        #pragma unroll
        for (int i = 0; i < 4; i++) {
            int lin = i * 128 + tid;
            int r = lin >> 3, c16 = lin & 7;
            uint32_t so = SW128B((uint32_t)(r * 128 + c16 * 16));
            *(uint4*)(q0 + so) = *(const uint4*)(Qh + (qrow0 + r) * D_MODEL + colb + c16 * 8);
        }
    }
    __syncthreads();

    uint32_t qfh[4][4];
    {
        const uint32_t bq0 = sb0 + 3 * TILE_B;
        int row = w * 16 + (lane & 15);
        #pragma unroll
        for (int u = 0; u < 4; u++) {
            uint32_t off = SW128B((uint32_t)(row * 128 + u * 32 + (lane >> 4) * 16));
            ldsm_x4(qfh[u], bq0 + off);
        }
    }

    float O[8][4];
    float Lac[4];
    #pragma unroll
    for (int t = 0; t < 8; t++)
        #pragma unroll
        for (int e = 0; e < 4; e++) O[t][e] = 0.f;
    Lac[0] = Lac[1] = Lac[2] = Lac[3] = 0.f;
    float m0 = -1e30f, m1 = -1e30f;

    const uint32_t ones2[2] = {0x3C003C00u, 0x3C003C00u};

    for (int kt = 0; kt < SEQ / 64; kt++) {
        CP_WAIT(0);
        __syncthreads();   // tile kt resident; all threads done with kt-1
        if (kt + 1 < SEQ / 64) {
            attn_load_kv(Kh, Kl, Vh, krow0 + (kt + 1) * 64, colb,
                         sb0 + ((kt + 1) & 1) * 3 * TILE_B, tid);
            CP_COMMIT();
        }

        const uint32_t bK0 = sb0 + (kt & 1) * 3 * TILE_B;
        const uint32_t bK1 = bK0 + TILE_B;
        const uint32_t bV0 = bK0 + 2 * TILE_B;

        float sacc[8][4];
        #pragma unroll
        for (int t = 0; t < 8; t++)
            #pragma unroll
            for (int e = 0; e < 4; e++) sacc[t][e] = 0.f;

        // ---- S = Qh @ (Kh + Kl)^T : 2-term f16, 4-acc round robin ----
        #pragma unroll
        for (int u = 0; u < 4; u++) {
            #pragma unroll
            for (int g2 = 0; g2 < 2; g2++) {
                int tpA = 2 * g2, tpB = 2 * g2 + 1;
                int rowA = tpA * 16 + ((lane >> 4) << 3) + (lane & 7);
                int rowB = tpB * 16 + ((lane >> 4) << 3) + (lane & 7);
                uint32_t offA = SW128B((uint32_t)(rowA * 128 + u * 32 + ((lane >> 3) & 1) * 16));
                uint32_t offB = SW128B((uint32_t)(rowB * 128 + u * 32 + ((lane >> 3) & 1) * 16));
                uint32_t khA[4], klA[4], khB[4], klB[4];
                ldsm_x4(khA, bK0 + offA);
                ldsm_x4(klA, bK1 + offA);
                ldsm_x4(khB, bK0 + offB);
                ldsm_x4(klB, bK1 + offB);
                float* a0 = sacc[4 * g2 + 0];
                float* a1 = sacc[4 * g2 + 1];
                float* a2 = sacc[4 * g2 + 2];
                float* a3 = sacc[4 * g2 + 3];
                mma_f16(a0, qfh[u], khA);
                mma_f16(a1, qfh[u], khA + 2);
                mma_f16(a2, qfh[u], khB);
                mma_f16(a3, qfh[u], khB + 2);
                mma_f16(a0, qfh[u], klA);
                mma_f16(a1, qfh[u], klA + 2);
                mma_f16(a2, qfh[u], klB);
                mma_f16(a3, qfh[u], klB + 2);
            }
        }

        // ---- online softmax over 64 keys ----
        float mx0 = sacc[0][0], mx1 = sacc[0][2];
        #pragma unroll
        for (int t = 0; t < 8; t++) {
            mx0 = fmaxf(mx0, fmaxf(sacc[t][0], sacc[t][1]));
            mx1 = fmaxf(mx1, fmaxf(sacc[t][2], sacc[t][3]));
        }
        mx0 = fmaxf(mx0, __shfl_xor_sync(0xffffffffu, mx0, 1));
        mx0 = fmaxf(mx0, __shfl_xor_sync(0xffffffffu, mx0, 2));
        mx1 = fmaxf(mx1, __shfl_xor_sync(0xffffffffu, mx1, 1));
        mx1 = fmaxf(mx1, __shfl_xor_sync(0xffffffffu, mx1, 2));

        float mn0 = fmaxf(m0, mx0), mn1 = fmaxf(m1, mx1);
        float c0 = exp2f(m0 - mn0), c1 = exp2f(m1 - mn1);
        m0 = mn0; m1 = mn1;

        #pragma unroll
        for (int t = 0; t < 8; t++) {
            O[t][0] *= c0; O[t][1] *= c0;
            O[t][2] *= c1; O[t][3] *= c1;
        }
        Lac[0] *= c0; Lac[1] *= c0; Lac[2] *= c1; Lac[3] *= c1;

        uint32_t P[4][4];
        #pragma unroll
        for (int t = 0; t < 8; t++) {
            uint32_t x01 = ex2_f16x2(cvt_f16x2(sacc[t][1] - mn0, sacc[t][0] - mn0));
            uint32_t x23 = ex2_f16x2(cvt_f16x2(sacc[t][3] - mn1, sacc[t][2] - mn1));
            if (t & 1) { P[t >> 1][2] = x01; P[t >> 1][3] = x23; }
            else       { P[t >> 1][0] = x01; P[t >> 1][1] = x23; }
        }

        #pragma unroll
        for (int u = 0; u < 4; u++) mma_f16(Lac, P[u], ones2);

        // ---- O += P @ V : u-outer / v-inner, 8 distinct accs per u ----
        #pragma unroll
        for (int u = 0; u < 4; u++) {
            int row = u * 16 + ((lane >> 3) & 1) * 8 + (lane & 7);
            uint32_t vh[4][4];
            #pragma unroll
            for (int v = 0; v < 4; v++) {
                uint32_t off = SW128B((uint32_t)(row * 128 + (2 * v + (lane >> 4)) * 16));
                ldsm_x4_t(vh[v], bV0 + off);
            }
            #pragma unroll
            for (int v = 0; v < 4; v++) {
                mma_f16(O[2 * v],     P[u], vh[v]);
                mma_f16(O[2 * v + 1], P[u], vh[v] + 2);
            }
        }
    }

    float inv0 = 1.0f / Lac[0];
    float inv1 = 1.0f / Lac[2];
    size_t r0 = qrow0 + w * 16 + (lane >> 2);
    size_t r1 = r0 + 8;
    #pragma unroll
    for (int t = 0; t < 8; t++) {
        size_t col = colb + t * 8 + (lane & 3) * 2;
        *(uint32_t*)(Ao + r0 * D_MODEL + col) = pk_h(O[t][0] * inv0, O[t][1] * inv0);
        *(uint32_t*)(Ao + r1 * D_MODEL + col) = pk_h(O[t][2] * inv1, O[t][3] * inv1);
    }
}

// ---------------------------------------------------------------------------
extern "C" void kernel_launch(void* const* d_in, const int* in_sizes, int n_in,
                              void* d_out, int out_size)
{
    const float* query = (const float*)d_in[0];
    const float* key   = (const float*)d_in[1];
    const float* value = (const float*)d_in[2];
    const float* Wq    = (const float*)d_in[3];
    const float* bq    = (const float*)d_in[4];
    const float* Wk    = (const float*)d_in[5];
    const float* bk    = (const float*)d_in[6];
    const float* Wv    = (const float*)d_in[7];
    const float* bv    = (const float*)d_in[8];
    const float* Wo    = (const float*)d_in[9];
    const float* bo    = (const float*)d_in[10];
    float* out = (float*)d_out;

    uint16_t *Qh, *Kh, *Kl, *Vh, *Ao, *Xq, *Xk, *Xv;
    uint16_t *Wq16, *Wk16, *Wv16, *Wo16;
    cudaGetSymbolAddress((void**)&Qh, g_Qh);
    cudaGetSymbolAddress((void**)&Kh, g_Kh);
    cudaGetSymbolAddress((void**)&Kl, g_Kl);
    cudaGetSymbolAddress((void**)&Vh, g_Vh);
    cudaGetSymbolAddress((void**)&Ao, g_Ao);
    cudaGetSymbolAddress((void**)&Xq, g_Xq);
    cudaGetSymbolAddress((void**)&Xk, g_Xk);
    cudaGetSymbolAddress((void**)&Xv, g_Xv);
    cudaGetSymbolAddress((void**)&Wq16, g_Wq16);
    cudaGetSymbolAddress((void**)&Wk16, g_Wk16);
    cudaGetSymbolAddress((void**)&Wv16, g_Wv16);
    cudaGetSymbolAddress((void**)&Wo16, g_Wo16);

    cudaFuncSetAttribute(gemm_qkv,
                         cudaFuncAttributeMaxDynamicSharedMemorySize, 3 * GB);
    cudaFuncSetAttribute(gemm_o,
                         cudaFuncAttributeMaxDynamicSharedMemorySize, 3 * GB);
    cudaFuncSetAttribute(attn_mma,
                         cudaFuncAttributeMaxDynamicSharedMemorySize, 6 * TILE_B);

    const int n_cvt = 3 * NX4 + 4 * NW4;   // 4,194,304 threads
    cvt_all<<<n_cvt / 256, 256>>>(
        (const float4*)query, (const float4*)key, (const float4*)value,
        (const float4*)Wq, (const float4*)Wk, (const float4*)Wv, (const float4*)Wo,
        (uint2*)Xq, (uint2*)Xk, (uint2*)Xv,
        (uint2*)Wq16, (uint2*)Wk16, (uint2*)Wv16, (uint2*)Wo16);

    gemm_qkv<<<dim3(D_MODEL / 128, M_TOT / 128, 3), 256, 3 * GB>>>(
        Xq, Xk, Xv, Wq16, Wk16, Wv16, bq, bk, bv, Qh, Kh, Kl, Vh);

    attn_mma<<<dim3(SEQ / 64, B_SZ * N_HEADS), 128, 6 * TILE_B>>>(
        Qh, Kh, Kl, Vh, Ao);

    gemm_o<<<dim3(D_MODEL / 128, M_TOT / 128), 256, 3 * GB>>>(Ao, Wo16, bo, out);
}